// round 1
// baseline (speedup 1.0000x reference)
#include <cuda_runtime.h>
#include <cuda_bf16.h>
#include <math.h>

#define BB   16
#define SS   512
#define DD   768
#define HH   12
#define DNN  64
#define FF   3072
#define LL   6
#define MM   (BB*SS)          // 8192 rows

// ---------------- scratch (device globals; no allocation) ----------------
__device__ float g_pe[SS*DD];
__device__ float g_h [MM*DD];
__device__ float g_q [MM*DD];
__device__ float g_k [MM*DD];
__device__ float g_v [MM*DD];
__device__ float g_o [MM*DD];
__device__ float g_t [MM*DD];
__device__ float g_ff[MM*FF];

// ---------------- positional encoding ----------------
__global__ void pe_kernel()
{
    int idx = blockIdx.x*blockDim.x + threadIdx.x;
    if (idx >= SS*DD) return;
    int s = idx / DD, d = idx % DD;
    const float LOG10000 = 9.210340371976184f;
    float val;
    if ((d & 1) == 0) {
        int i = d >> 1;
        float freq = expf(-(2.0f*i/DD)*LOG10000);
        val = sinf(s*freq);
    } else {
        int i = d >> 1;
        float freq = expf(-(2.0f*(i+1)/DD)*LOG10000);
        val = cosf(s*freq);
    }
    g_pe[idx] = val;
}

// ---------------- embedding + PE ----------------
__global__ void embed_kernel(const int* __restrict__ x, const float* __restrict__ emb)
{
    int idx = blockIdx.x*blockDim.x + threadIdx.x;
    if (idx >= MM*DD) return;
    int m = idx / DD, d = idx % DD;
    int s = m % SS;
    int tok = x[m];
    g_h[idx] = emb[(size_t)tok*DD + d] + g_pe[s*DD + d];
}

// ---------------- tiled fp32 GEMM 128x128x16 ----------------
// EPI: 0 = +bias, 1 = relu(+bias), 2 = +bias+residual
// QKV: weight is [H, K, 64] stacked per head (column c -> head c>>6, inner c&63)
template<int EPI, bool QKV>
__global__ __launch_bounds__(256)
void gemm128(const float* __restrict__ A, const float* __restrict__ W,
             const float* __restrict__ bias, const float* __restrict__ res,
             float* __restrict__ out, int Kdim, int Ndim)
{
    __shared__ __align__(16) float As[16][132];
    __shared__ __align__(16) float Bs[16][128];

    int tid = threadIdx.x;
    int c0 = blockIdx.x * 128;
    int m0 = blockIdx.y * 128;
    int ty = tid >> 4, tx = tid & 15;

    float acc[8][8];
#pragma unroll
    for (int i = 0; i < 8; i++)
#pragma unroll
        for (int j = 0; j < 8; j++) acc[i][j] = 0.f;

    for (int k0 = 0; k0 < Kdim; k0 += 16) {
        // load A tile [128 rows][16 k] -> As transposed [k][row]
#pragma unroll
        for (int ii = 0; ii < 2; ii++) {
            int qd = tid + ii*256;            // 0..511 float4s
            int r  = qd >> 2;                 // row 0..127
            int kq = qd & 3;                  // k-quad 0..3
            float4 a4 = *(const float4*)(A + (size_t)(m0+r)*Kdim + k0 + kq*4);
            As[kq*4+0][r] = a4.x;
            As[kq*4+1][r] = a4.y;
            As[kq*4+2][r] = a4.z;
            As[kq*4+3][r] = a4.w;
        }
        // load B tile [16 k][128 cols]
#pragma unroll
        for (int ii = 0; ii < 2; ii++) {
            int qd = tid + ii*256;            // 0..511 float4s
            int dk = qd >> 5;                 // 0..15
            int col = (qd & 31) * 4;          // 0..124
            const float* bp;
            if (QKV) {
                int c = c0 + col;
                bp = W + (size_t)(c >> 6)*Kdim*64 + (size_t)(k0+dk)*64 + (c & 63);
            } else {
                bp = W + (size_t)(k0+dk)*Ndim + c0 + col;
            }
            *(float4*)&Bs[dk][col] = *(const float4*)bp;
        }
        __syncthreads();
#pragma unroll
        for (int kk = 0; kk < 16; kk++) {
            float a[8], b[8];
            *(float4*)&a[0] = *(float4*)&As[kk][ty*8];
            *(float4*)&a[4] = *(float4*)&As[kk][ty*8+4];
            *(float4*)&b[0] = *(float4*)&Bs[kk][tx*8];
            *(float4*)&b[4] = *(float4*)&Bs[kk][tx*8+4];
#pragma unroll
            for (int i = 0; i < 8; i++)
#pragma unroll
                for (int j = 0; j < 8; j++)
                    acc[i][j] += a[i]*b[j];
        }
        __syncthreads();
    }

#pragma unroll
    for (int i = 0; i < 8; i++) {
        int m = m0 + ty*8 + i;
#pragma unroll
        for (int j = 0; j < 8; j++) {
            int c = c0 + tx*8 + j;
            float val = acc[i][j] + bias[c];
            if (EPI == 1) val = fmaxf(val, 0.f);
            if (EPI == 2) val += res[(size_t)m*Ndim + c];
            out[(size_t)m*Ndim + c] = val;
        }
    }
}

// ---------------- fused attention (flash-style, fp32) ----------------
// grid (B*H, S/128), 128 threads; thread = one query row
__global__ __launch_bounds__(128)
void attn_kernel(const float* __restrict__ q, const float* __restrict__ k,
                 const float* __restrict__ v, const int* __restrict__ mask,
                 float* __restrict__ o)
{
    __shared__ __align__(16) float Ks[64][64];
    __shared__ __align__(16) float Vs[64][64];

    int bh = blockIdx.x;
    int b = bh / HH, h = bh % HH;
    int sq = blockIdx.y*128 + threadIdx.x;

    float qr[64];
    const float* qp = q + ((size_t)(b*SS + sq))*DD + h*DNN;
#pragma unroll
    for (int e = 0; e < 64; e += 4)
        *(float4*)&qr[e] = *(const float4*)(qp + e);

    float acc[64];
#pragma unroll
    for (int e = 0; e < 64; e++) acc[e] = 0.f;
    float mmax = -1e30f, ssum = 0.f;

    const int* mrow = mask + ((size_t)b*SS + sq)*SS;
    const float scale = 0.125f;   // 1/sqrt(64)

    for (int kc = 0; kc < SS; kc += 64) {
        int t = threadIdx.x;
#pragma unroll
        for (int ii = 0; ii < 8; ii++) {
            int qd = t + ii*128;              // 0..1023 float4s
            int r = qd >> 4;
            int col = (qd & 15) * 4;
            size_t base = ((size_t)(b*SS + kc + r))*DD + h*DNN + col;
            *(float4*)&Ks[r][col] = *(const float4*)(k + base);
            *(float4*)&Vs[r][col] = *(const float4*)(v + base);
        }
        __syncthreads();

        for (int j = 0; j < 64; j++) {
            float s = 0.f;
#pragma unroll
            for (int e = 0; e < 64; e += 4) {
                float4 k4 = *(const float4*)&Ks[j][e];
                s += qr[e]*k4.x + qr[e+1]*k4.y + qr[e+2]*k4.z + qr[e+3]*k4.w;
            }
            s = s*scale + (mrow[kc+j] ? -1e9f : 0.f);
            if (s > mmax) {
                float corr = __expf(mmax - s);
                ssum *= corr;
#pragma unroll
                for (int e = 0; e < 64; e++) acc[e] *= corr;
                mmax = s;
            }
            float p = __expf(s - mmax);
            ssum += p;
#pragma unroll
            for (int e = 0; e < 64; e += 4) {
                float4 v4 = *(const float4*)&Vs[j][e];
                acc[e]   += p*v4.x;
                acc[e+1] += p*v4.y;
                acc[e+2] += p*v4.z;
                acc[e+3] += p*v4.w;
            }
        }
        __syncthreads();
    }

    float inv = 1.f / ssum;
    float* op = o + ((size_t)(b*SS + sq))*DD + h*DNN;
#pragma unroll
    for (int e = 0; e < 64; e += 4) {
        float4 r4 = make_float4(acc[e]*inv, acc[e+1]*inv, acc[e+2]*inv, acc[e+3]*inv);
        *(float4*)(op + e) = r4;
    }
}

// ---------------- layernorm ----------------
__global__ __launch_bounds__(256)
void ln_kernel(const float* __restrict__ in, const float* __restrict__ g,
               const float* __restrict__ be, float* __restrict__ out)
{
    int row = blockIdx.x;
    int t = threadIdx.x;
    const float* p = in + (size_t)row*DD;
    float x0 = p[t], x1 = p[t+256], x2 = p[t+512];
    __shared__ float rs[256], rq[256];
    rs[t] = x0+x1+x2;
    rq[t] = x0*x0 + x1*x1 + x2*x2;
    __syncthreads();
    for (int off = 128; off > 0; off >>= 1) {
        if (t < off) { rs[t] += rs[t+off]; rq[t] += rq[t+off]; }
        __syncthreads();
    }
    float mean = rs[0] * (1.0f/768.0f);
    float var  = rq[0] * (1.0f/768.0f) - mean*mean;
    float rstd = rsqrtf(var + 1e-5f);
    float* q = out + (size_t)row*DD;
    q[t]     = (x0-mean)*rstd*g[t]     + be[t];
    q[t+256] = (x1-mean)*rstd*g[t+256] + be[t+256];
    q[t+512] = (x2-mean)*rstd*g[t+512] + be[t+512];
}

// ---------------- host ----------------
extern "C" void kernel_launch(void* const* d_in, const int* in_sizes, int n_in,
                              void* d_out, int out_size)
{
    const int*   x    = (const int*)  d_in[0];
    const int*   pmsk = (const int*)  d_in[1];
    const float* emb  = (const float*)d_in[2];
    const float* Wq   = (const float*)d_in[3];
    const float* bq   = (const float*)d_in[4];
    const float* Wk   = (const float*)d_in[5];
    const float* bk   = (const float*)d_in[6];
    const float* Wv   = (const float*)d_in[7];
    const float* bv   = (const float*)d_in[8];
    const float* Wo   = (const float*)d_in[9];
    const float* bo   = (const float*)d_in[10];
    const float* W1   = (const float*)d_in[11];
    const float* b1   = (const float*)d_in[12];
    const float* W2   = (const float*)d_in[13];
    const float* b2   = (const float*)d_in[14];
    const float* g1   = (const float*)d_in[15];
    const float* be1  = (const float*)d_in[16];
    const float* g2   = (const float*)d_in[17];
    const float* be2  = (const float*)d_in[18];
    float* outp = (float*)d_out;

    float *hb, *qb, *kb, *vb, *ob, *tb, *ffb;
    cudaGetSymbolAddress((void**)&hb,  g_h);
    cudaGetSymbolAddress((void**)&qb,  g_q);
    cudaGetSymbolAddress((void**)&kb,  g_k);
    cudaGetSymbolAddress((void**)&vb,  g_v);
    cudaGetSymbolAddress((void**)&ob,  g_o);
    cudaGetSymbolAddress((void**)&tb,  g_t);
    cudaGetSymbolAddress((void**)&ffb, g_ff);

    pe_kernel<<<(SS*DD+255)/256, 256>>>();
    embed_kernel<<<(MM*DD+255)/256, 256>>>(x, emb);

    dim3 gProj(DD/128, MM/128);    // (6, 64)
    dim3 gFF1 (FF/128, MM/128);    // (24, 64)
    dim3 gAttn(BB*HH, SS/128);     // (192, 4)

    for (int l = 0; l < LL; l++) {
        const float* Wql = Wq + (size_t)l*HH*DD*DNN;
        const float* Wkl = Wk + (size_t)l*HH*DD*DNN;
        const float* Wvl = Wv + (size_t)l*HH*DD*DNN;
        const float* Wol = Wo + (size_t)l*DD*DD;
        const float* W1l = W1 + (size_t)l*DD*FF;
        const float* W2l = W2 + (size_t)l*FF*DD;

        gemm128<0,true ><<<gProj, 256>>>(hb, Wql, bq + l*DD, nullptr, qb, DD, DD);
        gemm128<0,true ><<<gProj, 256>>>(hb, Wkl, bk + l*DD, nullptr, kb, DD, DD);
        gemm128<0,true ><<<gProj, 256>>>(hb, Wvl, bv + l*DD, nullptr, vb, DD, DD);

        attn_kernel<<<gAttn, 128>>>(qb, kb, vb, pmsk, ob);

        gemm128<2,false><<<gProj, 256>>>(ob, Wol, bo + l*DD, hb, tb, DD, DD);
        ln_kernel<<<MM, 256>>>(tb, g1 + l*DD, be1 + l*DD, hb);

        gemm128<1,false><<<gFF1, 256>>>(hb, W1l, b1 + l*FF, nullptr, ffb, DD, FF);
        gemm128<2,false><<<gProj, 256>>>(ffb, W2l, b2 + l*DD, hb, tb, FF, DD);

        float* lnOut = (l == LL-1) ? outp : hb;
        ln_kernel<<<MM, 256>>>(tb, g2 + l*DD, be2 + l*DD, lnOut);
    }
}

// round 3
// speedup vs baseline: 1.3538x; 1.3538x over previous
#include <cuda_runtime.h>
#include <cuda_bf16.h>
#include <cstdint>
#include <math.h>

#define BB   16
#define SS   512
#define DD   768
#define HH   12
#define DNN  64
#define FF   3072
#define LL   6
#define MM   (BB*SS)          // 8192 rows
#define NQKV 2304

// per-layer bf16 weight region layout (element offsets)
#define SZ_QKV (NQKV*DD)
#define SZ_O   (DD*DD)
#define SZ_W1  (FF*DD)
#define SZ_W2  (DD*FF)
#define OFF_O   SZ_QKV
#define OFF_W1  (OFF_O + SZ_O)
#define OFF_W2  (OFF_W1 + SZ_W1)
#define LAYER_SZ (OFF_W2 + SZ_W2)

// ---------------- scratch (device globals; no allocation) ----------------
__device__ float g_pe [SS*DD];
__device__ float g_h  [MM*DD];
__device__ float g_qkv[MM*NQKV];
__device__ float g_o  [MM*DD];
__device__ float g_t  [MM*DD];
__device__ float g_ff [MM*FF];
__device__ __nv_bfloat16 g_Ahi[(size_t)MM*FF];
__device__ __nv_bfloat16 g_Alo[(size_t)MM*FF];
__device__ __nv_bfloat16 g_Whi[(size_t)LL*LAYER_SZ];
__device__ __nv_bfloat16 g_Wlo[(size_t)LL*LAYER_SZ];
__device__ float g_bqkv[LL*NQKV];

// ======================= PTX helpers =======================
__device__ __forceinline__ uint32_t smem_u32(const void* p) {
    uint32_t a;
    asm("{ .reg .u64 t; cvta.to.shared.u64 t, %1; cvt.u32.u64 %0, t; }" : "=r"(a) : "l"(p));
    return a;
}
#define CP_ASYNC(dst, src) \
    asm volatile("cp.async.cg.shared.global [%0], [%1], 16;" :: "r"(dst), "l"(src) : "memory")
#define CP_COMMIT() asm volatile("cp.async.commit_group;" ::: "memory")
#define CP_WAIT2()  asm volatile("cp.async.wait_group 2;" ::: "memory")

#define LDSM4(r, addr) \
    asm volatile("ldmatrix.sync.aligned.m8n8.x4.shared.b16 {%0,%1,%2,%3}, [%4];" \
        : "=r"((r)[0]), "=r"((r)[1]), "=r"((r)[2]), "=r"((r)[3]) : "r"(addr))
#define LDSM2(r, addr) \
    asm volatile("ldmatrix.sync.aligned.m8n8.x2.shared.b16 {%0,%1}, [%2];" \
        : "=r"((r)[0]), "=r"((r)[1]) : "r"(addr))
#define MMA16816(c, a, b) \
    asm volatile("mma.sync.aligned.m16n8k16.row.col.f32.bf16.bf16.f32 " \
        "{%0,%1,%2,%3},{%4,%5,%6,%7},{%8,%9},{%0,%1,%2,%3};" \
        : "+f"((c)[0]), "+f"((c)[1]), "+f"((c)[2]), "+f"((c)[3]) \
        : "r"((a)[0]), "r"((a)[1]), "r"((a)[2]), "r"((a)[3]), "r"((b)[0]), "r"((b)[1]))

// ======================= conversion kernels =======================
__global__ void conv_act(const float* __restrict__ s, __nv_bfloat16* __restrict__ hi,
                         __nv_bfloat16* __restrict__ lo, int n4)
{
    int i = blockIdx.x*blockDim.x + threadIdx.x;
    if (i >= n4) return;
    float4 x = *(const float4*)(s + (size_t)i*4);
    __nv_bfloat16 h0=__float2bfloat16(x.x), h1=__float2bfloat16(x.y),
                  h2=__float2bfloat16(x.z), h3=__float2bfloat16(x.w);
    size_t o = (size_t)i*4;
    hi[o]=h0; hi[o+1]=h1; hi[o+2]=h2; hi[o+3]=h3;
    lo[o]  =__float2bfloat16(x.x-__bfloat162float(h0));
    lo[o+1]=__float2bfloat16(x.y-__bfloat162float(h1));
    lo[o+2]=__float2bfloat16(x.z-__bfloat162float(h2));
    lo[o+3]=__float2bfloat16(x.w-__bfloat162float(h3));
}

__device__ __forceinline__ void wsplit(float v, __nv_bfloat16* hi, __nv_bfloat16* lo, size_t o){
    __nv_bfloat16 h = __float2bfloat16(v);
    hi[o] = h;
    lo[o] = __float2bfloat16(v - __bfloat162float(h));
}

__global__ void conv_wqkv(const float* __restrict__ Wq, const float* __restrict__ Wk,
                          const float* __restrict__ Wv)
{
    int l = blockIdx.y;
    int idx = blockIdx.x*256 + threadIdx.x;
    int n = idx / DD, k = idx % DD;
    int sec = n / DD, r = n % DD;
    int h = r >> 6, e = r & 63;
    const float* W = sec==0 ? Wq : (sec==1 ? Wk : Wv);
    float v = W[(((size_t)l*HH + h)*DD + k)*DNN + e];
    size_t o = (size_t)l*LAYER_SZ + (size_t)n*DD + k;
    wsplit(v, g_Whi, g_Wlo, o);
}
__global__ void conv_wo(const float* __restrict__ Wo)
{
    int l = blockIdx.y;
    int idx = blockIdx.x*256 + threadIdx.x;
    int n = idx / DD, k = idx % DD;
    float v = Wo[((size_t)l*DD + k)*DD + n];
    size_t o = (size_t)l*LAYER_SZ + OFF_O + (size_t)n*DD + k;
    wsplit(v, g_Whi, g_Wlo, o);
}
__global__ void conv_w1(const float* __restrict__ W1)
{
    int l = blockIdx.y;
    int idx = blockIdx.x*256 + threadIdx.x;
    int n = idx / DD, k = idx % DD;
    float v = W1[((size_t)l*DD + k)*FF + n];
    size_t o = (size_t)l*LAYER_SZ + OFF_W1 + (size_t)n*DD + k;
    wsplit(v, g_Whi, g_Wlo, o);
}
__global__ void conv_w2(const float* __restrict__ W2)
{
    int l = blockIdx.y;
    int idx = blockIdx.x*256 + threadIdx.x;
    int n = idx / FF, k = idx % FF;
    float v = W2[((size_t)l*FF + k)*DD + n];
    size_t o = (size_t)l*LAYER_SZ + OFF_W2 + (size_t)n*FF + k;
    wsplit(v, g_Whi, g_Wlo, o);
}
__global__ void conv_bqkv(const float* __restrict__ bq, const float* __restrict__ bk,
                          const float* __restrict__ bv)
{
    int idx = blockIdx.x*blockDim.x + threadIdx.x;
    if (idx >= LL*NQKV) return;
    int l = idx / NQKV, n = idx % NQKV;
    int sec = n / DD, r = n % DD;
    const float* b = sec==0 ? bq : (sec==1 ? bk : bv);
    g_bqkv[idx] = b[l*DD + r];
}

// ======================= HMMA split-bf16 GEMM =======================
// C[M,N] = A[M,K] * W[N,K]^T via extended-K: chunks over [AhBh | AlBh | AhBl]
// Block 128x128, 8 warps (2x4), warp tile 64x32, 4-stage cp.async pipeline.
#define NST 4
#define CHK 32
#define ASTRIDE 80                         // bytes per smem row (conflict-free)
#define TILE_B (128*ASTRIDE)               // 10240
#define STAGE_B (2*TILE_B)                 // 20480
#define GEMM_SMEM (NST*STAGE_B)            // 81920

template<int EPI>   // 0: +bias  1: relu(+bias)  2: +bias+res
__global__ void __launch_bounds__(256, 1)
gemm_mma(const __nv_bfloat16* __restrict__ Ahi, const __nv_bfloat16* __restrict__ Alo,
         const __nv_bfloat16* __restrict__ Bhi, const __nv_bfloat16* __restrict__ Blo,
         const float* __restrict__ bias, const float* __restrict__ res,
         float* __restrict__ out, int K, int Ndim)
{
    extern __shared__ char sm[];
    int tid = threadIdx.x, wid = tid >> 5, lid = tid & 31;
    int m0 = blockIdx.y * 128, c0 = blockIdx.x * 128;
    int warp_m = (wid & 1) * 64, warp_n = (wid >> 1) * 32;
    int KC = K / CHK;
    int NCH = 3 * KC;

    float c[4][4][4];
#pragma unroll
    for (int i=0;i<4;i++)
#pragma unroll
        for (int j=0;j<4;j++)
#pragma unroll
            for (int q=0;q<4;q++) c[i][j][q] = 0.f;

    // per-thread load slots (2 segs A + 2 segs B)
    int seg0 = tid, seg1 = tid + 256;
    int ar0 = seg0 >> 2, ac0 = (seg0 & 3) * 8;
    int ar1 = seg1 >> 2, ac1 = (seg1 & 3) * 8;

    auto load_chunk = [&](int ci, int st) {
        int s = ci / KC;
        const __nv_bfloat16* Ap = (s == 1) ? Alo : Ahi;
        const __nv_bfloat16* Bp = (s == 2) ? Blo : Bhi;
        int k0 = (ci - s*KC) * CHK;
        char* base = sm + st * STAGE_B;
        CP_ASYNC(smem_u32(base + ar0*ASTRIDE + (ac0>>3)*16),
                 Ap + (size_t)(m0 + ar0)*K + k0 + ac0);
        CP_ASYNC(smem_u32(base + ar1*ASTRIDE + (ac1>>3)*16),
                 Ap + (size_t)(m0 + ar1)*K + k0 + ac1);
        CP_ASYNC(smem_u32(base + TILE_B + ar0*ASTRIDE + (ac0>>3)*16),
                 Bp + (size_t)(c0 + ar0)*K + k0 + ac0);
        CP_ASYNC(smem_u32(base + TILE_B + ar1*ASTRIDE + (ac1>>3)*16),
                 Bp + (size_t)(c0 + ar1)*K + k0 + ac1);
        CP_COMMIT();
    };

    // prologue: stages 0..2
#pragma unroll
    for (int s = 0; s < NST-1; s++) load_chunk(s, s);

    for (int ci = 0; ci < NCH; ci++) {
        int st = ci & (NST-1);
        CP_WAIT2();
        __syncthreads();
        char* base = sm + st * STAGE_B;
        uint32_t aAbase = smem_u32(base + (warp_m + (lid & 15))*ASTRIDE + ((lid >> 4) << 4));
        uint32_t aBbase = smem_u32(base + TILE_B + (warp_n + (lid & 7))*ASTRIDE + (((lid >> 3) & 1) << 4));
#pragma unroll
        for (int ks = 0; ks < 2; ks++) {
            uint32_t a[4][4], b[4][2];
#pragma unroll
            for (int mt = 0; mt < 4; mt++)
                LDSM4(a[mt], aAbase + mt*16*ASTRIDE + ks*32);
#pragma unroll
            for (int nt = 0; nt < 4; nt++)
                LDSM2(b[nt], aBbase + nt*8*ASTRIDE + ks*32);
#pragma unroll
            for (int mt = 0; mt < 4; mt++)
#pragma unroll
                for (int nt = 0; nt < 4; nt++)
                    MMA16816(c[mt][nt], a[mt], b[nt]);
        }
        __syncthreads();
        int nci = ci + NST - 1;
        if (nci < NCH) load_chunk(nci, nci & (NST-1));
        else CP_COMMIT();               // keep group count in lockstep
    }

    // epilogue
    int g = lid >> 2, t2 = (lid & 3) * 2;
#pragma unroll
    for (int mt = 0; mt < 4; mt++) {
#pragma unroll
        for (int half = 0; half < 2; half++) {
            long m = m0 + warp_m + mt*16 + g + half*8;
            float* orow = out + m*(long)Ndim;
            const float* rrow = res + m*(long)Ndim;
#pragma unroll
            for (int nt = 0; nt < 4; nt++) {
                int col = c0 + warp_n + nt*8 + t2;
                float v0 = c[mt][nt][half*2+0] + bias[col];
                float v1 = c[mt][nt][half*2+1] + bias[col+1];
                if (EPI == 1) { v0 = fmaxf(v0, 0.f); v1 = fmaxf(v1, 0.f); }
                if (EPI == 2) { v0 += rrow[col]; v1 += rrow[col+1]; }
                float2 v = make_float2(v0, v1);
                *(float2*)(orow + col) = v;
            }
        }
    }
}

// ---------------- positional encoding ----------------
__global__ void pe_kernel()
{
    int idx = blockIdx.x*blockDim.x + threadIdx.x;
    if (idx >= SS*DD) return;
    int s = idx / DD, d = idx % DD;
    const float LOG10000 = 9.210340371976184f;
    float val;
    int i = d >> 1;
    if ((d & 1) == 0) {
        float freq = expf(-(2.0f*i/DD)*LOG10000);
        val = sinf(s*freq);
    } else {
        float freq = expf(-(2.0f*(i+1)/DD)*LOG10000);
        val = cosf(s*freq);
    }
    g_pe[idx] = val;
}

// ---------------- embedding + PE ----------------
__global__ void embed_kernel(const int* __restrict__ x, const float* __restrict__ emb)
{
    int idx = blockIdx.x*blockDim.x + threadIdx.x;
    if (idx >= MM*DD) return;
    int m = idx / DD, d = idx % DD;
    int s = m % SS;
    int tok = x[m];
    g_h[idx] = emb[(size_t)tok*DD + d] + g_pe[s*DD + d];
}

// ---------------- fused attention (flash-style, fp32) ----------------
__global__ void __launch_bounds__(128)
attn_kernel(const float* __restrict__ qkv, const int* __restrict__ mask,
            float* __restrict__ o)
{
    __shared__ __align__(16) float Ks[64][64];
    __shared__ __align__(16) float Vs[64][64];

    int bh = blockIdx.x;
    int b = bh / HH, h = bh % HH;
    int sq = blockIdx.y*128 + threadIdx.x;

    float qr[64];
    const float* qp = qkv + ((size_t)(b*SS + sq))*NQKV + h*DNN;
#pragma unroll
    for (int e = 0; e < 64; e += 4)
        *(float4*)&qr[e] = *(const float4*)(qp + e);

    float acc[64];
#pragma unroll
    for (int e = 0; e < 64; e++) acc[e] = 0.f;
    float mmax = -1e30f, ssum = 0.f;

    const int* mrow = mask + ((size_t)b*SS + sq)*SS;
    const float scale = 0.125f;

    for (int kc = 0; kc < SS; kc += 64) {
        int t = threadIdx.x;
#pragma unroll
        for (int ii = 0; ii < 8; ii++) {
            int qd = t + ii*128;
            int r = qd >> 4;
            int col = (qd & 15) * 4;
            size_t base = ((size_t)(b*SS + kc + r))*NQKV + h*DNN + col;
            *(float4*)&Ks[r][col] = *(const float4*)(qkv + base + DD);
            *(float4*)&Vs[r][col] = *(const float4*)(qkv + base + 2*DD);
        }
        __syncthreads();

        for (int j = 0; j < 64; j++) {
            float s = 0.f;
#pragma unroll
            for (int e = 0; e < 64; e += 4) {
                float4 k4 = *(const float4*)&Ks[j][e];
                s += qr[e]*k4.x + qr[e+1]*k4.y + qr[e+2]*k4.z + qr[e+3]*k4.w;
            }
            s = s*scale + (mrow[kc+j] ? -1e9f : 0.f);
            if (s > mmax) {
                float corr = __expf(mmax - s);
                ssum *= corr;
#pragma unroll
                for (int e = 0; e < 64; e++) acc[e] *= corr;
                mmax = s;
            }
            float p = __expf(s - mmax);
            ssum += p;
#pragma unroll
            for (int e = 0; e < 64; e += 4) {
                float4 v4 = *(const float4*)&Vs[j][e];
                acc[e]   += p*v4.x;
                acc[e+1] += p*v4.y;
                acc[e+2] += p*v4.z;
                acc[e+3] += p*v4.w;
            }
        }
        __syncthreads();
    }

    float inv = 1.f / ssum;
    float* op = o + ((size_t)(b*SS + sq))*DD + h*DNN;
#pragma unroll
    for (int e = 0; e < 64; e += 4) {
        float4 r4 = make_float4(acc[e]*inv, acc[e+1]*inv, acc[e+2]*inv, acc[e+3]*inv);
        *(float4*)(op + e) = r4;
    }
}

// ---------------- layernorm ----------------
__global__ void __launch_bounds__(256)
ln_kernel(const float* __restrict__ in, const float* __restrict__ g,
          const float* __restrict__ be, float* __restrict__ out)
{
    int row = blockIdx.x;
    int t = threadIdx.x;
    const float* p = in + (size_t)row*DD;
    float x0 = p[t], x1 = p[t+256], x2 = p[t+512];
    __shared__ float rs[256], rq[256];
    rs[t] = x0+x1+x2;
    rq[t] = x0*x0 + x1*x1 + x2*x2;
    __syncthreads();
    for (int off = 128; off > 0; off >>= 1) {
        if (t < off) { rs[t] += rs[t+off]; rq[t] += rq[t+off]; }
        __syncthreads();
    }
    float mean = rs[0] * (1.0f/768.0f);
    float var  = rq[0] * (1.0f/768.0f) - mean*mean;
    float rstd = rsqrtf(var + 1e-5f);
    float* q = out + (size_t)row*DD;
    q[t]     = (x0-mean)*rstd*g[t]     + be[t];
    q[t+256] = (x1-mean)*rstd*g[t+256] + be[t+256];
    q[t+512] = (x2-mean)*rstd*g[t+512] + be[t+512];
}

// ---------------- host ----------------
extern "C" void kernel_launch(void* const* d_in, const int* in_sizes, int n_in,
                              void* d_out, int out_size)
{
    const int*   x    = (const int*)  d_in[0];
    const int*   pmsk = (const int*)  d_in[1];
    const float* emb  = (const float*)d_in[2];
    const float* Wq   = (const float*)d_in[3];
    const float* bq   = (const float*)d_in[4];
    const float* Wk   = (const float*)d_in[5];
    const float* bk   = (const float*)d_in[6];
    const float* Wv   = (const float*)d_in[7];
    const float* bv   = (const float*)d_in[8];
    const float* Wo   = (const float*)d_in[9];
    const float* bo   = (const float*)d_in[10];
    const float* W1   = (const float*)d_in[11];
    const float* b1   = (const float*)d_in[12];
    const float* W2   = (const float*)d_in[13];
    const float* b2   = (const float*)d_in[14];
    const float* g1   = (const float*)d_in[15];
    const float* be1  = (const float*)d_in[16];
    const float* g2   = (const float*)d_in[17];
    const float* be2  = (const float*)d_in[18];
    float* outp = (float*)d_out;

    float *hb, *qkvb, *ob, *tb, *ffb, *bqkvb;
    __nv_bfloat16 *ahi, *alo, *whi, *wlo;
    cudaGetSymbolAddress((void**)&hb,    g_h);
    cudaGetSymbolAddress((void**)&qkvb,  g_qkv);
    cudaGetSymbolAddress((void**)&ob,    g_o);
    cudaGetSymbolAddress((void**)&tb,    g_t);
    cudaGetSymbolAddress((void**)&ffb,   g_ff);
    cudaGetSymbolAddress((void**)&ahi,   g_Ahi);
    cudaGetSymbolAddress((void**)&alo,   g_Alo);
    cudaGetSymbolAddress((void**)&whi,   g_Whi);
    cudaGetSymbolAddress((void**)&wlo,   g_Wlo);
    cudaGetSymbolAddress((void**)&bqkvb, g_bqkv);

    cudaFuncSetAttribute(gemm_mma<0>, cudaFuncAttributeMaxDynamicSharedMemorySize, GEMM_SMEM);
    cudaFuncSetAttribute(gemm_mma<1>, cudaFuncAttributeMaxDynamicSharedMemorySize, GEMM_SMEM);
    cudaFuncSetAttribute(gemm_mma<2>, cudaFuncAttributeMaxDynamicSharedMemorySize, GEMM_SMEM);

    // weight conversion (transpose + hi/lo split), all layers
    conv_wqkv<<<dim3(NQKV*DD/256, LL), 256>>>(Wq, Wk, Wv);
    conv_wo  <<<dim3(DD*DD/256,   LL), 256>>>(Wo);
    conv_w1  <<<dim3(FF*DD/256,   LL), 256>>>(W1);
    conv_w2  <<<dim3(DD*FF/256,   LL), 256>>>(W2);
    conv_bqkv<<<(LL*NQKV+255)/256, 256>>>(bq, bk, bv);

    pe_kernel<<<(SS*DD+255)/256, 256>>>();
    embed_kernel<<<(MM*DD+255)/256, 256>>>(x, emb);

    dim3 gQKV(NQKV/128, MM/128);   // (18, 64)
    dim3 gO  (DD/128,   MM/128);   // (6, 64)
    dim3 gF1 (FF/128,   MM/128);   // (24, 64)
    dim3 gAttn(BB*HH, SS/128);     // (192, 4)

    for (int l = 0; l < LL; l++) {
        const __nv_bfloat16* wh = whi + (size_t)l*LAYER_SZ;
        const __nv_bfloat16* wl = wlo + (size_t)l*LAYER_SZ;

        conv_act<<<(MM*DD/4+255)/256, 256>>>(hb, ahi, alo, MM*DD/4);
        gemm_mma<0><<<gQKV, 256, GEMM_SMEM>>>(ahi, alo, wh, wl,
                                              bqkvb + l*NQKV, nullptr, qkvb, DD, NQKV);

        attn_kernel<<<gAttn, 128>>>(qkvb, pmsk, ob);

        conv_act<<<(MM*DD/4+255)/256, 256>>>(ob, ahi, alo, MM*DD/4);
        gemm_mma<2><<<gO, 256, GEMM_SMEM>>>(ahi, alo, wh + OFF_O, wl + OFF_O,
                                            bo + l*DD, hb, tb, DD, DD);
        ln_kernel<<<MM, 256>>>(tb, g1 + l*DD, be1 + l*DD, hb);

        conv_act<<<(MM*DD/4+255)/256, 256>>>(hb, ahi, alo, MM*DD/4);
        gemm_mma<1><<<gF1, 256, GEMM_SMEM>>>(ahi, alo, wh + OFF_W1, wl + OFF_W1,
                                             b1 + l*FF, nullptr, ffb, DD, FF);

        conv_act<<<(MM*FF/4+255)/256, 256>>>(ffb, ahi, alo, MM*FF/4);
        gemm_mma<2><<<gO, 256, GEMM_SMEM>>>(ahi, alo, wh + OFF_W2, wl + OFF_W2,
                                            b2 + l*DD, hb, tb, FF, DD);

        float* lnOut = (l == LL-1) ? outp : hb;
        ln_kernel<<<MM, 256>>>(tb, g2 + l*DD, be2 + l*DD, lnOut);
    }
}

// round 5
// speedup vs baseline: 2.1412x; 1.5816x over previous
#include <cuda_runtime.h>
#include <cuda_bf16.h>
#include <cstdint>
#include <math.h>

#define BB   16
#define SS   512
#define DD   768
#define HH   12
#define DNN  64
#define FF   3072
#define LL   6
#define MM   (BB*SS)
#define NQKV 2304

#define SZ_QKV (NQKV*DD)
#define SZ_O   (DD*DD)
#define SZ_W1  (FF*DD)
#define SZ_W2  (DD*FF)
#define OFF_O   SZ_QKV
#define OFF_W1  (OFF_O + SZ_O)
#define OFF_W2  (OFF_W1 + SZ_W1)
#define LAYER_SZ (OFF_W2 + SZ_W2)

// ---------------- scratch ----------------
__device__ float g_pe [SS*DD];
__device__ float g_h  [MM*DD];
__device__ float g_qkv[MM*NQKV];
__device__ float g_t  [MM*DD];
__device__ __nv_bfloat16 g_hhi[(size_t)MM*DD];
__device__ __nv_bfloat16 g_hlo[(size_t)MM*DD];
__device__ __nv_bfloat16 g_ohi[(size_t)MM*DD];
__device__ __nv_bfloat16 g_olo[(size_t)MM*DD];
__device__ __nv_bfloat16 g_fhi[(size_t)MM*FF];
__device__ __nv_bfloat16 g_flo[(size_t)MM*FF];
__device__ __nv_bfloat16 g_Whi[(size_t)LL*LAYER_SZ];
__device__ __nv_bfloat16 g_Wlo[(size_t)LL*LAYER_SZ];
__device__ float g_bqkv[LL*NQKV];

// ======================= PTX helpers =======================
__device__ __forceinline__ uint32_t smem_u32(const void* p) {
    uint32_t a;
    asm("{ .reg .u64 t; cvta.to.shared.u64 t, %1; cvt.u32.u64 %0, t; }" : "=r"(a) : "l"(p));
    return a;
}
#define CP_ASYNC(dst, src) \
    asm volatile("cp.async.cg.shared.global [%0], [%1], 16;" :: "r"(dst), "l"(src) : "memory")
#define CP_COMMIT() asm volatile("cp.async.commit_group;" ::: "memory")
#define CP_WAIT2()  asm volatile("cp.async.wait_group 2;" ::: "memory")

#define LDSM4(r, addr) \
    asm volatile("ldmatrix.sync.aligned.m8n8.x4.shared.b16 {%0,%1,%2,%3}, [%4];" \
        : "=r"((r)[0]), "=r"((r)[1]), "=r"((r)[2]), "=r"((r)[3]) : "r"(addr))
#define LDSM2(r, addr) \
    asm volatile("ldmatrix.sync.aligned.m8n8.x2.shared.b16 {%0,%1}, [%2];" \
        : "=r"((r)[0]), "=r"((r)[1]) : "r"(addr))
#define MMA16816(c, a, b) \
    asm volatile("mma.sync.aligned.m16n8k16.row.col.f32.bf16.bf16.f32 " \
        "{%0,%1,%2,%3},{%4,%5,%6,%7},{%8,%9},{%0,%1,%2,%3};" \
        : "+f"((c)[0]), "+f"((c)[1]), "+f"((c)[2]), "+f"((c)[3]) \
        : "r"((a)[0]), "r"((a)[1]), "r"((a)[2]), "r"((a)[3]), "r"((b)[0]), "r"((b)[1]))

// ======================= weight conversion =======================
__device__ __forceinline__ void wsplit(float v, __nv_bfloat16* hi, __nv_bfloat16* lo, size_t o){
    __nv_bfloat16 h = __float2bfloat16(v);
    hi[o] = h;
    lo[o] = __float2bfloat16(v - __bfloat162float(h));
}

__global__ void conv_wqkv(const float* __restrict__ Wq, const float* __restrict__ Wk,
                          const float* __restrict__ Wv)
{
    int l = blockIdx.y;
    int idx = blockIdx.x*256 + threadIdx.x;
    int n = idx / DD, k = idx % DD;
    int sec = n / DD, r = n % DD;
    int h = r >> 6, e = r & 63;
    const float* W = sec==0 ? Wq : (sec==1 ? Wk : Wv);
    float v = W[(((size_t)l*HH + h)*DD + k)*DNN + e];
    wsplit(v, g_Whi, g_Wlo, (size_t)l*LAYER_SZ + (size_t)n*DD + k);
}
__global__ void conv_wo(const float* __restrict__ Wo)
{
    int l = blockIdx.y;
    int idx = blockIdx.x*256 + threadIdx.x;
    int n = idx / DD, k = idx % DD;
    float v = Wo[((size_t)l*DD + k)*DD + n];
    wsplit(v, g_Whi, g_Wlo, (size_t)l*LAYER_SZ + OFF_O + (size_t)n*DD + k);
}
__global__ void conv_w1(const float* __restrict__ W1)
{
    int l = blockIdx.y;
    int idx = blockIdx.x*256 + threadIdx.x;
    int n = idx / DD, k = idx % DD;
    float v = W1[((size_t)l*DD + k)*FF + n];
    wsplit(v, g_Whi, g_Wlo, (size_t)l*LAYER_SZ + OFF_W1 + (size_t)n*DD + k);
}
__global__ void conv_w2(const float* __restrict__ W2)
{
    int l = blockIdx.y;
    int idx = blockIdx.x*256 + threadIdx.x;
    int n = idx / FF, k = idx % FF;
    float v = W2[((size_t)l*FF + k)*DD + n];
    wsplit(v, g_Whi, g_Wlo, (size_t)l*LAYER_SZ + OFF_W2 + (size_t)n*FF + k);
}
__global__ void conv_bqkv(const float* __restrict__ bq, const float* __restrict__ bk,
                          const float* __restrict__ bv)
{
    int idx = blockIdx.x*blockDim.x + threadIdx.x;
    if (idx >= LL*NQKV) return;
    int l = idx / NQKV, n = idx % NQKV;
    int sec = n / DD, r = n % DD;
    const float* b = sec==0 ? bq : (sec==1 ? bk : bv);
    g_bqkv[idx] = b[l*DD + r];
}

// ======================= fused-chunk HMMA split-bf16 GEMM =======================
// Per 32-wide k-chunk: load Ahi/Alo/Bhi/Blo once, issue AhBh + AlBh + AhBl.
// Block 128x128, 8 warps (2x4), warp tile 64x32, 4-stage cp.async pipeline.
#define NST 4
#define TILE_B 8192               // 128 rows x 64B (32 bf16)
#define STAGE_B (4*TILE_B)        // 32768
#define GEMM_SMEM (NST*STAGE_B)   // 131072

// XOR swizzle: row r (64B), 16B-group cg -> conflict-free ldmatrix
__device__ __forceinline__ uint32_t swz(int r, int cg) {
    return (uint32_t)(r*64 + ((cg ^ ((r>>1)&3))<<4));
}

// EPI 0: +bias -> fp32 | 1: relu(+bias) -> bf16 hi/lo | 2: +bias+res -> fp32
template<int EPI>
__global__ void __launch_bounds__(256, 1)
gemm_mma(const __nv_bfloat16* __restrict__ Ahi, const __nv_bfloat16* __restrict__ Alo,
         const __nv_bfloat16* __restrict__ Bhi, const __nv_bfloat16* __restrict__ Blo,
         const float* __restrict__ bias, const float* __restrict__ res,
         float* __restrict__ outf, __nv_bfloat16* __restrict__ outhi,
         __nv_bfloat16* __restrict__ outlo, int K, int Ndim)
{
    extern __shared__ char sm[];
    int tid = threadIdx.x, wid = tid >> 5, lid = tid & 31;
    int m0 = blockIdx.y * 128, c0 = blockIdx.x * 128;
    int warp_m = (wid & 1) * 64, warp_n = (wid >> 1) * 32;
    int NCH = K >> 5;

    float c[4][4][4];
#pragma unroll
    for (int i=0;i<4;i++)
#pragma unroll
        for (int j=0;j<4;j++)
#pragma unroll
            for (int q=0;q<4;q++) c[i][j][q] = 0.f;

    auto load_chunk = [&](int ci, int st) {
        int k0 = ci << 5;
        char* base = sm + st * STAGE_B;
#pragma unroll
        for (int i = 0; i < 8; i++) {
            int seg = tid + i*256;            // 0..2047
            int tl  = seg >> 9;               // 0..3
            int rem = seg & 511;
            int r   = rem >> 2, cg = rem & 3;
            const __nv_bfloat16* src;
            if      (tl == 0) src = Ahi + (size_t)(m0 + r)*K + k0 + cg*8;
            else if (tl == 1) src = Alo + (size_t)(m0 + r)*K + k0 + cg*8;
            else if (tl == 2) src = Bhi + (size_t)(c0 + r)*K + k0 + cg*8;
            else              src = Blo + (size_t)(c0 + r)*K + k0 + cg*8;
            CP_ASYNC(smem_u32(base + tl*TILE_B + swz(r, cg)), src);
        }
        CP_COMMIT();
    };

#pragma unroll
    for (int s = 0; s < NST-1; s++) load_chunk(s, s);

    for (int ci = 0; ci < NCH; ci++) {
        int st = ci & (NST-1);
        CP_WAIT2();
        __syncthreads();
        int nci = ci + NST - 1;
        if (nci < NCH) load_chunk(nci, nci & (NST-1));
        else CP_COMMIT();

        uint32_t base = smem_u32(sm + st * STAGE_B);
#pragma unroll
        for (int ks = 0; ks < 2; ks++) {
            uint32_t ah[4][4], al[4][4], bh[4][2], bl[4][2];
            int acg = ks*2 + (lid >> 4);
            int bcg = ks*2 + ((lid >> 3) & 1);
#pragma unroll
            for (int mt = 0; mt < 4; mt++) {
                int r = warp_m + mt*16 + (lid & 15);
                LDSM4(ah[mt], base + 0*TILE_B + swz(r, acg));
                LDSM4(al[mt], base + 1*TILE_B + swz(r, acg));
            }
#pragma unroll
            for (int nt = 0; nt < 4; nt++) {
                int r = warp_n + nt*8 + (lid & 7);
                LDSM2(bh[nt], base + 2*TILE_B + swz(r, bcg));
                LDSM2(bl[nt], base + 3*TILE_B + swz(r, bcg));
            }
#pragma unroll
            for (int mt = 0; mt < 4; mt++)
#pragma unroll
                for (int nt = 0; nt < 4; nt++) {
                    MMA16816(c[mt][nt], ah[mt], bh[nt]);
                    MMA16816(c[mt][nt], al[mt], bh[nt]);
                    MMA16816(c[mt][nt], ah[mt], bl[nt]);
                }
        }
        __syncthreads();
    }

    // epilogue
    int g = lid >> 2, t2 = (lid & 3) * 2;
#pragma unroll
    for (int mt = 0; mt < 4; mt++) {
#pragma unroll
        for (int half = 0; half < 2; half++) {
            long m = m0 + warp_m + mt*16 + g + half*8;
#pragma unroll
            for (int nt = 0; nt < 4; nt++) {
                int col = c0 + warp_n + nt*8 + t2;
                float v0 = c[mt][nt][half*2+0] + bias[col];
                float v1 = c[mt][nt][half*2+1] + bias[col+1];
                if (EPI == 1) {
                    v0 = fmaxf(v0, 0.f); v1 = fmaxf(v1, 0.f);
                    __nv_bfloat162 hp, lp;
                    hp.x = __float2bfloat16(v0);
                    hp.y = __float2bfloat16(v1);
                    lp.x = __float2bfloat16(v0 - __bfloat162float(hp.x));
                    lp.y = __float2bfloat16(v1 - __bfloat162float(hp.y));
                    *(__nv_bfloat162*)(outhi + m*(long)Ndim + col) = hp;
                    *(__nv_bfloat162*)(outlo + m*(long)Ndim + col) = lp;
                } else {
                    if (EPI == 2) {
                        const float* rrow = res + m*(long)Ndim;
                        v0 += rrow[col]; v1 += rrow[col+1];
                    }
                    *(float2*)(outf + m*(long)Ndim + col) = make_float2(v0, v1);
                }
            }
        }
    }
}

// ---------------- positional encoding ----------------
__global__ void pe_kernel()
{
    int idx = blockIdx.x*blockDim.x + threadIdx.x;
    if (idx >= SS*DD) return;
    int s = idx / DD, d = idx % DD;
    const float LOG10000 = 9.210340371976184f;
    float val;
    int i = d >> 1;
    if ((d & 1) == 0) {
        float freq = expf(-(2.0f*i/DD)*LOG10000);
        val = sinf(s*freq);
    } else {
        float freq = expf(-(2.0f*(i+1)/DD)*LOG10000);
        val = cosf(s*freq);
    }
    g_pe[idx] = val;
}

// ---------------- embedding + PE (+ split) ----------------
__global__ void embed_kernel(const int* __restrict__ x, const float* __restrict__ emb)
{
    int idx = blockIdx.x*blockDim.x + threadIdx.x;
    if (idx >= MM*DD) return;
    int m = idx / DD, d = idx % DD;
    int s = m % SS;
    int tok = x[m];
    float v = emb[(size_t)tok*DD + d] + g_pe[s*DD + d];
    g_h[idx] = v;
    __nv_bfloat16 h = __float2bfloat16(v);
    g_hhi[idx] = h;
    g_hlo[idx] = __float2bfloat16(v - __bfloat162float(h));
}

// ---------------- fused attention (no-rescale softmax, smem mask) ----------------
__global__ void __launch_bounds__(128)
attn_kernel(const float* __restrict__ qkv, const int* __restrict__ mask,
            __nv_bfloat16* __restrict__ ohi, __nv_bfloat16* __restrict__ olo)
{
    __shared__ __align__(16) float Ks[64][64];
    __shared__ __align__(16) float Vs[64][64];
    __shared__ unsigned char Ms[128][68];

    int bh = blockIdx.x;
    int b = bh / HH, h = bh % HH;
    int sq0 = blockIdx.y*128;
    int tx = threadIdx.x;
    int sq = sq0 + tx;

    float qr[64];
    const float* qp = qkv + ((size_t)(b*SS + sq))*NQKV + h*DNN;
#pragma unroll
    for (int e = 0; e < 64; e += 4)
        *(float4*)&qr[e] = *(const float4*)(qp + e);

    float acc[64];
#pragma unroll
    for (int e = 0; e < 64; e++) acc[e] = 0.f;
    float ssum = 0.f;

    for (int kc = 0; kc < SS; kc += 64) {
#pragma unroll
        for (int ii = 0; ii < 8; ii++) {
            int qd = tx + ii*128;
            int r = qd >> 4;
            int col = (qd & 15) * 4;
            size_t base = ((size_t)(b*SS + kc + r))*NQKV + h*DNN + col;
            *(float4*)&Ks[r][col] = *(const float4*)(qkv + base + DD);
            *(float4*)&Vs[r][col] = *(const float4*)(qkv + base + 2*DD);
        }
        // mask tile: 128 rows x 64 cols -> u8
#pragma unroll
        for (int ii = 0; ii < 16; ii++) {
            int i = tx + ii*128;              // 0..2047 int4s
            int row = i >> 4, c4 = i & 15;
            int4 mv = *((const int4*)(mask + ((size_t)(b*SS + sq0 + row))*SS + kc) + c4);
            Ms[row][c4*4+0] = (unsigned char)mv.x;
            Ms[row][c4*4+1] = (unsigned char)mv.y;
            Ms[row][c4*4+2] = (unsigned char)mv.z;
            Ms[row][c4*4+3] = (unsigned char)mv.w;
        }
        __syncthreads();

        for (int j = 0; j < 64; j++) {
            float s0=0.f, s1=0.f, s2=0.f, s3=0.f;
#pragma unroll
            for (int e = 0; e < 64; e += 16) {
                float4 k0 = *(const float4*)&Ks[j][e];
                float4 k1 = *(const float4*)&Ks[j][e+4];
                float4 k2 = *(const float4*)&Ks[j][e+8];
                float4 k3 = *(const float4*)&Ks[j][e+12];
                s0 += qr[e+0]*k0.x + qr[e+1]*k0.y + qr[e+2]*k0.z + qr[e+3]*k0.w;
                s1 += qr[e+4]*k1.x + qr[e+5]*k1.y + qr[e+6]*k1.z + qr[e+7]*k1.w;
                s2 += qr[e+8]*k2.x + qr[e+9]*k2.y + qr[e+10]*k2.z + qr[e+11]*k2.w;
                s3 += qr[e+12]*k3.x + qr[e+13]*k3.y + qr[e+14]*k3.z + qr[e+15]*k3.w;
            }
            float s = (s0+s1) + (s2+s3);
            float bias = Ms[tx][j] ? -1e9f : 0.f;
            float p = __expf(fmaf(s, 0.125f, bias));
            ssum += p;
#pragma unroll
            for (int e = 0; e < 64; e += 4) {
                float4 v4 = *(const float4*)&Vs[j][e];
                acc[e]   += p*v4.x;
                acc[e+1] += p*v4.y;
                acc[e+2] += p*v4.z;
                acc[e+3] += p*v4.w;
            }
        }
        __syncthreads();
    }

    float inv = 1.f / ssum;
    size_t ob = ((size_t)(b*SS + sq))*DD + h*DNN;
#pragma unroll
    for (int e = 0; e < 64; e += 2) {
        float v0 = acc[e]*inv, v1 = acc[e+1]*inv;
        __nv_bfloat162 hp, lp;
        hp.x = __float2bfloat16(v0);
        hp.y = __float2bfloat16(v1);
        lp.x = __float2bfloat16(v0 - __bfloat162float(hp.x));
        lp.y = __float2bfloat16(v1 - __bfloat162float(hp.y));
        *(__nv_bfloat162*)(ohi + ob + e) = hp;
        *(__nv_bfloat162*)(olo + ob + e) = lp;
    }
}

// ---------------- layernorm (+ split outputs) ----------------
__global__ void __launch_bounds__(256)
ln_kernel(const float* __restrict__ in, const float* __restrict__ g,
          const float* __restrict__ be, float* __restrict__ out,
          __nv_bfloat16* __restrict__ ohi, __nv_bfloat16* __restrict__ olo)
{
    int row = blockIdx.x;
    int t = threadIdx.x;
    const float* p = in + (size_t)row*DD;
    float x0 = p[t], x1 = p[t+256], x2 = p[t+512];
    __shared__ float rs[256], rq[256];
    rs[t] = x0+x1+x2;
    rq[t] = x0*x0 + x1*x1 + x2*x2;
    __syncthreads();
    for (int off = 128; off > 0; off >>= 1) {
        if (t < off) { rs[t] += rs[t+off]; rq[t] += rq[t+off]; }
        __syncthreads();
    }
    float mean = rs[0] * (1.0f/768.0f);
    float var  = rq[0] * (1.0f/768.0f) - mean*mean;
    float rstd = rsqrtf(var + 1e-5f);
    size_t base = (size_t)row*DD;
#pragma unroll
    for (int q = 0; q < 3; q++) {
        int d = t + q*256;
        float x = (q==0) ? x0 : (q==1) ? x1 : x2;
        float v = (x-mean)*rstd*g[d] + be[d];
        out[base + d] = v;
        __nv_bfloat16 h = __float2bfloat16(v);
        ohi[base + d] = h;
        olo[base + d] = __float2bfloat16(v - __bfloat162float(h));
    }
}

// ---------------- host ----------------
extern "C" void kernel_launch(void* const* d_in, const int* in_sizes, int n_in,
                              void* d_out, int out_size)
{
    const int*   x    = (const int*)  d_in[0];
    const int*   pmsk = (const int*)  d_in[1];
    const float* emb  = (const float*)d_in[2];
    const float* Wq   = (const float*)d_in[3];
    const float* bq   = (const float*)d_in[4];
    const float* Wk   = (const float*)d_in[5];
    const float* bk   = (const float*)d_in[6];
    const float* Wv   = (const float*)d_in[7];
    const float* bv   = (const float*)d_in[8];
    const float* Wo   = (const float*)d_in[9];
    const float* bo   = (const float*)d_in[10];
    const float* W1   = (const float*)d_in[11];
    const float* b1   = (const float*)d_in[12];
    const float* W2   = (const float*)d_in[13];
    const float* b2   = (const float*)d_in[14];
    const float* g1   = (const float*)d_in[15];
    const float* be1  = (const float*)d_in[16];
    const float* g2   = (const float*)d_in[17];
    const float* be2  = (const float*)d_in[18];
    float* outp = (float*)d_out;

    float *hb, *qkvb, *tb, *bqkvb;
    __nv_bfloat16 *hhi, *hlo, *ohi, *olo, *fhi, *flo, *whi, *wlo;
    cudaGetSymbolAddress((void**)&hb,    g_h);
    cudaGetSymbolAddress((void**)&qkvb,  g_qkv);
    cudaGetSymbolAddress((void**)&tb,    g_t);
    cudaGetSymbolAddress((void**)&hhi,   g_hhi);
    cudaGetSymbolAddress((void**)&hlo,   g_hlo);
    cudaGetSymbolAddress((void**)&ohi,   g_ohi);
    cudaGetSymbolAddress((void**)&olo,   g_olo);
    cudaGetSymbolAddress((void**)&fhi,   g_fhi);
    cudaGetSymbolAddress((void**)&flo,   g_flo);
    cudaGetSymbolAddress((void**)&whi,   g_Whi);
    cudaGetSymbolAddress((void**)&wlo,   g_Wlo);
    cudaGetSymbolAddress((void**)&bqkvb, g_bqkv);

    cudaFuncSetAttribute(gemm_mma<0>, cudaFuncAttributeMaxDynamicSharedMemorySize, GEMM_SMEM);
    cudaFuncSetAttribute(gemm_mma<1>, cudaFuncAttributeMaxDynamicSharedMemorySize, GEMM_SMEM);
    cudaFuncSetAttribute(gemm_mma<2>, cudaFuncAttributeMaxDynamicSharedMemorySize, GEMM_SMEM);

    conv_wqkv<<<dim3(NQKV*DD/256, LL), 256>>>(Wq, Wk, Wv);
    conv_wo  <<<dim3(DD*DD/256,   LL), 256>>>(Wo);
    conv_w1  <<<dim3(FF*DD/256,   LL), 256>>>(W1);
    conv_w2  <<<dim3(DD*FF/256,   LL), 256>>>(W2);
    conv_bqkv<<<(LL*NQKV+255)/256, 256>>>(bq, bk, bv);

    pe_kernel<<<(SS*DD+255)/256, 256>>>();
    embed_kernel<<<(MM*DD+255)/256, 256>>>(x, emb);

    dim3 gQKV(NQKV/128, MM/128);
    dim3 gO  (DD/128,   MM/128);
    dim3 gF1 (FF/128,   MM/128);
    dim3 gAttn(BB*HH, SS/128);

    for (int l = 0; l < LL; l++) {
        const __nv_bfloat16* wh = whi + (size_t)l*LAYER_SZ;
        const __nv_bfloat16* wl = wlo + (size_t)l*LAYER_SZ;

        gemm_mma<0><<<gQKV, 256, GEMM_SMEM>>>(hhi, hlo, wh, wl,
            bqkvb + l*NQKV, nullptr, qkvb, nullptr, nullptr, DD, NQKV);

        attn_kernel<<<gAttn, 128>>>(qkvb, pmsk, ohi, olo);

        gemm_mma<2><<<gO, 256, GEMM_SMEM>>>(ohi, olo, wh + OFF_O, wl + OFF_O,
            bo + l*DD, hb, tb, nullptr, nullptr, DD, DD);
        ln_kernel<<<MM, 256>>>(tb, g1 + l*DD, be1 + l*DD, hb, hhi, hlo);

        gemm_mma<1><<<gF1, 256, GEMM_SMEM>>>(hhi, hlo, wh + OFF_W1, wl + OFF_W1,
            b1 + l*FF, nullptr, nullptr, fhi, flo, DD, FF);

        gemm_mma<2><<<gO, 256, GEMM_SMEM>>>(fhi, flo, wh + OFF_W2, wl + OFF_W2,
            b2 + l*DD, hb, tb, nullptr, nullptr, FF, DD);

        float* lnOut = (l == LL-1) ? outp : hb;
        ln_kernel<<<MM, 256>>>(tb, g2 + l*DD, be2 + l*DD, lnOut, hhi, hlo);
    }
}

// round 7
// speedup vs baseline: 2.8509x; 1.3315x over previous
#include <cuda_runtime.h>
#include <cuda_bf16.h>
#include <cstdint>
#include <math.h>

#define BB   16
#define SS   512
#define DD   768
#define HH   12
#define DNN  64
#define FF   3072
#define LL   6
#define MM   (BB*SS)
#define NQKV 2304

#define SZ_QKV (NQKV*DD)
#define SZ_O   (DD*DD)
#define SZ_W1  (FF*DD)
#define SZ_W2  (DD*FF)
#define OFF_O   SZ_QKV
#define OFF_W1  (OFF_O + SZ_O)
#define OFF_W2  (OFF_W1 + SZ_W1)
#define LAYER_SZ (OFF_W2 + SZ_W2)

// ---------------- scratch ----------------
__device__ __align__(16) float g_pe [SS*DD];
__device__ __align__(16) float g_h  [MM*DD];
__device__ __align__(16) float g_t  [MM*DD];
__device__ __align__(16) __nv_bfloat16 g_hhi[(size_t)MM*DD];
__device__ __align__(16) __nv_bfloat16 g_hlo[(size_t)MM*DD];
__device__ __align__(16) __nv_bfloat16 g_qkvh[(size_t)MM*NQKV];
__device__ __align__(16) __nv_bfloat16 g_qkvl[(size_t)MM*NQKV];
__device__ __align__(16) __nv_bfloat16 g_ohi[(size_t)MM*DD];
__device__ __align__(16) __nv_bfloat16 g_olo[(size_t)MM*DD];
__device__ __align__(16) __nv_bfloat16 g_fhi[(size_t)MM*FF];
__device__ __align__(16) __nv_bfloat16 g_flo[(size_t)MM*FF];
__device__ __align__(16) __nv_bfloat16 g_Whi[(size_t)LL*LAYER_SZ];
__device__ __align__(16) __nv_bfloat16 g_Wlo[(size_t)LL*LAYER_SZ];
__device__ __align__(16) float g_bqkv[LL*NQKV];

// ======================= PTX helpers =======================
__device__ __forceinline__ uint32_t smem_u32(const void* p) {
    uint32_t a;
    asm("{ .reg .u64 t; cvta.to.shared.u64 t, %1; cvt.u32.u64 %0, t; }" : "=r"(a) : "l"(p));
    return a;
}
#define CP_ASYNC(dst, src) \
    asm volatile("cp.async.cg.shared.global [%0], [%1], 16;" :: "r"(dst), "l"(src) : "memory")
#define CP_COMMIT() asm volatile("cp.async.commit_group;" ::: "memory")
#define CP_WAIT1()  asm volatile("cp.async.wait_group 1;" ::: "memory")
#define CP_WAIT0()  asm volatile("cp.async.wait_group 0;" ::: "memory")

#define LDSM4(r, addr) \
    asm volatile("ldmatrix.sync.aligned.m8n8.x4.shared.b16 {%0,%1,%2,%3}, [%4];" \
        : "=r"((r)[0]), "=r"((r)[1]), "=r"((r)[2]), "=r"((r)[3]) : "r"(addr))
#define LDSM2(r, addr) \
    asm volatile("ldmatrix.sync.aligned.m8n8.x2.shared.b16 {%0,%1}, [%2];" \
        : "=r"((r)[0]), "=r"((r)[1]) : "r"(addr))
#define LDSM2T(r, addr) \
    asm volatile("ldmatrix.sync.aligned.m8n8.x2.trans.shared.b16 {%0,%1}, [%2];" \
        : "=r"((r)[0]), "=r"((r)[1]) : "r"(addr))
#define MMA16816(c, a, b) \
    asm volatile("mma.sync.aligned.m16n8k16.row.col.f32.bf16.bf16.f32 " \
        "{%0,%1,%2,%3},{%4,%5,%6,%7},{%8,%9},{%0,%1,%2,%3};" \
        : "+f"((c)[0]), "+f"((c)[1]), "+f"((c)[2]), "+f"((c)[3]) \
        : "r"((a)[0]), "r"((a)[1]), "r"((a)[2]), "r"((a)[3]), "r"((b)[0]), "r"((b)[1]))

// fast exp on fma pipe: exp(x) = 2^(x*log2e), rn-int trick + degree-5 poly
__device__ __forceinline__ float fexp(float x) {
    x = fminf(fmaxf(x, -60.f), 60.f);
    float y = x * 1.4426950408889634f;
    float t = y + 12582912.0f;
    int n = __float_as_int(t) - 0x4B400000;
    float f = y - (t - 12582912.0f);
    float p =       1.3333558e-3f;
    p = fmaf(p, f,  9.6181291e-3f);
    p = fmaf(p, f,  5.5504109e-2f);
    p = fmaf(p, f,  2.4022651e-1f);
    p = fmaf(p, f,  6.9314718e-1f);
    p = fmaf(p, f,  1.0f);
    return __int_as_float(__float_as_int(p) + (n << 23));
}

// ======================= weight conversion =======================
__device__ __forceinline__ void wsplit(float v, __nv_bfloat16* hi, __nv_bfloat16* lo, size_t o){
    __nv_bfloat16 h = __float2bfloat16(v);
    hi[o] = h;
    lo[o] = __float2bfloat16(v - __bfloat162float(h));
}

__global__ void conv_wqkv(const float* __restrict__ Wq, const float* __restrict__ Wk,
                          const float* __restrict__ Wv)
{
    int l = blockIdx.y;
    int idx = blockIdx.x*256 + threadIdx.x;
    int n = idx / DD, k = idx % DD;
    int sec = n / DD, r = n % DD;
    int h = r >> 6, e = r & 63;
    const float* W = sec==0 ? Wq : (sec==1 ? Wk : Wv);
    float v = W[(((size_t)l*HH + h)*DD + k)*DNN + e];
    wsplit(v, g_Whi, g_Wlo, (size_t)l*LAYER_SZ + (size_t)n*DD + k);
}
__global__ void conv_wo(const float* __restrict__ Wo)
{
    int l = blockIdx.y;
    int idx = blockIdx.x*256 + threadIdx.x;
    int n = idx / DD, k = idx % DD;
    float v = Wo[((size_t)l*DD + k)*DD + n];
    wsplit(v, g_Whi, g_Wlo, (size_t)l*LAYER_SZ + OFF_O + (size_t)n*DD + k);
}
__global__ void conv_w1(const float* __restrict__ W1)
{
    int l = blockIdx.y;
    int idx = blockIdx.x*256 + threadIdx.x;
    int n = idx / DD, k = idx % DD;
    float v = W1[((size_t)l*DD + k)*FF + n];
    wsplit(v, g_Whi, g_Wlo, (size_t)l*LAYER_SZ + OFF_W1 + (size_t)n*DD + k);
}
__global__ void conv_w2(const float* __restrict__ W2)
{
    int l = blockIdx.y;
    int idx = blockIdx.x*256 + threadIdx.x;
    int n = idx / FF, k = idx % FF;
    float v = W2[((size_t)l*FF + k)*DD + n];
    wsplit(v, g_Whi, g_Wlo, (size_t)l*LAYER_SZ + OFF_W2 + (size_t)n*FF + k);
}
__global__ void conv_bqkv(const float* __restrict__ bq, const float* __restrict__ bk,
                          const float* __restrict__ bv)
{
    int idx = blockIdx.x*blockDim.x + threadIdx.x;
    if (idx >= LL*NQKV) return;
    int l = idx / NQKV, n = idx % NQKV;
    int sec = n / DD, r = n % DD;
    const float* b = sec==0 ? bq : (sec==1 ? bk : bv);
    g_bqkv[idx] = b[l*DD + r];
}

// ======================= fused-chunk HMMA split-bf16 GEMM =======================
#define NST 3
#define TILE_B 8192
#define STAGE_B (4*TILE_B)
#define GEMM_SMEM (NST*STAGE_B)   // 98304

__device__ __forceinline__ uint32_t swz(int r, int cg) {
    return (uint32_t)(r*64 + ((cg ^ ((r>>1)&3))<<4));
}

// EPI 1: relu(+bias) -> bf16 hi/lo | 2: +bias+res -> fp32 | 3: +bias -> bf16 hi/lo
template<int EPI>
__global__ void __launch_bounds__(256, 2)
gemm_mma(const __nv_bfloat16* __restrict__ Ahi, const __nv_bfloat16* __restrict__ Alo,
         const __nv_bfloat16* __restrict__ Bhi, const __nv_bfloat16* __restrict__ Blo,
         const float* __restrict__ bias, const float* __restrict__ res,
         float* __restrict__ outf, __nv_bfloat16* __restrict__ outhi,
         __nv_bfloat16* __restrict__ outlo, int K, int Ndim)
{
    extern __shared__ char sm[];
    int tid = threadIdx.x, wid = tid >> 5, lid = tid & 31;
    int m0 = blockIdx.y * 128, c0 = blockIdx.x * 128;
    int warp_m = (wid & 1) * 64, warp_n = (wid >> 1) * 32;
    int NCH = K >> 5;

    float c[4][4][4];
#pragma unroll
    for (int i=0;i<4;i++)
#pragma unroll
        for (int j=0;j<4;j++)
#pragma unroll
            for (int q=0;q<4;q++) c[i][j][q] = 0.f;

    auto load_chunk = [&](int ci, int st) {
        int k0 = ci << 5;
        char* base = sm + st * STAGE_B;
#pragma unroll
        for (int i = 0; i < 8; i++) {
            int seg = tid + i*256;
            int tl  = seg >> 9;
            int rem = seg & 511;
            int r   = rem >> 2, cg = rem & 3;
            const __nv_bfloat16* src;
            if      (tl == 0) src = Ahi + (size_t)(m0 + r)*K + k0 + cg*8;
            else if (tl == 1) src = Alo + (size_t)(m0 + r)*K + k0 + cg*8;
            else if (tl == 2) src = Bhi + (size_t)(c0 + r)*K + k0 + cg*8;
            else              src = Blo + (size_t)(c0 + r)*K + k0 + cg*8;
            CP_ASYNC(smem_u32(base + tl*TILE_B + swz(r, cg)), src);
        }
        CP_COMMIT();
    };

    load_chunk(0, 0);
    load_chunk(1, 1);

    for (int ci = 0; ci < NCH; ci++) {
        int st = ci % 3;
        CP_WAIT1();
        __syncthreads();
        int nci = ci + 2;
        if (nci < NCH) load_chunk(nci, nci % 3);
        else CP_COMMIT();

        uint32_t base = smem_u32(sm + st * STAGE_B);
#pragma unroll
        for (int ks = 0; ks < 2; ks++) {
            uint32_t ah[4][4], al[4][4], bh[4][2], bl[4][2];
            int acg = ks*2 + (lid >> 4);
            int bcg = ks*2 + ((lid >> 3) & 1);
#pragma unroll
            for (int mt = 0; mt < 4; mt++) {
                int r = warp_m + mt*16 + (lid & 15);
                LDSM4(ah[mt], base + 0*TILE_B + swz(r, acg));
                LDSM4(al[mt], base + 1*TILE_B + swz(r, acg));
            }
#pragma unroll
            for (int nt = 0; nt < 4; nt++) {
                int r = warp_n + nt*8 + (lid & 7);
                LDSM2(bh[nt], base + 2*TILE_B + swz(r, bcg));
                LDSM2(bl[nt], base + 3*TILE_B + swz(r, bcg));
            }
#pragma unroll
            for (int mt = 0; mt < 4; mt++)
#pragma unroll
                for (int nt = 0; nt < 4; nt++) {
                    MMA16816(c[mt][nt], ah[mt], bh[nt]);
                    MMA16816(c[mt][nt], al[mt], bh[nt]);
                    MMA16816(c[mt][nt], ah[mt], bl[nt]);
                }
        }
    }

    int g = lid >> 2, t2 = (lid & 3) * 2;
#pragma unroll
    for (int mt = 0; mt < 4; mt++) {
#pragma unroll
        for (int half = 0; half < 2; half++) {
            long m = m0 + warp_m + mt*16 + g + half*8;
#pragma unroll
            for (int nt = 0; nt < 4; nt++) {
                int col = c0 + warp_n + nt*8 + t2;
                float v0 = c[mt][nt][half*2+0] + bias[col];
                float v1 = c[mt][nt][half*2+1] + bias[col+1];
                if (EPI == 1 || EPI == 3) {
                    if (EPI == 1) { v0 = fmaxf(v0, 0.f); v1 = fmaxf(v1, 0.f); }
                    __nv_bfloat162 hp, lp;
                    hp.x = __float2bfloat16(v0);
                    hp.y = __float2bfloat16(v1);
                    lp.x = __float2bfloat16(v0 - __bfloat162float(hp.x));
                    lp.y = __float2bfloat16(v1 - __bfloat162float(hp.y));
                    *(__nv_bfloat162*)(outhi + m*(long)Ndim + col) = hp;
                    *(__nv_bfloat162*)(outlo + m*(long)Ndim + col) = lp;
                } else {
                    const float* rrow = res + m*(long)Ndim;
                    v0 += rrow[col]; v1 += rrow[col+1];
                    *(float2*)(outf + m*(long)Ndim + col) = make_float2(v0, v1);
                }
            }
        }
    }
}

// ======================= tensor-core attention =======================
// block: (b,h) x 128 q-rows, 8 warps (16 rows each). Split-bf16 QK^T and PV.
#define AT_QH 0
#define AT_QL 18432
#define AT_ST0 36864
#define AT_KH 0
#define AT_KL 9216
#define AT_VH 18432
#define AT_VL 27648
#define AT_MS 36864
#define AT_STAGE 69632
#define AT_SMEM (AT_ST0 + 2*AT_STAGE)   // 176128

__global__ void __launch_bounds__(256, 1)
attn_mma(const __nv_bfloat16* __restrict__ qvh, const __nv_bfloat16* __restrict__ qvl,
         const int* __restrict__ mask,
         __nv_bfloat16* __restrict__ ohi, __nv_bfloat16* __restrict__ olo)
{
    extern __shared__ char smn[];
    int tid = threadIdx.x, wid = tid >> 5, lid = tid & 31;
    int bh = blockIdx.x;
    int b = bh / HH, h = bh % HH;
    int sq0 = blockIdx.y * 128;
    const size_t rowbase = (size_t)b * SS;
    int g = lid >> 2, t2 = lid & 3;

    // ---- prologue: Q (hi/lo) + chunk 0 in one group
#pragma unroll
    for (int i = 0; i < 8; i++) {
        int s = tid + i*256;
        int arr = s >> 10, rem = s & 1023;
        int r = rem >> 3, cg = rem & 7;
        const __nv_bfloat16* src = (arr ? qvl : qvh) +
            (rowbase + sq0 + r)*(size_t)NQKV + h*DNN + cg*8;
        CP_ASYNC(smem_u32(smn + arr*18432 + r*144 + cg*16), src);
    }

    auto load_kv = [&](int kci, int st) {
        int kc = kci * 64;
        char* base = smn + AT_ST0 + st*AT_STAGE;
#pragma unroll
        for (int i = 0; i < 8; i++) {
            int s = tid + i*256;
            int tl = s >> 9, rem = s & 511;
            int r = rem >> 3, cg = rem & 7;
            size_t off = (rowbase + kc + r)*(size_t)NQKV + h*DNN + cg*8;
            const __nv_bfloat16* src;
            if      (tl == 0) src = qvh + off + DD;
            else if (tl == 1) src = qvl + off + DD;
            else if (tl == 2) src = qvh + off + 2*DD;
            else              src = qvl + off + 2*DD;
            CP_ASYNC(smem_u32(base + tl*9216 + r*144 + cg*16), src);
        }
#pragma unroll
        for (int i = 0; i < 8; i++) {
            int s = tid + i*256;
            int r = s >> 4, seg = s & 15;
            CP_ASYNC(smem_u32(base + AT_MS + r*256 + seg*16),
                     mask + (rowbase + sq0 + r)*(size_t)SS + kc + seg*4);
        }
        CP_COMMIT();
    };

    load_kv(0, 0);

    uint32_t qfh[4][4], qfl[4][4];
    float o[8][4];
#pragma unroll
    for (int nt = 0; nt < 8; nt++)
#pragma unroll
        for (int q = 0; q < 4; q++) o[nt][q] = 0.f;
    float rs0 = 0.f, rs1 = 0.f;

    for (int ci = 0; ci < 8; ci++) {
        int st = ci & 1;
        CP_WAIT0();
        __syncthreads();
        if (ci == 0) {
            uint32_t qb = smem_u32(smn);
#pragma unroll
            for (int kg = 0; kg < 4; kg++) {
                uint32_t qa = qb + (wid*16 + (lid & 15))*144 + kg*32 + (lid >> 4)*16;
                LDSM4(qfh[kg], qa);
                LDSM4(qfl[kg], qa + 18432);
            }
        }
        if (ci < 7) load_kv(ci + 1, st ^ 1);

        uint32_t sb = smem_u32(smn + AT_ST0 + st*AT_STAGE);
        float s[8][4];
#pragma unroll
        for (int nt = 0; nt < 8; nt++)
#pragma unroll
            for (int q = 0; q < 4; q++) s[nt][q] = 0.f;

        // S = Q K^T (split-bf16)
#pragma unroll
        for (int kg = 0; kg < 4; kg++) {
#pragma unroll
            for (int nt = 0; nt < 8; nt++) {
                uint32_t bh2[2], bl2[2];
                uint32_t ka = sb + (nt*8 + (lid & 7))*144 + kg*32 + ((lid >> 3) & 1)*16;
                LDSM2(bh2, ka + AT_KH);
                LDSM2(bl2, ka + AT_KL);
                MMA16816(s[nt], qfh[kg], bh2);
                MMA16816(s[nt], qfl[kg], bh2);
                MMA16816(s[nt], qfh[kg], bl2);
            }
        }

        // softmax numerator + pack P into A-frags (hi/lo)
        // mask rows for this warp: query rows wid*16 + g and wid*16 + g + 8
        const int* msm = (const int*)(smn + AT_ST0 + st*AT_STAGE + AT_MS);
        const int* mr0 = msm + (wid*16 + g)*64;
        const int* mr1 = msm + (wid*16 + g + 8)*64;
        uint32_t aPh[4][4], aPl[4][4];
#pragma unroll
        for (int nt = 0; nt < 8; nt++) {
            int2 m0 = *(const int2*)(mr0 + nt*8 + t2*2);
            int2 m1 = *(const int2*)(mr1 + nt*8 + t2*2);
            float p0 = m0.x ? 0.f : fexp(s[nt][0]*0.125f);
            float p1 = m0.y ? 0.f : fexp(s[nt][1]*0.125f);
            float p2 = m1.x ? 0.f : fexp(s[nt][2]*0.125f);
            float p3 = m1.y ? 0.f : fexp(s[nt][3]*0.125f);
            rs0 += p0 + p1;
            rs1 += p2 + p3;
            __nv_bfloat162 h01 = __floats2bfloat162_rn(p0, p1);
            __nv_bfloat162 h23 = __floats2bfloat162_rn(p2, p3);
            __nv_bfloat162 l01 = __floats2bfloat162_rn(p0 - __low2float(h01), p1 - __high2float(h01));
            __nv_bfloat162 l23 = __floats2bfloat162_rn(p2 - __low2float(h23), p3 - __high2float(h23));
            int kg = nt >> 1, sub = (nt & 1)*2;
            aPh[kg][sub]   = *(uint32_t*)&h01;
            aPh[kg][sub+1] = *(uint32_t*)&h23;
            aPl[kg][sub]   = *(uint32_t*)&l01;
            aPl[kg][sub+1] = *(uint32_t*)&l23;
        }

        // O += P V (split-bf16), V via ldmatrix.trans
#pragma unroll
        for (int kg = 0; kg < 4; kg++) {
#pragma unroll
            for (int nt = 0; nt < 8; nt++) {
                uint32_t vh2[2], vl2[2];
                uint32_t va = sb + (kg*16 + (lid & 15))*144 + nt*16;
                LDSM2T(vh2, va + AT_VH);
                LDSM2T(vl2, va + AT_VL);
                MMA16816(o[nt], aPh[kg], vh2);
                MMA16816(o[nt], aPl[kg], vh2);
                MMA16816(o[nt], aPh[kg], vl2);
            }
        }
    }

    // row-sum reduce across the quad, normalize, split-store
    rs0 += __shfl_xor_sync(0xFFFFFFFFu, rs0, 1);
    rs0 += __shfl_xor_sync(0xFFFFFFFFu, rs0, 2);
    rs1 += __shfl_xor_sync(0xFFFFFFFFu, rs1, 1);
    rs1 += __shfl_xor_sync(0xFFFFFFFFu, rs1, 2);
    float inv0 = 1.f / rs0, inv1 = 1.f / rs1;

    long r0 = rowbase + sq0 + wid*16 + g;
    int colb = h*DNN + t2*2;
#pragma unroll
    for (int nt = 0; nt < 8; nt++) {
        int col = colb + nt*8;
        float v0 = o[nt][0]*inv0, v1 = o[nt][1]*inv0;
        float v2 = o[nt][2]*inv1, v3 = o[nt][3]*inv1;
        __nv_bfloat162 hp0, lp0, hp1, lp1;
        hp0 = __floats2bfloat162_rn(v0, v1);
        lp0 = __floats2bfloat162_rn(v0 - __low2float(hp0), v1 - __high2float(hp0));
        hp1 = __floats2bfloat162_rn(v2, v3);
        lp1 = __floats2bfloat162_rn(v2 - __low2float(hp1), v3 - __high2float(hp1));
        *(__nv_bfloat162*)(ohi + r0*DD + col)     = hp0;
        *(__nv_bfloat162*)(olo + r0*DD + col)     = lp0;
        *(__nv_bfloat162*)(ohi + (r0+8)*DD + col) = hp1;
        *(__nv_bfloat162*)(olo + (r0+8)*DD + col) = lp1;
    }
}

// ---------------- positional encoding ----------------
__global__ void pe_kernel()
{
    int idx = blockIdx.x*blockDim.x + threadIdx.x;
    if (idx >= SS*DD) return;
    int s = idx / DD, d = idx % DD;
    const float LOG10000 = 9.210340371976184f;
    float val;
    int i = d >> 1;
    if ((d & 1) == 0) {
        float freq = expf(-(2.0f*i/DD)*LOG10000);
        val = sinf(s*freq);
    } else {
        float freq = expf(-(2.0f*(i+1)/DD)*LOG10000);
        val = cosf(s*freq);
    }
    g_pe[idx] = val;
}

// ---------------- embedding + PE (+ split) ----------------
__global__ void embed_kernel(const int* __restrict__ x, const float* __restrict__ emb)
{
    int idx = blockIdx.x*blockDim.x + threadIdx.x;
    if (idx >= MM*DD) return;
    int m = idx / DD, d = idx % DD;
    int s = m % SS;
    int tok = x[m];
    float v = emb[(size_t)tok*DD + d] + g_pe[s*DD + d];
    g_h[idx] = v;
    __nv_bfloat16 h = __float2bfloat16(v);
    g_hhi[idx] = h;
    g_hlo[idx] = __float2bfloat16(v - __bfloat162float(h));
}

// ---------------- layernorm (+ split outputs) ----------------
__global__ void __launch_bounds__(256)
ln_kernel(const float* __restrict__ in, const float* __restrict__ g,
          const float* __restrict__ be, float* __restrict__ out,
          __nv_bfloat16* __restrict__ ohi, __nv_bfloat16* __restrict__ olo)
{
    int row = blockIdx.x;
    int t = threadIdx.x;
    const float* p = in + (size_t)row*DD;
    float x0 = p[t], x1 = p[t+256], x2 = p[t+512];
    __shared__ float rs[256], rq[256];
    rs[t] = x0+x1+x2;
    rq[t] = x0*x0 + x1*x1 + x2*x2;
    __syncthreads();
    for (int off = 128; off > 0; off >>= 1) {
        if (t < off) { rs[t] += rs[t+off]; rq[t] += rq[t+off]; }
        __syncthreads();
    }
    float mean = rs[0] * (1.0f/768.0f);
    float var  = rq[0] * (1.0f/768.0f) - mean*mean;
    float rstd = rsqrtf(var + 1e-5f);
    size_t base = (size_t)row*DD;
#pragma unroll
    for (int q = 0; q < 3; q++) {
        int d = t + q*256;
        float x = (q==0) ? x0 : (q==1) ? x1 : x2;
        float v = (x-mean)*rstd*g[d] + be[d];
        out[base + d] = v;
        __nv_bfloat16 h = __float2bfloat16(v);
        ohi[base + d] = h;
        olo[base + d] = __float2bfloat16(v - __bfloat162float(h));
    }
}

// ---------------- host ----------------
extern "C" void kernel_launch(void* const* d_in, const int* in_sizes, int n_in,
                              void* d_out, int out_size)
{
    const int*   x    = (const int*)  d_in[0];
    const int*   pmsk = (const int*)  d_in[1];
    const float* emb  = (const float*)d_in[2];
    const float* Wq   = (const float*)d_in[3];
    const float* bq   = (const float*)d_in[4];
    const float* Wk   = (const float*)d_in[5];
    const float* bk   = (const float*)d_in[6];
    const float* Wv   = (const float*)d_in[7];
    const float* bv   = (const float*)d_in[8];
    const float* Wo   = (const float*)d_in[9];
    const float* bo   = (const float*)d_in[10];
    const float* W1   = (const float*)d_in[11];
    const float* b1   = (const float*)d_in[12];
    const float* W2   = (const float*)d_in[13];
    const float* b2   = (const float*)d_in[14];
    const float* g1   = (const float*)d_in[15];
    const float* be1  = (const float*)d_in[16];
    const float* g2   = (const float*)d_in[17];
    const float* be2  = (const float*)d_in[18];
    float* outp = (float*)d_out;

    float *hb, *tb, *bqkvb;
    __nv_bfloat16 *hhi, *hlo, *qkvh, *qkvl, *ohi, *olo, *fhi, *flo, *whi, *wlo;
    cudaGetSymbolAddress((void**)&hb,    g_h);
    cudaGetSymbolAddress((void**)&tb,    g_t);
    cudaGetSymbolAddress((void**)&hhi,   g_hhi);
    cudaGetSymbolAddress((void**)&hlo,   g_hlo);
    cudaGetSymbolAddress((void**)&qkvh,  g_qkvh);
    cudaGetSymbolAddress((void**)&qkvl,  g_qkvl);
    cudaGetSymbolAddress((void**)&ohi,   g_ohi);
    cudaGetSymbolAddress((void**)&olo,   g_olo);
    cudaGetSymbolAddress((void**)&fhi,   g_fhi);
    cudaGetSymbolAddress((void**)&flo,   g_flo);
    cudaGetSymbolAddress((void**)&whi,   g_Whi);
    cudaGetSymbolAddress((void**)&wlo,   g_Wlo);
    cudaGetSymbolAddress((void**)&bqkvb, g_bqkv);

    cudaFuncSetAttribute(gemm_mma<1>, cudaFuncAttributeMaxDynamicSharedMemorySize, GEMM_SMEM);
    cudaFuncSetAttribute(gemm_mma<2>, cudaFuncAttributeMaxDynamicSharedMemorySize, GEMM_SMEM);
    cudaFuncSetAttribute(gemm_mma<3>, cudaFuncAttributeMaxDynamicSharedMemorySize, GEMM_SMEM);
    cudaFuncSetAttribute(attn_mma,    cudaFuncAttributeMaxDynamicSharedMemorySize, AT_SMEM);

    conv_wqkv<<<dim3(NQKV*DD/256, LL), 256>>>(Wq, Wk, Wv);
    conv_wo  <<<dim3(DD*DD/256,   LL), 256>>>(Wo);
    conv_w1  <<<dim3(FF*DD/256,   LL), 256>>>(W1);
    conv_w2  <<<dim3(DD*FF/256,   LL), 256>>>(W2);
    conv_bqkv<<<(LL*NQKV+255)/256, 256>>>(bq, bk, bv);

    pe_kernel<<<(SS*DD+255)/256, 256>>>();
    embed_kernel<<<(MM*DD+255)/256, 256>>>(x, emb);

    dim3 gQKV(NQKV/128, MM/128);
    dim3 gO  (DD/128,   MM/128);
    dim3 gF1 (FF/128,   MM/128);
    dim3 gAttn(BB*HH, SS/128);

    for (int l = 0; l < LL; l++) {
        const __nv_bfloat16* wh = whi + (size_t)l*LAYER_SZ;
        const __nv_bfloat16* wl = wlo + (size_t)l*LAYER_SZ;

        gemm_mma<3><<<gQKV, 256, GEMM_SMEM>>>(hhi, hlo, wh, wl,
            bqkvb + l*NQKV, nullptr, nullptr, qkvh, qkvl, DD, NQKV);

        attn_mma<<<gAttn, 256, AT_SMEM>>>(qkvh, qkvl, pmsk, ohi, olo);

        gemm_mma<2><<<gO, 256, GEMM_SMEM>>>(ohi, olo, wh + OFF_O, wl + OFF_O,
            bo + l*DD, hb, tb, nullptr, nullptr, DD, DD);
        ln_kernel<<<MM, 256>>>(tb, g1 + l*DD, be1 + l*DD, hb, hhi, hlo);

        gemm_mma<1><<<gF1, 256, GEMM_SMEM>>>(hhi, hlo, wh + OFF_W1, wl + OFF_W1,
            b1 + l*FF, nullptr, nullptr, fhi, flo, DD, FF);

        gemm_mma<2><<<gO, 256, GEMM_SMEM>>>(fhi, flo, wh + OFF_W2, wl + OFF_W2,
            b2 + l*DD, hb, tb, nullptr, nullptr, FF, DD);

        float* lnOut = (l == LL-1) ? outp : hb;
        ln_kernel<<<MM, 256>>>(tb, g2 + l*DD, be2 + l*DD, lnOut, hhi, hlo);
    }
}

// round 8
// speedup vs baseline: 2.9788x; 1.0448x over previous
#include <cuda_runtime.h>
#include <cuda_bf16.h>
#include <cstdint>
#include <math.h>

#define BB   16
#define SS   512
#define DD   768
#define HH   12
#define DNN  64
#define FF   3072
#define LL   6
#define MM   (BB*SS)
#define NQKV 2304

#define SZ_QKV (NQKV*DD)
#define SZ_O   (DD*DD)
#define SZ_W1  (FF*DD)
#define SZ_W2  (DD*FF)
#define OFF_O   SZ_QKV
#define OFF_W1  (OFF_O + SZ_O)
#define OFF_W2  (OFF_W1 + SZ_W1)
#define LAYER_SZ (OFF_W2 + SZ_W2)

// ---------------- scratch ----------------
__device__ __align__(16) float g_pe [SS*DD];
__device__ __align__(16) float g_h  [MM*DD];
__device__ __align__(16) float g_t  [MM*DD];
__device__ __align__(16) __nv_bfloat16 g_hhi[(size_t)MM*DD];
__device__ __align__(16) __nv_bfloat16 g_hlo[(size_t)MM*DD];
__device__ __align__(16) __nv_bfloat16 g_qkvh[(size_t)MM*NQKV];
__device__ __align__(16) __nv_bfloat16 g_qkvl[(size_t)MM*NQKV];
__device__ __align__(16) __nv_bfloat16 g_ohi[(size_t)MM*DD];
__device__ __align__(16) __nv_bfloat16 g_olo[(size_t)MM*DD];
__device__ __align__(16) __nv_bfloat16 g_fhi[(size_t)MM*FF];
__device__ __align__(16) __nv_bfloat16 g_flo[(size_t)MM*FF];
__device__ __align__(16) __nv_bfloat16 g_Whi[(size_t)LL*LAYER_SZ];
__device__ __align__(16) __nv_bfloat16 g_Wlo[(size_t)LL*LAYER_SZ];
__device__ __align__(16) unsigned char g_mask8[(size_t)BB*SS*SS];

// ======================= PTX helpers =======================
__device__ __forceinline__ uint32_t smem_u32(const void* p) {
    uint32_t a;
    asm("{ .reg .u64 t; cvta.to.shared.u64 t, %1; cvt.u32.u64 %0, t; }" : "=r"(a) : "l"(p));
    return a;
}
#define CP_ASYNC(dst, src) \
    asm volatile("cp.async.cg.shared.global [%0], [%1], 16;" :: "r"(dst), "l"(src) : "memory")
#define CP_COMMIT() asm volatile("cp.async.commit_group;" ::: "memory")
#define CP_WAIT1()  asm volatile("cp.async.wait_group 1;" ::: "memory")
#define CP_WAIT0()  asm volatile("cp.async.wait_group 0;" ::: "memory")

#define LDSM4(r, addr) \
    asm volatile("ldmatrix.sync.aligned.m8n8.x4.shared.b16 {%0,%1,%2,%3}, [%4];" \
        : "=r"((r)[0]), "=r"((r)[1]), "=r"((r)[2]), "=r"((r)[3]) : "r"(addr))
#define LDSM2(r, addr) \
    asm volatile("ldmatrix.sync.aligned.m8n8.x2.shared.b16 {%0,%1}, [%2];" \
        : "=r"((r)[0]), "=r"((r)[1]) : "r"(addr))
#define LDSM2T(r, addr) \
    asm volatile("ldmatrix.sync.aligned.m8n8.x2.trans.shared.b16 {%0,%1}, [%2];" \
        : "=r"((r)[0]), "=r"((r)[1]) : "r"(addr))
#define MMA16816(c, a, b) \
    asm volatile("mma.sync.aligned.m16n8k16.row.col.f32.bf16.bf16.f32 " \
        "{%0,%1,%2,%3},{%4,%5,%6,%7},{%8,%9},{%0,%1,%2,%3};" \
        : "+f"((c)[0]), "+f"((c)[1]), "+f"((c)[2]), "+f"((c)[3]) \
        : "r"((a)[0]), "r"((a)[1]), "r"((a)[2]), "r"((a)[3]), "r"((b)[0]), "r"((b)[1]))

// fast exp on fma pipe
__device__ __forceinline__ float fexp(float x) {
    x = fminf(fmaxf(x, -60.f), 60.f);
    float y = x * 1.4426950408889634f;
    float t = y + 12582912.0f;
    int n = __float_as_int(t) - 0x4B400000;
    float f = y - (t - 12582912.0f);
    float p =       1.3333558e-3f;
    p = fmaf(p, f,  9.6181291e-3f);
    p = fmaf(p, f,  5.5504109e-2f);
    p = fmaf(p, f,  2.4022651e-1f);
    p = fmaf(p, f,  6.9314718e-1f);
    p = fmaf(p, f,  1.0f);
    return __int_as_float(__float_as_int(p) + (n << 23));
}

// ======================= tiled transpose + hi/lo split =======================
// src[z]: [R, C] row-major. dst[z]: [C, R] (row stride R).
__device__ __forceinline__ void tsplit_body(const float* __restrict__ src,
                                            __nv_bfloat16* __restrict__ hi,
                                            __nv_bfloat16* __restrict__ lo,
                                            int R, int C)
{
    __shared__ float t[32][33];
    int c0 = blockIdx.x*32, r0 = blockIdx.y*32;
    int tx = threadIdx.x & 31, ty = threadIdx.x >> 5;    // ty 0..7
#pragma unroll
    for (int i = 0; i < 32; i += 8)
        t[ty+i][tx] = src[(size_t)(r0+ty+i)*C + c0+tx];
    __syncthreads();
#pragma unroll
    for (int i = 0; i < 32; i += 8) {
        float v = t[tx][ty+i];
        size_t o = (size_t)(c0+ty+i)*R + r0+tx;
        __nv_bfloat16 h = __float2bfloat16(v);
        hi[o] = h;
        lo[o] = __float2bfloat16(v - __bfloat162float(h));
    }
}

__global__ void tsplit(const float* __restrict__ src, __nv_bfloat16* __restrict__ hi,
                       __nv_bfloat16* __restrict__ lo, int R, int C,
                       size_t sStride, size_t dStride)
{
    int z = blockIdx.z;
    tsplit_body(src + z*sStride, hi + z*dStride, lo + z*dStride, R, C);
}

__global__ void tsplit_qkv(const float* __restrict__ Wq, const float* __restrict__ Wk,
                           const float* __restrict__ Wv)
{
    int z = blockIdx.z;                    // l*36 + sec*12 + h
    int l = z / 36, rem = z % 36, sec = rem / 12, h = rem % 12;
    const float* W = sec==0 ? Wq : (sec==1 ? Wk : Wv);
    const float* src = W + ((size_t)l*HH + h)*DD*DNN;          // [DD, 64]
    size_t dofs = (size_t)l*LAYER_SZ + (size_t)(sec*DD + h*DNN)*DD;
    tsplit_body(src, g_Whi + dofs, g_Wlo + dofs, DD, DNN);
}

__global__ void mask_conv(const int* __restrict__ m)
{
    int i = blockIdx.x*256 + threadIdx.x;       // 1,048,576 int4s
    int4 v = ((const int4*)m)[i];
    ((uchar4*)g_mask8)[i] = make_uchar4((unsigned char)v.x, (unsigned char)v.y,
                                        (unsigned char)v.z, (unsigned char)v.w);
}

// ======================= fused-chunk HMMA split-bf16 GEMM =======================
#define NST 3
#define TILE_B 8192
#define STAGE_B (4*TILE_B)
#define GEMM_SMEM (NST*STAGE_B)   // 98304

__device__ __forceinline__ uint32_t swz(int r, int cg) {
    return (uint32_t)(r*64 + ((cg ^ ((r>>1)&3))<<4));
}

// EPI 1: relu(+bias) -> bf16 hi/lo | 2: +bias+res -> fp32 | 3: +qkv-bias -> bf16 hi/lo
template<int EPI>
__global__ void __launch_bounds__(256, 2)
gemm_mma(const __nv_bfloat16* __restrict__ Ahi, const __nv_bfloat16* __restrict__ Alo,
         const __nv_bfloat16* __restrict__ Bhi, const __nv_bfloat16* __restrict__ Blo,
         const float* __restrict__ bias, const float* __restrict__ biasK,
         const float* __restrict__ biasV, const float* __restrict__ res,
         float* __restrict__ outf, __nv_bfloat16* __restrict__ outhi,
         __nv_bfloat16* __restrict__ outlo, int K, int Ndim)
{
    extern __shared__ char sm[];
    int tid = threadIdx.x, wid = tid >> 5, lid = tid & 31;
    int m0 = blockIdx.y * 128, c0 = blockIdx.x * 128;
    int warp_m = (wid & 1) * 64, warp_n = (wid >> 1) * 32;
    int NCH = K >> 5;

    float c[4][4][4];
#pragma unroll
    for (int i=0;i<4;i++)
#pragma unroll
        for (int j=0;j<4;j++)
#pragma unroll
            for (int q=0;q<4;q++) c[i][j][q] = 0.f;

    auto load_chunk = [&](int ci, int st) {
        int k0 = ci << 5;
        char* base = sm + st * STAGE_B;
#pragma unroll
        for (int i = 0; i < 8; i++) {
            int seg = tid + i*256;
            int tl  = seg >> 9;
            int rem = seg & 511;
            int r   = rem >> 2, cg = rem & 3;
            const __nv_bfloat16* src;
            if      (tl == 0) src = Ahi + (size_t)(m0 + r)*K + k0 + cg*8;
            else if (tl == 1) src = Alo + (size_t)(m0 + r)*K + k0 + cg*8;
            else if (tl == 2) src = Bhi + (size_t)(c0 + r)*K + k0 + cg*8;
            else              src = Blo + (size_t)(c0 + r)*K + k0 + cg*8;
            CP_ASYNC(smem_u32(base + tl*TILE_B + swz(r, cg)), src);
        }
        CP_COMMIT();
    };

    load_chunk(0, 0);
    load_chunk(1, 1);

    for (int ci = 0; ci < NCH; ci++) {
        int st = ci % 3;
        CP_WAIT1();
        __syncthreads();
        int nci = ci + 2;
        if (nci < NCH) load_chunk(nci, nci % 3);
        else CP_COMMIT();

        uint32_t base = smem_u32(sm + st * STAGE_B);
#pragma unroll
        for (int ks = 0; ks < 2; ks++) {
            uint32_t ah[4][4], al[4][4], bh[4][2], bl[4][2];
            int acg = ks*2 + (lid >> 4);
            int bcg = ks*2 + ((lid >> 3) & 1);
#pragma unroll
            for (int mt = 0; mt < 4; mt++) {
                int r = warp_m + mt*16 + (lid & 15);
                LDSM4(ah[mt], base + 0*TILE_B + swz(r, acg));
                LDSM4(al[mt], base + 1*TILE_B + swz(r, acg));
            }
#pragma unroll
            for (int np = 0; np < 2; np++) {
                int r = warp_n + np*16 + ((lid >> 4) << 3) + (lid & 7);
                uint32_t t4[4];
                LDSM4(t4, base + 2*TILE_B + swz(r, bcg));
                bh[np*2][0]=t4[0]; bh[np*2][1]=t4[1]; bh[np*2+1][0]=t4[2]; bh[np*2+1][1]=t4[3];
                LDSM4(t4, base + 3*TILE_B + swz(r, bcg));
                bl[np*2][0]=t4[0]; bl[np*2][1]=t4[1]; bl[np*2+1][0]=t4[2]; bl[np*2+1][1]=t4[3];
            }
#pragma unroll
            for (int mt = 0; mt < 4; mt++)
#pragma unroll
                for (int nt = 0; nt < 4; nt++) {
                    MMA16816(c[mt][nt], ah[mt], bh[nt]);
                    MMA16816(c[mt][nt], al[mt], bh[nt]);
                    MMA16816(c[mt][nt], ah[mt], bl[nt]);
                }
        }
    }

    // epilogue; for EPI==3 decode q/k/v bias section (c0-uniform)
    const float* bptr = bias;
    int cofs = 0;
    if (EPI == 3) {
        int sec = (c0 >= 1536) ? 2 : (c0 >= 768 ? 1 : 0);
        bptr = (sec == 0) ? bias : (sec == 1 ? biasK : biasV);
        cofs = sec * 768;
    }
    int g = lid >> 2, t2 = (lid & 3) * 2;
#pragma unroll
    for (int mt = 0; mt < 4; mt++) {
#pragma unroll
        for (int half = 0; half < 2; half++) {
            long m = m0 + warp_m + mt*16 + g + half*8;
#pragma unroll
            for (int nt = 0; nt < 4; nt++) {
                int col = c0 + warp_n + nt*8 + t2;
                float v0 = c[mt][nt][half*2+0] + bptr[col - cofs];
                float v1 = c[mt][nt][half*2+1] + bptr[col - cofs + 1];
                if (EPI == 1 || EPI == 3) {
                    if (EPI == 1) { v0 = fmaxf(v0, 0.f); v1 = fmaxf(v1, 0.f); }
                    __nv_bfloat162 hp, lp;
                    hp.x = __float2bfloat16(v0);
                    hp.y = __float2bfloat16(v1);
                    lp.x = __float2bfloat16(v0 - __bfloat162float(hp.x));
                    lp.y = __float2bfloat16(v1 - __bfloat162float(hp.y));
                    *(__nv_bfloat162*)(outhi + m*(long)Ndim + col) = hp;
                    *(__nv_bfloat162*)(outlo + m*(long)Ndim + col) = lp;
                } else {
                    const float* rrow = res + m*(long)Ndim;
                    v0 += rrow[col]; v1 += rrow[col+1];
                    *(float2*)(outf + m*(long)Ndim + col) = make_float2(v0, v1);
                }
            }
        }
    }
}

// ======================= tensor-core attention =======================
#define AT_QH 0
#define AT_QL 18432
#define AT_ST0 36864
#define AT_KH 0
#define AT_KL 9216
#define AT_VH 18432
#define AT_VL 27648
#define AT_MS 36864
#define AT_STAGE 45056
#define AT_SMEM (AT_ST0 + 2*AT_STAGE)   // 126976

__global__ void __launch_bounds__(256, 1)
attn_mma(const __nv_bfloat16* __restrict__ qvh, const __nv_bfloat16* __restrict__ qvl,
         const unsigned char* __restrict__ mask8,
         __nv_bfloat16* __restrict__ ohi, __nv_bfloat16* __restrict__ olo)
{
    extern __shared__ char smn[];
    int tid = threadIdx.x, wid = tid >> 5, lid = tid & 31;
    int bh = blockIdx.x;
    int b = bh / HH, h = bh % HH;
    int sq0 = blockIdx.y * 128;
    const size_t rowbase = (size_t)b * SS;
    int g = lid >> 2, t2 = lid & 3;

    // prologue: Q (hi/lo)
#pragma unroll
    for (int i = 0; i < 8; i++) {
        int s = tid + i*256;
        int arr = s >> 10, rem = s & 1023;
        int r = rem >> 3, cg = rem & 7;
        const __nv_bfloat16* src = (arr ? qvl : qvh) +
            (rowbase + sq0 + r)*(size_t)NQKV + h*DNN + cg*8;
        CP_ASYNC(smem_u32(smn + arr*18432 + r*144 + cg*16), src);
    }

    auto load_kv = [&](int kci, int st) {
        int kc = kci * 64;
        char* base = smn + AT_ST0 + st*AT_STAGE;
#pragma unroll
        for (int i = 0; i < 8; i++) {
            int s = tid + i*256;
            int tl = s >> 9, rem = s & 511;
            int r = rem >> 3, cg = rem & 7;
            size_t off = (rowbase + kc + r)*(size_t)NQKV + h*DNN + cg*8;
            const __nv_bfloat16* src;
            if      (tl == 0) src = qvh + off + DD;
            else if (tl == 1) src = qvl + off + DD;
            else if (tl == 2) src = qvh + off + 2*DD;
            else              src = qvl + off + 2*DD;
            CP_ASYNC(smem_u32(base + tl*9216 + r*144 + cg*16), src);
        }
        // mask tile: 128 rows x 64 u8 = 8KB
#pragma unroll
        for (int i = 0; i < 2; i++) {
            int s = tid + i*256;             // 0..511
            int r = s >> 2, seg = s & 3;
            CP_ASYNC(smem_u32(base + AT_MS + r*64 + seg*16),
                     mask8 + (rowbase + sq0 + r)*(size_t)SS + kc + seg*16);
        }
        CP_COMMIT();
    };

    load_kv(0, 0);

    uint32_t qfh[4][4], qfl[4][4];
    float o[8][4];
#pragma unroll
    for (int nt = 0; nt < 8; nt++)
#pragma unroll
        for (int q = 0; q < 4; q++) o[nt][q] = 0.f;
    float rs0 = 0.f, rs1 = 0.f;

    for (int ci = 0; ci < 8; ci++) {
        int st = ci & 1;
        CP_WAIT0();
        __syncthreads();
        if (ci == 0) {
            uint32_t qb = smem_u32(smn);
#pragma unroll
            for (int kg = 0; kg < 4; kg++) {
                uint32_t qa = qb + (wid*16 + (lid & 15))*144 + kg*32 + (lid >> 4)*16;
                LDSM4(qfh[kg], qa);
                LDSM4(qfl[kg], qa + 18432);
            }
        }
        if (ci < 7) load_kv(ci + 1, st ^ 1);

        uint32_t sb = smem_u32(smn + AT_ST0 + st*AT_STAGE);
        float s[8][4];
#pragma unroll
        for (int nt = 0; nt < 8; nt++)
#pragma unroll
            for (int q = 0; q < 4; q++) s[nt][q] = 0.f;

        // S = Q K^T (split-bf16)
#pragma unroll
        for (int kg = 0; kg < 4; kg++) {
#pragma unroll
            for (int nt = 0; nt < 8; nt++) {
                uint32_t bh2[2], bl2[2];
                uint32_t ka = sb + (nt*8 + (lid & 7))*144 + kg*32 + ((lid >> 3) & 1)*16;
                LDSM2(bh2, ka + AT_KH);
                LDSM2(bl2, ka + AT_KL);
                MMA16816(s[nt], qfh[kg], bh2);
                MMA16816(s[nt], qfl[kg], bh2);
                MMA16816(s[nt], qfh[kg], bl2);
            }
        }

        // softmax numerator + pack P into A-frags (hi/lo)
        const unsigned char* msm = (const unsigned char*)(smn + AT_ST0 + st*AT_STAGE + AT_MS);
        const unsigned char* mr0 = msm + (wid*16 + g)*64;
        const unsigned char* mr1 = mr0 + 8*64;
        uint32_t aPh[4][4], aPl[4][4];
#pragma unroll
        for (int nt = 0; nt < 8; nt++) {
            uchar2 m0 = *(const uchar2*)(mr0 + nt*8 + t2*2);
            uchar2 m1 = *(const uchar2*)(mr1 + nt*8 + t2*2);
            float p0 = m0.x ? 0.f : fexp(s[nt][0]*0.125f);
            float p1 = m0.y ? 0.f : fexp(s[nt][1]*0.125f);
            float p2 = m1.x ? 0.f : fexp(s[nt][2]*0.125f);
            float p3 = m1.y ? 0.f : fexp(s[nt][3]*0.125f);
            rs0 += p0 + p1;
            rs1 += p2 + p3;
            __nv_bfloat162 h01 = __floats2bfloat162_rn(p0, p1);
            __nv_bfloat162 h23 = __floats2bfloat162_rn(p2, p3);
            __nv_bfloat162 l01 = __floats2bfloat162_rn(p0 - __low2float(h01), p1 - __high2float(h01));
            __nv_bfloat162 l23 = __floats2bfloat162_rn(p2 - __low2float(h23), p3 - __high2float(h23));
            int kg = nt >> 1, sub = (nt & 1)*2;
            aPh[kg][sub]   = *(uint32_t*)&h01;
            aPh[kg][sub+1] = *(uint32_t*)&h23;
            aPl[kg][sub]   = *(uint32_t*)&l01;
            aPl[kg][sub+1] = *(uint32_t*)&l23;
        }

        // O += P V (split-bf16)
#pragma unroll
        for (int kg = 0; kg < 4; kg++) {
#pragma unroll
            for (int nt = 0; nt < 8; nt++) {
                uint32_t vh2[2], vl2[2];
                uint32_t va = sb + (kg*16 + (lid & 15))*144 + nt*16;
                LDSM2T(vh2, va + AT_VH);
                LDSM2T(vl2, va + AT_VL);
                MMA16816(o[nt], aPh[kg], vh2);
                MMA16816(o[nt], aPl[kg], vh2);
                MMA16816(o[nt], aPh[kg], vl2);
            }
        }
    }

    rs0 += __shfl_xor_sync(0xFFFFFFFFu, rs0, 1);
    rs0 += __shfl_xor_sync(0xFFFFFFFFu, rs0, 2);
    rs1 += __shfl_xor_sync(0xFFFFFFFFu, rs1, 1);
    rs1 += __shfl_xor_sync(0xFFFFFFFFu, rs1, 2);
    float inv0 = 1.f / rs0, inv1 = 1.f / rs1;

    long r0 = rowbase + sq0 + wid*16 + g;
    int colb = h*DNN + t2*2;
#pragma unroll
    for (int nt = 0; nt < 8; nt++) {
        int col = colb + nt*8;
        float v0 = o[nt][0]*inv0, v1 = o[nt][1]*inv0;
        float v2 = o[nt][2]*inv1, v3 = o[nt][3]*inv1;
        __nv_bfloat162 hp0, lp0, hp1, lp1;
        hp0 = __floats2bfloat162_rn(v0, v1);
        lp0 = __floats2bfloat162_rn(v0 - __low2float(hp0), v1 - __high2float(hp0));
        hp1 = __floats2bfloat162_rn(v2, v3);
        lp1 = __floats2bfloat162_rn(v2 - __low2float(hp1), v3 - __high2float(hp1));
        *(__nv_bfloat162*)(ohi + r0*DD + col)     = hp0;
        *(__nv_bfloat162*)(olo + r0*DD + col)     = lp0;
        *(__nv_bfloat162*)(ohi + (r0+8)*DD + col) = hp1;
        *(__nv_bfloat162*)(olo + (r0+8)*DD + col) = lp1;
    }
}

// ---------------- positional encoding ----------------
__global__ void pe_kernel()
{
    int idx = blockIdx.x*blockDim.x + threadIdx.x;
    if (idx >= SS*DD) return;
    int s = idx / DD, d = idx % DD;
    const float LOG10000 = 9.210340371976184f;
    float val;
    int i = d >> 1;
    if ((d & 1) == 0) {
        float freq = expf(-(2.0f*i/DD)*LOG10000);
        val = sinf(s*freq);
    } else {
        float freq = expf(-(2.0f*(i+1)/DD)*LOG10000);
        val = cosf(s*freq);
    }
    g_pe[idx] = val;
}

// ---------------- embedding + PE (+ split) ----------------
__global__ void embed_kernel(const int* __restrict__ x, const float* __restrict__ emb)
{
    int idx = blockIdx.x*blockDim.x + threadIdx.x;
    if (idx >= MM*DD) return;
    int m = idx / DD, d = idx % DD;
    int s = m % SS;
    int tok = x[m];
    float v = emb[(size_t)tok*DD + d] + g_pe[s*DD + d];
    g_h[idx] = v;
    __nv_bfloat16 h = __float2bfloat16(v);
    g_hhi[idx] = h;
    g_hlo[idx] = __float2bfloat16(v - __bfloat162float(h));
}

// ---------------- layernorm (+ split outputs) ----------------
__global__ void __launch_bounds__(256)
ln_kernel(const float* __restrict__ in, const float* __restrict__ g,
          const float* __restrict__ be, float* __restrict__ out,
          __nv_bfloat16* __restrict__ ohi, __nv_bfloat16* __restrict__ olo)
{
    int row = blockIdx.x;
    int t = threadIdx.x;
    const float* p = in + (size_t)row*DD;
    float x0 = p[t], x1 = p[t+256], x2 = p[t+512];
    __shared__ float rs[256], rq[256];
    rs[t] = x0+x1+x2;
    rq[t] = x0*x0 + x1*x1 + x2*x2;
    __syncthreads();
    for (int off = 128; off > 0; off >>= 1) {
        if (t < off) { rs[t] += rs[t+off]; rq[t] += rq[t+off]; }
        __syncthreads();
    }
    float mean = rs[0] * (1.0f/768.0f);
    float var  = rq[0] * (1.0f/768.0f) - mean*mean;
    float rstd = rsqrtf(var + 1e-5f);
    size_t base = (size_t)row*DD;
#pragma unroll
    for (int q = 0; q < 3; q++) {
        int d = t + q*256;
        float x = (q==0) ? x0 : (q==1) ? x1 : x2;
        float v = (x-mean)*rstd*g[d] + be[d];
        out[base + d] = v;
        __nv_bfloat16 h = __float2bfloat16(v);
        ohi[base + d] = h;
        olo[base + d] = __float2bfloat16(v - __bfloat162float(h));
    }
}

// ---------------- host ----------------
extern "C" void kernel_launch(void* const* d_in, const int* in_sizes, int n_in,
                              void* d_out, int out_size)
{
    const int*   x    = (const int*)  d_in[0];
    const int*   pmsk = (const int*)  d_in[1];
    const float* emb  = (const float*)d_in[2];
    const float* Wq   = (const float*)d_in[3];
    const float* bq   = (const float*)d_in[4];
    const float* Wk   = (const float*)d_in[5];
    const float* bk   = (const float*)d_in[6];
    const float* Wv   = (const float*)d_in[7];
    const float* bv   = (const float*)d_in[8];
    const float* Wo   = (const float*)d_in[9];
    const float* bo   = (const float*)d_in[10];
    const float* W1   = (const float*)d_in[11];
    const float* b1   = (const float*)d_in[12];
    const float* W2   = (const float*)d_in[13];
    const float* b2   = (const float*)d_in[14];
    const float* g1   = (const float*)d_in[15];
    const float* be1  = (const float*)d_in[16];
    const float* g2   = (const float*)d_in[17];
    const float* be2  = (const float*)d_in[18];
    float* outp = (float*)d_out;

    float *hb, *tb;
    __nv_bfloat16 *hhi, *hlo, *qkvh, *qkvl, *ohi, *olo, *fhi, *flo, *whi, *wlo;
    unsigned char* m8;
    cudaGetSymbolAddress((void**)&hb,    g_h);
    cudaGetSymbolAddress((void**)&tb,    g_t);
    cudaGetSymbolAddress((void**)&hhi,   g_hhi);
    cudaGetSymbolAddress((void**)&hlo,   g_hlo);
    cudaGetSymbolAddress((void**)&qkvh,  g_qkvh);
    cudaGetSymbolAddress((void**)&qkvl,  g_qkvl);
    cudaGetSymbolAddress((void**)&ohi,   g_ohi);
    cudaGetSymbolAddress((void**)&olo,   g_olo);
    cudaGetSymbolAddress((void**)&fhi,   g_fhi);
    cudaGetSymbolAddress((void**)&flo,   g_flo);
    cudaGetSymbolAddress((void**)&whi,   g_Whi);
    cudaGetSymbolAddress((void**)&wlo,   g_Wlo);
    cudaGetSymbolAddress((void**)&m8,    g_mask8);

    cudaFuncSetAttribute(gemm_mma<1>, cudaFuncAttributeMaxDynamicSharedMemorySize, GEMM_SMEM);
    cudaFuncSetAttribute(gemm_mma<2>, cudaFuncAttributeMaxDynamicSharedMemorySize, GEMM_SMEM);
    cudaFuncSetAttribute(gemm_mma<3>, cudaFuncAttributeMaxDynamicSharedMemorySize, GEMM_SMEM);
    cudaFuncSetAttribute(attn_mma,    cudaFuncAttributeMaxDynamicSharedMemorySize, AT_SMEM);

    dim3 gQKV(NQKV/128, MM/128);
    dim3 gO  (DD/128,   MM/128);
    dim3 gF1 (FF/128,   MM/128);
    dim3 gAttn(BB*HH, SS/128);

    // prologue ordered so first gemm_mma<3> is launch #4 (for ncu -s 5 -c 1 capture)
    tsplit_qkv<<<dim3(2, 24, LL*36), 256>>>(Wq, Wk, Wv);                  // 1
    pe_kernel<<<(SS*DD+255)/256, 256>>>();                                // 2
    embed_kernel<<<(MM*DD+255)/256, 256>>>(x, emb);                       // 3

    for (int l = 0; l < LL; l++) {
        const __nv_bfloat16* wh = whi + (size_t)l*LAYER_SZ;
        const __nv_bfloat16* wl = wlo + (size_t)l*LAYER_SZ;

        gemm_mma<3><<<gQKV, 256, GEMM_SMEM>>>(hhi, hlo, wh, wl,           // 4
            bq + l*DD, bk + l*DD, bv + l*DD, nullptr,
            nullptr, qkvh, qkvl, DD, NQKV);

        if (l == 0)
            mask_conv<<<(BB*SS*SS/4+255)/256, 256>>>(pmsk);               // 5

        attn_mma<<<gAttn, 256, AT_SMEM>>>(qkvh, qkvl, m8, ohi, olo);      // 6

        if (l == 0)
            tsplit<<<dim3(24, 24, LL), 256>>>(Wo, whi + OFF_O, wlo + OFF_O,
                DD, DD, (size_t)DD*DD, (size_t)LAYER_SZ);                 // 7

        gemm_mma<2><<<gO, 256, GEMM_SMEM>>>(ohi, olo, wh + OFF_O, wl + OFF_O,
            bo + l*DD, nullptr, nullptr, hb, tb, nullptr, nullptr, DD, DD);  // 8
        ln_kernel<<<MM, 256>>>(tb, g1 + l*DD, be1 + l*DD, hb, hhi, hlo);     // 9

        if (l == 0)
            tsplit<<<dim3(96, 24, LL), 256>>>(W1, whi + OFF_W1, wlo + OFF_W1,
                DD, FF, (size_t)DD*FF, (size_t)LAYER_SZ);                 // 10

        gemm_mma<1><<<gF1, 256, GEMM_SMEM>>>(hhi, hlo, wh + OFF_W1, wl + OFF_W1,
            b1 + l*FF, nullptr, nullptr, nullptr, nullptr, fhi, flo, DD, FF); // 11

        if (l == 0)
            tsplit<<<dim3(24, 96, LL), 256>>>(W2, whi + OFF_W2, wlo + OFF_W2,
                FF, DD, (size_t)FF*DD, (size_t)LAYER_SZ);                 // 12

        gemm_mma<2><<<gO, 256, GEMM_SMEM>>>(fhi, flo, wh + OFF_W2, wl + OFF_W2,
            b2 + l*DD, nullptr, nullptr, hb, tb, nullptr, nullptr, FF, DD);   // 13

        float* lnOut = (l == LL-1) ? outp : hb;
        ln_kernel<<<MM, 256>>>(tb, g2 + l*DD, be2 + l*DD, lnOut, hhi, hlo);   // 14
    }
}

// round 9
// speedup vs baseline: 3.0486x; 1.0234x over previous
#include <cuda_runtime.h>
#include <cuda_bf16.h>
#include <cstdint>
#include <math.h>

#define BB   16
#define SS   512
#define DD   768
#define HH   12
#define DNN  64
#define FF   3072
#define LL   6
#define MM   (BB*SS)
#define NQKV 2304

#define SZ_QKV (NQKV*DD)
#define SZ_O   (DD*DD)
#define SZ_W1  (FF*DD)
#define SZ_W2  (DD*FF)
#define OFF_O   SZ_QKV
#define OFF_W1  (OFF_O + SZ_O)
#define OFF_W2  (OFF_W1 + SZ_W1)
#define LAYER_SZ (OFF_W2 + SZ_W2)

// ---------------- scratch ----------------
__device__ __align__(16) float g_pe [SS*DD];
__device__ __align__(16) float g_h  [MM*DD];
__device__ __align__(16) float g_t  [MM*DD];
__device__ __align__(16) float g_t2 [MM*DD];
__device__ __align__(16) __nv_bfloat16 g_hhi[(size_t)MM*DD];
__device__ __align__(16) __nv_bfloat16 g_hlo[(size_t)MM*DD];
__device__ __align__(16) __nv_bfloat16 g_qkvh[(size_t)MM*NQKV];
__device__ __align__(16) __nv_bfloat16 g_qkvl[(size_t)MM*NQKV];
__device__ __align__(16) __nv_bfloat16 g_ohi[(size_t)MM*DD];
__device__ __align__(16) __nv_bfloat16 g_olo[(size_t)MM*DD];
__device__ __align__(16) __nv_bfloat16 g_fhi[(size_t)MM*FF];
__device__ __align__(16) __nv_bfloat16 g_flo[(size_t)MM*FF];
__device__ __align__(16) __nv_bfloat16 g_Whi[(size_t)LL*LAYER_SZ];
__device__ __align__(16) __nv_bfloat16 g_Wlo[(size_t)LL*LAYER_SZ];
__device__ __align__(16) unsigned char g_mask8[(size_t)BB*SS*SS];

// ======================= PTX helpers =======================
__device__ __forceinline__ uint32_t smem_u32(const void* p) {
    uint32_t a;
    asm("{ .reg .u64 t; cvta.to.shared.u64 t, %1; cvt.u32.u64 %0, t; }" : "=r"(a) : "l"(p));
    return a;
}
#define CP_ASYNC(dst, src) \
    asm volatile("cp.async.cg.shared.global [%0], [%1], 16;" :: "r"(dst), "l"(src) : "memory")
#define CP_COMMIT() asm volatile("cp.async.commit_group;" ::: "memory")
#define CP_WAIT1()  asm volatile("cp.async.wait_group 1;" ::: "memory")
#define CP_WAIT0()  asm volatile("cp.async.wait_group 0;" ::: "memory")

#define LDSM4(r, addr) \
    asm volatile("ldmatrix.sync.aligned.m8n8.x4.shared.b16 {%0,%1,%2,%3}, [%4];" \
        : "=r"((r)[0]), "=r"((r)[1]), "=r"((r)[2]), "=r"((r)[3]) : "r"(addr))
#define LDSM2(r, addr) \
    asm volatile("ldmatrix.sync.aligned.m8n8.x2.shared.b16 {%0,%1}, [%2];" \
        : "=r"((r)[0]), "=r"((r)[1]) : "r"(addr))
#define LDSM2T(r, addr) \
    asm volatile("ldmatrix.sync.aligned.m8n8.x2.trans.shared.b16 {%0,%1}, [%2];" \
        : "=r"((r)[0]), "=r"((r)[1]) : "r"(addr))
#define MMA16816(c, a, b) \
    asm volatile("mma.sync.aligned.m16n8k16.row.col.f32.bf16.bf16.f32 " \
        "{%0,%1,%2,%3},{%4,%5,%6,%7},{%8,%9},{%0,%1,%2,%3};" \
        : "+f"((c)[0]), "+f"((c)[1]), "+f"((c)[2]), "+f"((c)[3]) \
        : "r"((a)[0]), "r"((a)[1]), "r"((a)[2]), "r"((a)[3]), "r"((b)[0]), "r"((b)[1]))

// fast exp on fma pipe
__device__ __forceinline__ float fexp(float x) {
    x = fminf(fmaxf(x, -60.f), 60.f);
    float y = x * 1.4426950408889634f;
    float t = y + 12582912.0f;
    int n = __float_as_int(t) - 0x4B400000;
    float f = y - (t - 12582912.0f);
    float p =       1.3333558e-3f;
    p = fmaf(p, f,  9.6181291e-3f);
    p = fmaf(p, f,  5.5504109e-2f);
    p = fmaf(p, f,  2.4022651e-1f);
    p = fmaf(p, f,  6.9314718e-1f);
    p = fmaf(p, f,  1.0f);
    return __int_as_float(__float_as_int(p) + (n << 23));
}

// ======================= tiled transpose + hi/lo split =======================
__device__ __forceinline__ void tsplit_body(const float* __restrict__ src,
                                            __nv_bfloat16* __restrict__ hi,
                                            __nv_bfloat16* __restrict__ lo,
                                            int R, int C)
{
    __shared__ float t[32][33];
    int c0 = blockIdx.x*32, r0 = blockIdx.y*32;
    int tx = threadIdx.x & 31, ty = threadIdx.x >> 5;
#pragma unroll
    for (int i = 0; i < 32; i += 8)
        t[ty+i][tx] = src[(size_t)(r0+ty+i)*C + c0+tx];
    __syncthreads();
#pragma unroll
    for (int i = 0; i < 32; i += 8) {
        float v = t[tx][ty+i];
        size_t o = (size_t)(c0+ty+i)*R + r0+tx;
        __nv_bfloat16 h = __float2bfloat16(v);
        hi[o] = h;
        lo[o] = __float2bfloat16(v - __bfloat162float(h));
    }
}

__global__ void tsplit(const float* __restrict__ src, __nv_bfloat16* __restrict__ hi,
                       __nv_bfloat16* __restrict__ lo, int R, int C,
                       size_t sStride, size_t dStride)
{
    int z = blockIdx.z;
    tsplit_body(src + z*sStride, hi + z*dStride, lo + z*dStride, R, C);
}

__global__ void tsplit_qkv(const float* __restrict__ Wq, const float* __restrict__ Wk,
                           const float* __restrict__ Wv)
{
    int z = blockIdx.z;
    int l = z / 36, rem = z % 36, sec = rem / 12, h = rem % 12;
    const float* W = sec==0 ? Wq : (sec==1 ? Wk : Wv);
    const float* src = W + ((size_t)l*HH + h)*DD*DNN;
    size_t dofs = (size_t)l*LAYER_SZ + (size_t)(sec*DD + h*DNN)*DD;
    tsplit_body(src, g_Whi + dofs, g_Wlo + dofs, DD, DNN);
}

__global__ void mask_conv(const int* __restrict__ m)
{
    int i = blockIdx.x*256 + threadIdx.x;
    int4 v = ((const int4*)m)[i];
    ((uchar4*)g_mask8)[i] = make_uchar4((unsigned char)v.x, (unsigned char)v.y,
                                        (unsigned char)v.z, (unsigned char)v.w);
}

// ======================= fused-chunk HMMA split-bf16 GEMM =======================
#define NST 3
#define TILE_B 8192
#define STAGE_B (4*TILE_B)
#define GEMM_SMEM (NST*STAGE_B)   // 98304

__device__ __forceinline__ uint32_t swz(int r, int cg) {
    return (uint32_t)(r*64 + ((cg ^ ((r>>1)&3))<<4));
}

// EPI 1: relu(+bias)->bf16 hi/lo | 3: +qkv-bias->bf16 hi/lo | 4: split-K raw fp32 partial
template<int EPI>
__global__ void __launch_bounds__(256, 2)
gemm_mma(const __nv_bfloat16* __restrict__ Ahi, const __nv_bfloat16* __restrict__ Alo,
         const __nv_bfloat16* __restrict__ Bhi, const __nv_bfloat16* __restrict__ Blo,
         const float* __restrict__ bias, const float* __restrict__ biasK,
         const float* __restrict__ biasV,
         float* __restrict__ outf, float* __restrict__ outf2,
         __nv_bfloat16* __restrict__ outhi, __nv_bfloat16* __restrict__ outlo,
         int K, int Ndim)
{
    extern __shared__ char sm[];
    int tid = threadIdx.x, wid = tid >> 5, lid = tid & 31;
    int m0 = blockIdx.y * 128, c0 = blockIdx.x * 128;
    int warp_m = (wid & 1) * 64, warp_n = (wid >> 1) * 32;

    const __nv_bfloat16 *pAh = Ahi, *pAl = Alo, *pBh = Bhi, *pBl = Blo;
    float* pout = outf;
    int NCH;
    if (EPI == 4) {
        int half = K >> 1;
        int kofs = blockIdx.z * half;
        pAh += kofs; pAl += kofs; pBh += kofs; pBl += kofs;
        if (blockIdx.z) pout = outf2;
        NCH = half >> 5;
    } else {
        NCH = K >> 5;
    }

    float c[4][4][4];
#pragma unroll
    for (int i=0;i<4;i++)
#pragma unroll
        for (int j=0;j<4;j++)
#pragma unroll
            for (int q=0;q<4;q++) c[i][j][q] = 0.f;

    auto load_chunk = [&](int ci, int st) {
        int k0 = ci << 5;
        char* base = sm + st * STAGE_B;
#pragma unroll
        for (int i = 0; i < 8; i++) {
            int seg = tid + i*256;
            int tl  = seg >> 9;
            int rem = seg & 511;
            int r   = rem >> 2, cg = rem & 3;
            const __nv_bfloat16* src;
            if      (tl == 0) src = pAh + (size_t)(m0 + r)*K + k0 + cg*8;
            else if (tl == 1) src = pAl + (size_t)(m0 + r)*K + k0 + cg*8;
            else if (tl == 2) src = pBh + (size_t)(c0 + r)*K + k0 + cg*8;
            else              src = pBl + (size_t)(c0 + r)*K + k0 + cg*8;
            CP_ASYNC(smem_u32(base + tl*TILE_B + swz(r, cg)), src);
        }
        CP_COMMIT();
    };

    load_chunk(0, 0);
    load_chunk(1, 1);

    for (int ci = 0; ci < NCH; ci++) {
        int st = ci % 3;
        CP_WAIT1();
        __syncthreads();
        int nci = ci + 2;
        if (nci < NCH) load_chunk(nci, nci % 3);
        else CP_COMMIT();

        uint32_t base = smem_u32(sm + st * STAGE_B);
#pragma unroll
        for (int ks = 0; ks < 2; ks++) {
            uint32_t ah[4][4], al[4][4], bh[4][2], bl[4][2];
            int acg = ks*2 + (lid >> 4);
            int bcg = ks*2 + ((lid >> 3) & 1);
#pragma unroll
            for (int mt = 0; mt < 4; mt++) {
                int r = warp_m + mt*16 + (lid & 15);
                LDSM4(ah[mt], base + 0*TILE_B + swz(r, acg));
                LDSM4(al[mt], base + 1*TILE_B + swz(r, acg));
            }
#pragma unroll
            for (int np = 0; np < 2; np++) {
                int r = warp_n + np*16 + ((lid >> 4) << 3) + (lid & 7);
                uint32_t t4[4];
                LDSM4(t4, base + 2*TILE_B + swz(r, bcg));
                bh[np*2][0]=t4[0]; bh[np*2][1]=t4[1]; bh[np*2+1][0]=t4[2]; bh[np*2+1][1]=t4[3];
                LDSM4(t4, base + 3*TILE_B + swz(r, bcg));
                bl[np*2][0]=t4[0]; bl[np*2][1]=t4[1]; bl[np*2+1][0]=t4[2]; bl[np*2+1][1]=t4[3];
            }
#pragma unroll
            for (int mt = 0; mt < 4; mt++)
#pragma unroll
                for (int nt = 0; nt < 4; nt++) {
                    MMA16816(c[mt][nt], ah[mt], bh[nt]);
                    MMA16816(c[mt][nt], al[mt], bh[nt]);
                    MMA16816(c[mt][nt], ah[mt], bl[nt]);
                }
        }
    }

    const float* bptr = bias;
    int cofs = 0;
    if (EPI == 3) {
        int sec = (c0 >= 1536) ? 2 : (c0 >= 768 ? 1 : 0);
        bptr = (sec == 0) ? bias : (sec == 1 ? biasK : biasV);
        cofs = sec * 768;
    }
    int g = lid >> 2, t2 = (lid & 3) * 2;
#pragma unroll
    for (int mt = 0; mt < 4; mt++) {
#pragma unroll
        for (int half = 0; half < 2; half++) {
            long m = m0 + warp_m + mt*16 + g + half*8;
#pragma unroll
            for (int nt = 0; nt < 4; nt++) {
                int col = c0 + warp_n + nt*8 + t2;
                if (EPI == 4) {
                    *(float2*)(pout + m*(long)Ndim + col) =
                        make_float2(c[mt][nt][half*2+0], c[mt][nt][half*2+1]);
                } else {
                    float v0 = c[mt][nt][half*2+0] + bptr[col - cofs];
                    float v1 = c[mt][nt][half*2+1] + bptr[col - cofs + 1];
                    if (EPI == 1) { v0 = fmaxf(v0, 0.f); v1 = fmaxf(v1, 0.f); }
                    __nv_bfloat162 hp, lp;
                    hp.x = __float2bfloat16(v0);
                    hp.y = __float2bfloat16(v1);
                    lp.x = __float2bfloat16(v0 - __bfloat162float(hp.x));
                    lp.y = __float2bfloat16(v1 - __bfloat162float(hp.y));
                    *(__nv_bfloat162*)(outhi + m*(long)Ndim + col) = hp;
                    *(__nv_bfloat162*)(outlo + m*(long)Ndim + col) = lp;
                }
            }
        }
    }
}

// ======================= tensor-core attention =======================
#define AT_QH 0
#define AT_QL 18432
#define AT_ST0 36864
#define AT_KH 0
#define AT_KL 9216
#define AT_VH 18432
#define AT_VL 27648
#define AT_MS 36864
#define AT_STAGE 45056
#define AT_SMEM (AT_ST0 + 2*AT_STAGE)   // 126976

__global__ void __launch_bounds__(256, 1)
attn_mma(const __nv_bfloat16* __restrict__ qvh, const __nv_bfloat16* __restrict__ qvl,
         const unsigned char* __restrict__ mask8,
         __nv_bfloat16* __restrict__ ohi, __nv_bfloat16* __restrict__ olo)
{
    extern __shared__ char smn[];
    int tid = threadIdx.x, wid = tid >> 5, lid = tid & 31;
    int bh = blockIdx.x;
    int b = bh / HH, h = bh % HH;
    int sq0 = blockIdx.y * 128;
    const size_t rowbase = (size_t)b * SS;
    int g = lid >> 2, t2 = lid & 3;

#pragma unroll
    for (int i = 0; i < 8; i++) {
        int s = tid + i*256;
        int arr = s >> 10, rem = s & 1023;
        int r = rem >> 3, cg = rem & 7;
        const __nv_bfloat16* src = (arr ? qvl : qvh) +
            (rowbase + sq0 + r)*(size_t)NQKV + h*DNN + cg*8;
        CP_ASYNC(smem_u32(smn + arr*18432 + r*144 + cg*16), src);
    }

    auto load_kv = [&](int kci, int st) {
        int kc = kci * 64;
        char* base = smn + AT_ST0 + st*AT_STAGE;
#pragma unroll
        for (int i = 0; i < 8; i++) {
            int s = tid + i*256;
            int tl = s >> 9, rem = s & 511;
            int r = rem >> 3, cg = rem & 7;
            size_t off = (rowbase + kc + r)*(size_t)NQKV + h*DNN + cg*8;
            const __nv_bfloat16* src;
            if      (tl == 0) src = qvh + off + DD;
            else if (tl == 1) src = qvl + off + DD;
            else if (tl == 2) src = qvh + off + 2*DD;
            else              src = qvl + off + 2*DD;
            CP_ASYNC(smem_u32(base + tl*9216 + r*144 + cg*16), src);
        }
#pragma unroll
        for (int i = 0; i < 2; i++) {
            int s = tid + i*256;
            int r = s >> 2, seg = s & 3;
            CP_ASYNC(smem_u32(base + AT_MS + r*64 + seg*16),
                     mask8 + (rowbase + sq0 + r)*(size_t)SS + kc + seg*16);
        }
        CP_COMMIT();
    };

    load_kv(0, 0);

    uint32_t qfh[4][4], qfl[4][4];
    float o[8][4];
#pragma unroll
    for (int nt = 0; nt < 8; nt++)
#pragma unroll
        for (int q = 0; q < 4; q++) o[nt][q] = 0.f;
    float rs0 = 0.f, rs1 = 0.f;

    for (int ci = 0; ci < 8; ci++) {
        int st = ci & 1;
        CP_WAIT0();
        __syncthreads();
        if (ci == 0) {
            uint32_t qb = smem_u32(smn);
#pragma unroll
            for (int kg = 0; kg < 4; kg++) {
                uint32_t qa = qb + (wid*16 + (lid & 15))*144 + kg*32 + (lid >> 4)*16;
                LDSM4(qfh[kg], qa);
                LDSM4(qfl[kg], qa + 18432);
            }
        }
        if (ci < 7) load_kv(ci + 1, st ^ 1);

        uint32_t sb = smem_u32(smn + AT_ST0 + st*AT_STAGE);
        float s[8][4];
#pragma unroll
        for (int nt = 0; nt < 8; nt++)
#pragma unroll
            for (int q = 0; q < 4; q++) s[nt][q] = 0.f;

#pragma unroll
        for (int kg = 0; kg < 4; kg++) {
#pragma unroll
            for (int nt = 0; nt < 8; nt++) {
                uint32_t bh2[2], bl2[2];
                uint32_t ka = sb + (nt*8 + (lid & 7))*144 + kg*32 + ((lid >> 3) & 1)*16;
                LDSM2(bh2, ka + AT_KH);
                LDSM2(bl2, ka + AT_KL);
                MMA16816(s[nt], qfh[kg], bh2);
                MMA16816(s[nt], qfl[kg], bh2);
                MMA16816(s[nt], qfh[kg], bl2);
            }
        }

        const unsigned char* msm = (const unsigned char*)(smn + AT_ST0 + st*AT_STAGE + AT_MS);
        const unsigned char* mr0 = msm + (wid*16 + g)*64;
        const unsigned char* mr1 = mr0 + 8*64;
        uint32_t aPh[4][4], aPl[4][4];
#pragma unroll
        for (int nt = 0; nt < 8; nt++) {
            uchar2 m0 = *(const uchar2*)(mr0 + nt*8 + t2*2);
            uchar2 m1 = *(const uchar2*)(mr1 + nt*8 + t2*2);
            float p0 = m0.x ? 0.f : fexp(s[nt][0]*0.125f);
            float p1 = m0.y ? 0.f : fexp(s[nt][1]*0.125f);
            float p2 = m1.x ? 0.f : fexp(s[nt][2]*0.125f);
            float p3 = m1.y ? 0.f : fexp(s[nt][3]*0.125f);
            rs0 += p0 + p1;
            rs1 += p2 + p3;
            __nv_bfloat162 h01 = __floats2bfloat162_rn(p0, p1);
            __nv_bfloat162 h23 = __floats2bfloat162_rn(p2, p3);
            __nv_bfloat162 l01 = __floats2bfloat162_rn(p0 - __low2float(h01), p1 - __high2float(h01));
            __nv_bfloat162 l23 = __floats2bfloat162_rn(p2 - __low2float(h23), p3 - __high2float(h23));
            int kg = nt >> 1, sub = (nt & 1)*2;
            aPh[kg][sub]   = *(uint32_t*)&h01;
            aPh[kg][sub+1] = *(uint32_t*)&h23;
            aPl[kg][sub]   = *(uint32_t*)&l01;
            aPl[kg][sub+1] = *(uint32_t*)&l23;
        }

#pragma unroll
        for (int kg = 0; kg < 4; kg++) {
#pragma unroll
            for (int nt = 0; nt < 8; nt++) {
                uint32_t vh2[2], vl2[2];
                uint32_t va = sb + (kg*16 + (lid & 15))*144 + nt*16;
                LDSM2T(vh2, va + AT_VH);
                LDSM2T(vl2, va + AT_VL);
                MMA16816(o[nt], aPh[kg], vh2);
                MMA16816(o[nt], aPl[kg], vh2);
                MMA16816(o[nt], aPh[kg], vl2);
            }
        }
    }

    rs0 += __shfl_xor_sync(0xFFFFFFFFu, rs0, 1);
    rs0 += __shfl_xor_sync(0xFFFFFFFFu, rs0, 2);
    rs1 += __shfl_xor_sync(0xFFFFFFFFu, rs1, 1);
    rs1 += __shfl_xor_sync(0xFFFFFFFFu, rs1, 2);
    float inv0 = 1.f / rs0, inv1 = 1.f / rs1;

    long r0 = rowbase + sq0 + wid*16 + g;
    int colb = h*DNN + t2*2;
#pragma unroll
    for (int nt = 0; nt < 8; nt++) {
        int col = colb + nt*8;
        float v0 = o[nt][0]*inv0, v1 = o[nt][1]*inv0;
        float v2 = o[nt][2]*inv1, v3 = o[nt][3]*inv1;
        __nv_bfloat162 hp0, lp0, hp1, lp1;
        hp0 = __floats2bfloat162_rn(v0, v1);
        lp0 = __floats2bfloat162_rn(v0 - __low2float(hp0), v1 - __high2float(hp0));
        hp1 = __floats2bfloat162_rn(v2, v3);
        lp1 = __floats2bfloat162_rn(v2 - __low2float(hp1), v3 - __high2float(hp1));
        *(__nv_bfloat162*)(ohi + r0*DD + col)     = hp0;
        *(__nv_bfloat162*)(olo + r0*DD + col)     = lp0;
        *(__nv_bfloat162*)(ohi + (r0+8)*DD + col) = hp1;
        *(__nv_bfloat162*)(olo + (r0+8)*DD + col) = lp1;
    }
}

// ---------------- positional encoding ----------------
__global__ void pe_kernel()
{
    int idx = blockIdx.x*blockDim.x + threadIdx.x;
    if (idx >= SS*DD) return;
    int s = idx / DD, d = idx % DD;
    const float LOG10000 = 9.210340371976184f;
    float val;
    int i = d >> 1;
    if ((d & 1) == 0) {
        float freq = expf(-(2.0f*i/DD)*LOG10000);
        val = sinf(s*freq);
    } else {
        float freq = expf(-(2.0f*(i+1)/DD)*LOG10000);
        val = cosf(s*freq);
    }
    g_pe[idx] = val;
}

// ---------------- embedding + PE (+ split) ----------------
__global__ void embed_kernel(const int* __restrict__ x, const float* __restrict__ emb)
{
    int idx = blockIdx.x*blockDim.x + threadIdx.x;
    if (idx >= MM*DD) return;
    int m = idx / DD, d = idx % DD;
    int s = m % SS;
    int tok = x[m];
    float v = emb[(size_t)tok*DD + d] + g_pe[s*DD + d];
    g_h[idx] = v;
    __nv_bfloat16 h = __float2bfloat16(v);
    g_hhi[idx] = h;
    g_hlo[idx] = __float2bfloat16(v - __bfloat162float(h));
}

// ---------------- fused split-K-reduce + layernorm (warp-per-row) ----------------
// in = p1 + p2 + res + bias ; out = LN(in)*g + be ; also emits bf16 hi/lo
__global__ void __launch_bounds__(256)
ln2_kernel(const float* __restrict__ p1, const float* __restrict__ p2,
           const float* __restrict__ res, const float* __restrict__ bias,
           const float* __restrict__ g, const float* __restrict__ be,
           float* __restrict__ out,
           __nv_bfloat16* __restrict__ ohi, __nv_bfloat16* __restrict__ olo)
{
    int row = blockIdx.x*8 + (threadIdx.x >> 5);
    int lane = threadIdx.x & 31;
    size_t base = (size_t)row*DD;

    float v[24];
    float s = 0.f, sq = 0.f;
#pragma unroll
    for (int i = 0; i < 6; i++) {
        int col = lane*4 + i*128;
        float4 a  = *(const float4*)(p1  + base + col);
        float4 b  = *(const float4*)(p2  + base + col);
        float4 r  = *(const float4*)(res + base + col);
        float4 bi = *(const float4*)(bias + col);
        float x0 = a.x + b.x + r.x + bi.x;
        float x1 = a.y + b.y + r.y + bi.y;
        float x2 = a.z + b.z + r.z + bi.z;
        float x3 = a.w + b.w + r.w + bi.w;
        v[i*4+0]=x0; v[i*4+1]=x1; v[i*4+2]=x2; v[i*4+3]=x3;
        s += (x0+x1) + (x2+x3);
        sq += (x0*x0 + x1*x1) + (x2*x2 + x3*x3);
    }
#pragma unroll
    for (int o = 16; o > 0; o >>= 1) {
        s  += __shfl_xor_sync(0xFFFFFFFFu, s,  o);
        sq += __shfl_xor_sync(0xFFFFFFFFu, sq, o);
    }
    float mean = s * (1.0f/768.0f);
    float var  = sq * (1.0f/768.0f) - mean*mean;
    float rstd = rsqrtf(var + 1e-5f);

#pragma unroll
    for (int i = 0; i < 6; i++) {
        int col = lane*4 + i*128;
        float4 gg = *(const float4*)(g  + col);
        float4 bb = *(const float4*)(be + col);
        float y0 = (v[i*4+0]-mean)*rstd*gg.x + bb.x;
        float y1 = (v[i*4+1]-mean)*rstd*gg.y + bb.y;
        float y2 = (v[i*4+2]-mean)*rstd*gg.z + bb.z;
        float y3 = (v[i*4+3]-mean)*rstd*gg.w + bb.w;
        *(float4*)(out + base + col) = make_float4(y0, y1, y2, y3);
        __nv_bfloat162 h01 = __floats2bfloat162_rn(y0, y1);
        __nv_bfloat162 h23 = __floats2bfloat162_rn(y2, y3);
        __nv_bfloat162 l01 = __floats2bfloat162_rn(y0 - __low2float(h01), y1 - __high2float(h01));
        __nv_bfloat162 l23 = __floats2bfloat162_rn(y2 - __low2float(h23), y3 - __high2float(h23));
        uint2 hp, lp;
        hp.x = *(uint32_t*)&h01; hp.y = *(uint32_t*)&h23;
        lp.x = *(uint32_t*)&l01; lp.y = *(uint32_t*)&l23;
        *(uint2*)(ohi + base + col) = hp;
        *(uint2*)(olo + base + col) = lp;
    }
}

// ---------------- host ----------------
extern "C" void kernel_launch(void* const* d_in, const int* in_sizes, int n_in,
                              void* d_out, int out_size)
{
    const int*   x    = (const int*)  d_in[0];
    const int*   pmsk = (const int*)  d_in[1];
    const float* emb  = (const float*)d_in[2];
    const float* Wq   = (const float*)d_in[3];
    const float* bq   = (const float*)d_in[4];
    const float* Wk   = (const float*)d_in[5];
    const float* bk   = (const float*)d_in[6];
    const float* Wv   = (const float*)d_in[7];
    const float* bv   = (const float*)d_in[8];
    const float* Wo   = (const float*)d_in[9];
    const float* bo   = (const float*)d_in[10];
    const float* W1   = (const float*)d_in[11];
    const float* b1   = (const float*)d_in[12];
    const float* W2   = (const float*)d_in[13];
    const float* b2   = (const float*)d_in[14];
    const float* g1   = (const float*)d_in[15];
    const float* be1  = (const float*)d_in[16];
    const float* g2   = (const float*)d_in[17];
    const float* be2  = (const float*)d_in[18];
    float* outp = (float*)d_out;

    float *hb, *tb, *tb2;
    __nv_bfloat16 *hhi, *hlo, *qkvh, *qkvl, *ohi, *olo, *fhi, *flo, *whi, *wlo;
    unsigned char* m8;
    cudaGetSymbolAddress((void**)&hb,    g_h);
    cudaGetSymbolAddress((void**)&tb,    g_t);
    cudaGetSymbolAddress((void**)&tb2,   g_t2);
    cudaGetSymbolAddress((void**)&hhi,   g_hhi);
    cudaGetSymbolAddress((void**)&hlo,   g_hlo);
    cudaGetSymbolAddress((void**)&qkvh,  g_qkvh);
    cudaGetSymbolAddress((void**)&qkvl,  g_qkvl);
    cudaGetSymbolAddress((void**)&ohi,   g_ohi);
    cudaGetSymbolAddress((void**)&olo,   g_olo);
    cudaGetSymbolAddress((void**)&fhi,   g_fhi);
    cudaGetSymbolAddress((void**)&flo,   g_flo);
    cudaGetSymbolAddress((void**)&whi,   g_Whi);
    cudaGetSymbolAddress((void**)&wlo,   g_Wlo);
    cudaGetSymbolAddress((void**)&m8,    g_mask8);

    cudaFuncSetAttribute(gemm_mma<1>, cudaFuncAttributeMaxDynamicSharedMemorySize, GEMM_SMEM);
    cudaFuncSetAttribute(gemm_mma<3>, cudaFuncAttributeMaxDynamicSharedMemorySize, GEMM_SMEM);
    cudaFuncSetAttribute(gemm_mma<4>, cudaFuncAttributeMaxDynamicSharedMemorySize, GEMM_SMEM);
    cudaFuncSetAttribute(attn_mma,    cudaFuncAttributeMaxDynamicSharedMemorySize, AT_SMEM);

    dim3 gQKV(NQKV/128, MM/128);
    dim3 gSplit(DD/128, MM/128, 2);    // (6, 64, 2)
    dim3 gF1 (FF/128,   MM/128);
    dim3 gAttn(BB*HH, SS/128);

    tsplit_qkv<<<dim3(2, 24, LL*36), 256>>>(Wq, Wk, Wv);                  // 1
    pe_kernel<<<(SS*DD+255)/256, 256>>>();                                // 2
    embed_kernel<<<(MM*DD+255)/256, 256>>>(x, emb);                       // 3

    for (int l = 0; l < LL; l++) {
        const __nv_bfloat16* wh = whi + (size_t)l*LAYER_SZ;
        const __nv_bfloat16* wl = wlo + (size_t)l*LAYER_SZ;

        gemm_mma<3><<<gQKV, 256, GEMM_SMEM>>>(hhi, hlo, wh, wl,           // 4
            bq + l*DD, bk + l*DD, bv + l*DD,
            nullptr, nullptr, qkvh, qkvl, DD, NQKV);

        if (l == 0)
            mask_conv<<<(BB*SS*SS/4+255)/256, 256>>>(pmsk);

        attn_mma<<<gAttn, 256, AT_SMEM>>>(qkvh, qkvl, m8, ohi, olo);

        if (l == 0)
            tsplit<<<dim3(24, 24, LL), 256>>>(Wo, whi + OFF_O, wlo + OFF_O,
                DD, DD, (size_t)DD*DD, (size_t)LAYER_SZ);

        gemm_mma<4><<<gSplit, 256, GEMM_SMEM>>>(ohi, olo, wh + OFF_O, wl + OFF_O,
            nullptr, nullptr, nullptr, tb, tb2, nullptr, nullptr, DD, DD);

        ln2_kernel<<<MM/8, 256>>>(tb, tb2, hb, bo + l*DD,
                                  g1 + l*DD, be1 + l*DD, hb, hhi, hlo);

        if (l == 0)
            tsplit<<<dim3(96, 24, LL), 256>>>(W1, whi + OFF_W1, wlo + OFF_W1,
                DD, FF, (size_t)DD*FF, (size_t)LAYER_SZ);

        gemm_mma<1><<<gF1, 256, GEMM_SMEM>>>(hhi, hlo, wh + OFF_W1, wl + OFF_W1,
            b1 + l*FF, nullptr, nullptr, nullptr, nullptr, fhi, flo, DD, FF);

        if (l == 0)
            tsplit<<<dim3(24, 96, LL), 256>>>(W2, whi + OFF_W2, wlo + OFF_W2,
                FF, DD, (size_t)FF*DD, (size_t)LAYER_SZ);

        gemm_mma<4><<<gSplit, 256, GEMM_SMEM>>>(fhi, flo, wh + OFF_W2, wl + OFF_W2,
            nullptr, nullptr, nullptr, tb, tb2, nullptr, nullptr, FF, DD);

        float* lnOut = (l == LL-1) ? outp : hb;
        ln2_kernel<<<MM/8, 256>>>(tb, tb2, hb, b2 + l*DD,
                                  g2 + l*DD, be2 + l*DD, lnOut, hhi, hlo);
    }
}

// round 11
// speedup vs baseline: 3.2091x; 1.0526x over previous
#include <cuda_runtime.h>
#include <cuda_bf16.h>
#include <cstdint>
#include <math.h>

#define BB   16
#define SS   512
#define DD   768
#define HH   12
#define DNN  64
#define FF   3072
#define LL   6
#define MM   (BB*SS)
#define NQKV 2304

#define SZ_QKV (NQKV*DD)
#define SZ_O   (DD*DD)
#define SZ_W1  (FF*DD)
#define SZ_W2  (DD*FF)
#define OFF_O   SZ_QKV
#define OFF_W1  (OFF_O + SZ_O)
#define OFF_W2  (OFF_W1 + SZ_W1)
#define LAYER_SZ (OFF_W2 + SZ_W2)

// ---------------- scratch ----------------
__device__ __align__(16) float g_pe [SS*DD];
__device__ __align__(16) float g_h  [MM*DD];
__device__ __align__(16) float g_t  [MM*DD];
__device__ __align__(16) float g_t2 [MM*DD];
__device__ __align__(16) __nv_bfloat16 g_hhi[(size_t)MM*DD];
__device__ __align__(16) __nv_bfloat16 g_hlo[(size_t)MM*DD];
__device__ __align__(16) __nv_bfloat16 g_qkvh[(size_t)MM*NQKV];
__device__ __align__(16) __nv_bfloat16 g_qkvl[(size_t)MM*NQKV];
__device__ __align__(16) __nv_bfloat16 g_ohi[(size_t)MM*DD];
__device__ __align__(16) __nv_bfloat16 g_olo[(size_t)MM*DD];
__device__ __align__(16) __nv_bfloat16 g_fhi[(size_t)MM*FF];
__device__ __align__(16) __nv_bfloat16 g_flo[(size_t)MM*FF];
__device__ __align__(16) __nv_bfloat16 g_Whi[(size_t)LL*LAYER_SZ];
__device__ __align__(16) __nv_bfloat16 g_Wlo[(size_t)LL*LAYER_SZ];
__device__ __align__(16) unsigned char g_mask8[(size_t)BB*SS*SS];

// ======================= PTX helpers =======================
__device__ __forceinline__ uint32_t smem_u32(const void* p) {
    uint32_t a;
    asm("{ .reg .u64 t; cvta.to.shared.u64 t, %1; cvt.u32.u64 %0, t; }" : "=r"(a) : "l"(p));
    return a;
}
#define CP_ASYNC(dst, src) \
    asm volatile("cp.async.cg.shared.global [%0], [%1], 16;" :: "r"(dst), "l"(src) : "memory")
#define CP_COMMIT() asm volatile("cp.async.commit_group;" ::: "memory")
#define CP_WAIT1()  asm volatile("cp.async.wait_group 1;" ::: "memory")
#define CP_WAIT0()  asm volatile("cp.async.wait_group 0;" ::: "memory")

#define LDSM4(r, addr) \
    asm volatile("ldmatrix.sync.aligned.m8n8.x4.shared.b16 {%0,%1,%2,%3}, [%4];" \
        : "=r"((r)[0]), "=r"((r)[1]), "=r"((r)[2]), "=r"((r)[3]) : "r"(addr))
#define LDSM2(r, addr) \
    asm volatile("ldmatrix.sync.aligned.m8n8.x2.shared.b16 {%0,%1}, [%2];" \
        : "=r"((r)[0]), "=r"((r)[1]) : "r"(addr))
#define LDSM2T(r, addr) \
    asm volatile("ldmatrix.sync.aligned.m8n8.x2.trans.shared.b16 {%0,%1}, [%2];" \
        : "=r"((r)[0]), "=r"((r)[1]) : "r"(addr))
#define MMA16816(c, a, b) \
    asm volatile("mma.sync.aligned.m16n8k16.row.col.f32.bf16.bf16.f32 " \
        "{%0,%1,%2,%3},{%4,%5,%6,%7},{%8,%9},{%0,%1,%2,%3};" \
        : "+f"((c)[0]), "+f"((c)[1]), "+f"((c)[2]), "+f"((c)[3]) \
        : "r"((a)[0]), "r"((a)[1]), "r"((a)[2]), "r"((a)[3]), "r"((b)[0]), "r"((b)[1]))

// fast exp on fma pipe
__device__ __forceinline__ float fexp(float x) {
    x = fminf(fmaxf(x, -60.f), 60.f);
    float y = x * 1.4426950408889634f;
    float t = y + 12582912.0f;
    int n = __float_as_int(t) - 0x4B400000;
    float f = y - (t - 12582912.0f);
    float p =       1.3333558e-3f;
    p = fmaf(p, f,  9.6181291e-3f);
    p = fmaf(p, f,  5.5504109e-2f);
    p = fmaf(p, f,  2.4022651e-1f);
    p = fmaf(p, f,  6.9314718e-1f);
    p = fmaf(p, f,  1.0f);
    return __int_as_float(__float_as_int(p) + (n << 23));
}

// ======================= tiled transpose + hi/lo split =======================
__device__ __forceinline__ void tsplit_body(const float* __restrict__ src,
                                            __nv_bfloat16* __restrict__ hi,
                                            __nv_bfloat16* __restrict__ lo,
                                            int R, int C)
{
    __shared__ float t[32][33];
    int c0 = blockIdx.x*32, r0 = blockIdx.y*32;
    int tx = threadIdx.x & 31, ty = threadIdx.x >> 5;
#pragma unroll
    for (int i = 0; i < 32; i += 8)
        t[ty+i][tx] = src[(size_t)(r0+ty+i)*C + c0+tx];
    __syncthreads();
#pragma unroll
    for (int i = 0; i < 32; i += 8) {
        float v = t[tx][ty+i];
        size_t o = (size_t)(c0+ty+i)*R + r0+tx;
        __nv_bfloat16 h = __float2bfloat16(v);
        hi[o] = h;
        lo[o] = __float2bfloat16(v - __bfloat162float(h));
    }
}

__global__ void tsplit(const float* __restrict__ src, __nv_bfloat16* __restrict__ hi,
                       __nv_bfloat16* __restrict__ lo, int R, int C,
                       size_t sStride, size_t dStride)
{
    int z = blockIdx.z;
    tsplit_body(src + z*sStride, hi + z*dStride, lo + z*dStride, R, C);
}

__global__ void tsplit_qkv(const float* __restrict__ Wq, const float* __restrict__ Wk,
                           const float* __restrict__ Wv)
{
    int z = blockIdx.z;
    int l = z / 36, rem = z % 36, sec = rem / 12, h = rem % 12;
    const float* W = sec==0 ? Wq : (sec==1 ? Wk : Wv);
    const float* src = W + ((size_t)l*HH + h)*DD*DNN;
    size_t dofs = (size_t)l*LAYER_SZ + (size_t)(sec*DD + h*DNN)*DD;
    tsplit_body(src, g_Whi + dofs, g_Wlo + dofs, DD, DNN);
}

__global__ void mask_conv(const int* __restrict__ m)
{
    int i = blockIdx.x*256 + threadIdx.x;
    int4 v = ((const int4*)m)[i];
    ((uchar4*)g_mask8)[i] = make_uchar4((unsigned char)v.x, (unsigned char)v.y,
                                        (unsigned char)v.z, (unsigned char)v.w);
}

// ======================= fused-chunk HMMA split-bf16 GEMM =======================
#define NST 3
#define TILE_B 8192
#define STAGE_B (4*TILE_B)
#define GEMM_SMEM (NST*STAGE_B)   // 98304

__device__ __forceinline__ uint32_t swz(int r, int cg) {
    return (uint32_t)(r*64 + ((cg ^ ((r>>1)&3))<<4));
}

// EPI 1: relu(+bias)->bf16 hi/lo | 3: +qkv-bias->bf16 hi/lo | 4: split-K raw fp32 partial
template<int EPI>
__global__ void __launch_bounds__(256, 2)
gemm_mma(const __nv_bfloat16* __restrict__ Ahi, const __nv_bfloat16* __restrict__ Alo,
         const __nv_bfloat16* __restrict__ Bhi, const __nv_bfloat16* __restrict__ Blo,
         const float* __restrict__ bias, const float* __restrict__ biasK,
         const float* __restrict__ biasV,
         float* __restrict__ outf, float* __restrict__ outf2,
         __nv_bfloat16* __restrict__ outhi, __nv_bfloat16* __restrict__ outlo,
         int K, int Ndim)
{
    extern __shared__ char sm[];
    int tid = threadIdx.x, wid = tid >> 5, lid = tid & 31;
    int m0 = blockIdx.y * 128, c0 = blockIdx.x * 128;
    int warp_m = (wid & 1) * 64, warp_n = (wid >> 1) * 32;

    const __nv_bfloat16 *pAh = Ahi, *pAl = Alo, *pBh = Bhi, *pBl = Blo;
    float* pout = outf;
    int NCH;
    if (EPI == 4) {
        int half = K >> 1;
        int kofs = blockIdx.z * half;
        pAh += kofs; pAl += kofs; pBh += kofs; pBl += kofs;
        if (blockIdx.z) pout = outf2;
        NCH = half >> 5;
    } else {
        NCH = K >> 5;
    }

    float c[4][4][4];
#pragma unroll
    for (int i=0;i<4;i++)
#pragma unroll
        for (int j=0;j<4;j++)
#pragma unroll
            for (int q=0;q<4;q++) c[i][j][q] = 0.f;

    auto load_chunk = [&](int ci, int st) {
        int k0 = ci << 5;
        char* base = sm + st * STAGE_B;
#pragma unroll
        for (int i = 0; i < 8; i++) {
            int seg = tid + i*256;
            int tl  = seg >> 9;
            int rem = seg & 511;
            int r   = rem >> 2, cg = rem & 3;
            const __nv_bfloat16* src;
            if      (tl == 0) src = pAh + (size_t)(m0 + r)*K + k0 + cg*8;
            else if (tl == 1) src = pAl + (size_t)(m0 + r)*K + k0 + cg*8;
            else if (tl == 2) src = pBh + (size_t)(c0 + r)*K + k0 + cg*8;
            else              src = pBl + (size_t)(c0 + r)*K + k0 + cg*8;
            CP_ASYNC(smem_u32(base + tl*TILE_B + swz(r, cg)), src);
        }
        CP_COMMIT();
    };

    load_chunk(0, 0);
    load_chunk(1, 1);

    for (int ci = 0; ci < NCH; ci++) {
        int st = ci % 3;
        CP_WAIT1();
        __syncthreads();
        int nci = ci + 2;
        if (nci < NCH) load_chunk(nci, nci % 3);
        else CP_COMMIT();

        uint32_t base = smem_u32(sm + st * STAGE_B);
#pragma unroll
        for (int ks = 0; ks < 2; ks++) {
            uint32_t ah[4][4], al[4][4], bh[4][2], bl[4][2];
            int acg = ks*2 + (lid >> 4);
            int bcg = ks*2 + ((lid >> 3) & 1);
#pragma unroll
            for (int mt = 0; mt < 4; mt++) {
                int r = warp_m + mt*16 + (lid & 15);
                LDSM4(ah[mt], base + 0*TILE_B + swz(r, acg));
                LDSM4(al[mt], base + 1*TILE_B + swz(r, acg));
            }
#pragma unroll
            for (int np = 0; np < 2; np++) {
                int r = warp_n + np*16 + ((lid >> 4) << 3) + (lid & 7);
                uint32_t t4[4];
                LDSM4(t4, base + 2*TILE_B + swz(r, bcg));
                bh[np*2][0]=t4[0]; bh[np*2][1]=t4[1]; bh[np*2+1][0]=t4[2]; bh[np*2+1][1]=t4[3];
                LDSM4(t4, base + 3*TILE_B + swz(r, bcg));
                bl[np*2][0]=t4[0]; bl[np*2][1]=t4[1]; bl[np*2+1][0]=t4[2]; bl[np*2+1][1]=t4[3];
            }
#pragma unroll
            for (int mt = 0; mt < 4; mt++)
#pragma unroll
                for (int nt = 0; nt < 4; nt++) {
                    MMA16816(c[mt][nt], ah[mt], bh[nt]);
                    MMA16816(c[mt][nt], al[mt], bh[nt]);
                    MMA16816(c[mt][nt], ah[mt], bl[nt]);
                }
        }
    }

    const float* bptr = bias;
    int cofs = 0;
    if (EPI == 3) {
        int sec = (c0 >= 1536) ? 2 : (c0 >= 768 ? 1 : 0);
        bptr = (sec == 0) ? bias : (sec == 1 ? biasK : biasV);
        cofs = sec * 768;
    }
    int g = lid >> 2, t2 = (lid & 3) * 2;
#pragma unroll
    for (int mt = 0; mt < 4; mt++) {
#pragma unroll
        for (int half = 0; half < 2; half++) {
            long m = m0 + warp_m + mt*16 + g + half*8;
#pragma unroll
            for (int nt = 0; nt < 4; nt++) {
                int col = c0 + warp_n + nt*8 + t2;
                if (EPI == 4) {
                    *(float2*)(pout + m*(long)Ndim + col) =
                        make_float2(c[mt][nt][half*2+0], c[mt][nt][half*2+1]);
                } else {
                    float v0 = c[mt][nt][half*2+0] + bptr[col - cofs];
                    float v1 = c[mt][nt][half*2+1] + bptr[col - cofs + 1];
                    if (EPI == 1) { v0 = fmaxf(v0, 0.f); v1 = fmaxf(v1, 0.f); }
                    __nv_bfloat162 hp, lp;
                    hp.x = __float2bfloat16(v0);
                    hp.y = __float2bfloat16(v1);
                    lp.x = __float2bfloat16(v0 - __bfloat162float(hp.x));
                    lp.y = __float2bfloat16(v1 - __bfloat162float(hp.y));
                    *(__nv_bfloat162*)(outhi + m*(long)Ndim + col) = hp;
                    *(__nv_bfloat162*)(outlo + m*(long)Ndim + col) = lp;
                }
            }
        }
    }
}

// ======================= tensor-core attention (32-row chunks, 2 CTA/SM) =======================
#define AT_QH 0
#define AT_QL 18432
#define AT_ST0 36864
#define AT_KH 0
#define AT_KL 4608
#define AT_VH 9216
#define AT_VL 13824
#define AT_MS 18432
#define AT_STAGE 22528
#define AT_SMEM (AT_ST0 + 2*AT_STAGE)   // 81920

__global__ void __launch_bounds__(256, 2)
attn_mma(const __nv_bfloat16* __restrict__ qvh, const __nv_bfloat16* __restrict__ qvl,
         const unsigned char* __restrict__ mask8,
         __nv_bfloat16* __restrict__ ohi, __nv_bfloat16* __restrict__ olo)
{
    extern __shared__ char smn[];
    int tid = threadIdx.x, wid = tid >> 5, lid = tid & 31;
    int bh = blockIdx.x;
    int b = bh / HH, h = bh % HH;
    int sq0 = blockIdx.y * 128;
    const size_t rowbase = (size_t)b * SS;
    int g = lid >> 2, t2 = lid & 3;

    // prologue: Q (hi/lo), 128 rows x 128B, stride 144
#pragma unroll
    for (int i = 0; i < 8; i++) {
        int s = tid + i*256;
        int arr = s >> 10, rem = s & 1023;
        int r = rem >> 3, cg = rem & 7;
        const __nv_bfloat16* src = (arr ? qvl : qvh) +
            (rowbase + sq0 + r)*(size_t)NQKV + h*DNN + cg*8;
        CP_ASYNC(smem_u32(smn + arr*18432 + r*144 + cg*16), src);
    }

    auto load_kv = [&](int kci, int st) {
        int kc = kci * 32;
        char* base = smn + AT_ST0 + st*AT_STAGE;
        // KV: 4 tiles x 32 rows x 8 cg = 1024 segs
#pragma unroll
        for (int i = 0; i < 4; i++) {
            int s = tid + i*256;
            int tl = s >> 8, rem = s & 255;
            int r = rem >> 3, cg = rem & 7;
            size_t off = (rowbase + kc + r)*(size_t)NQKV + h*DNN + cg*8;
            const __nv_bfloat16* src;
            if      (tl == 0) src = qvh + off + DD;
            else if (tl == 1) src = qvl + off + DD;
            else if (tl == 2) src = qvh + off + 2*DD;
            else              src = qvl + off + 2*DD;
            CP_ASYNC(smem_u32(base + tl*4608 + r*144 + cg*16), src);
        }
        // mask: 128 q-rows x 32 u8 = 4KB = 256 x 16B
        {
            int r = tid >> 1, seg = tid & 1;
            CP_ASYNC(smem_u32(base + AT_MS + r*32 + seg*16),
                     mask8 + (rowbase + sq0 + r)*(size_t)SS + kc + seg*16);
        }
        CP_COMMIT();
    };

    load_kv(0, 0);

    uint32_t qfh[4][4], qfl[4][4];
    float o[8][4];
#pragma unroll
    for (int nt = 0; nt < 8; nt++)
#pragma unroll
        for (int q = 0; q < 4; q++) o[nt][q] = 0.f;
    float rs0 = 0.f, rs1 = 0.f;

    for (int ci = 0; ci < 16; ci++) {
        int st = ci & 1;
        CP_WAIT0();
        __syncthreads();
        if (ci == 0) {
            uint32_t qb = smem_u32(smn);
#pragma unroll
            for (int kg = 0; kg < 4; kg++) {
                uint32_t qa = qb + (wid*16 + (lid & 15))*144 + kg*32 + (lid >> 4)*16;
                LDSM4(qfh[kg], qa);
                LDSM4(qfl[kg], qa + 18432);
            }
        }
        if (ci < 15) load_kv(ci + 1, st ^ 1);

        uint32_t sb = smem_u32(smn + AT_ST0 + st*AT_STAGE);
        float s[4][4];
#pragma unroll
        for (int nt = 0; nt < 4; nt++)
#pragma unroll
            for (int q = 0; q < 4; q++) s[nt][q] = 0.f;

        // S = Q K^T (split-bf16), 32 kv rows
#pragma unroll
        for (int kg = 0; kg < 4; kg++) {
#pragma unroll
            for (int nt = 0; nt < 4; nt++) {
                uint32_t bh2[2], bl2[2];
                uint32_t ka = sb + (nt*8 + (lid & 7))*144 + kg*32 + ((lid >> 3) & 1)*16;
                LDSM2(bh2, ka + AT_KH);
                LDSM2(bl2, ka + AT_KL);
                MMA16816(s[nt], qfh[kg], bh2);
                MMA16816(s[nt], qfl[kg], bh2);
                MMA16816(s[nt], qfh[kg], bl2);
            }
        }

        // softmax numerator + pack P (128x32) into PV A-frags
        const unsigned char* msm = (const unsigned char*)(smn + AT_ST0 + st*AT_STAGE + AT_MS);
        const unsigned char* mr0 = msm + (wid*16 + g)*32;
        const unsigned char* mr1 = mr0 + 8*32;
        uint32_t aPh[2][4], aPl[2][4];
#pragma unroll
        for (int nt = 0; nt < 4; nt++) {
            uchar2 m0 = *(const uchar2*)(mr0 + nt*8 + t2*2);
            uchar2 m1 = *(const uchar2*)(mr1 + nt*8 + t2*2);
            float p0 = m0.x ? 0.f : fexp(s[nt][0]*0.125f);
            float p1 = m0.y ? 0.f : fexp(s[nt][1]*0.125f);
            float p2 = m1.x ? 0.f : fexp(s[nt][2]*0.125f);
            float p3 = m1.y ? 0.f : fexp(s[nt][3]*0.125f);
            rs0 += p0 + p1;
            rs1 += p2 + p3;
            __nv_bfloat162 h01 = __floats2bfloat162_rn(p0, p1);
            __nv_bfloat162 h23 = __floats2bfloat162_rn(p2, p3);
            __nv_bfloat162 l01 = __floats2bfloat162_rn(p0 - __low2float(h01), p1 - __high2float(h01));
            __nv_bfloat162 l23 = __floats2bfloat162_rn(p2 - __low2float(h23), p3 - __high2float(h23));
            int kg = nt >> 1, sub = (nt & 1)*2;
            aPh[kg][sub]   = *(uint32_t*)&h01;
            aPh[kg][sub+1] = *(uint32_t*)&h23;
            aPl[kg][sub]   = *(uint32_t*)&l01;
            aPl[kg][sub+1] = *(uint32_t*)&l23;
        }

        // O += P V (split-bf16), V via ldmatrix.trans, 32 kv rows = 2 k-groups
#pragma unroll
        for (int kg = 0; kg < 2; kg++) {
#pragma unroll
            for (int nt = 0; nt < 8; nt++) {
                uint32_t vh2[2], vl2[2];
                uint32_t va = sb + (kg*16 + (lid & 15))*144 + nt*16;
                LDSM2T(vh2, va + AT_VH);
                LDSM2T(vl2, va + AT_VL);
                MMA16816(o[nt], aPh[kg], vh2);
                MMA16816(o[nt], aPl[kg], vh2);
                MMA16816(o[nt], aPh[kg], vl2);
            }
        }
    }

    rs0 += __shfl_xor_sync(0xFFFFFFFFu, rs0, 1);
    rs0 += __shfl_xor_sync(0xFFFFFFFFu, rs0, 2);
    rs1 += __shfl_xor_sync(0xFFFFFFFFu, rs1, 1);
    rs1 += __shfl_xor_sync(0xFFFFFFFFu, rs1, 2);
    float inv0 = 1.f / rs0, inv1 = 1.f / rs1;

    long r0 = rowbase + sq0 + wid*16 + g;
    int colb = h*DNN + t2*2;
#pragma unroll
    for (int nt = 0; nt < 8; nt++) {
        int col = colb + nt*8;
        float v0 = o[nt][0]*inv0, v1 = o[nt][1]*inv0;
        float v2 = o[nt][2]*inv1, v3 = o[nt][3]*inv1;
        __nv_bfloat162 hp0, lp0, hp1, lp1;
        hp0 = __floats2bfloat162_rn(v0, v1);
        lp0 = __floats2bfloat162_rn(v0 - __low2float(hp0), v1 - __high2float(hp0));
        hp1 = __floats2bfloat162_rn(v2, v3);
        lp1 = __floats2bfloat162_rn(v2 - __low2float(hp1), v3 - __high2float(hp1));
        *(__nv_bfloat162*)(ohi + r0*DD + col)     = hp0;
        *(__nv_bfloat162*)(olo + r0*DD + col)     = lp0;
        *(__nv_bfloat162*)(ohi + (r0+8)*DD + col) = hp1;
        *(__nv_bfloat162*)(olo + (r0+8)*DD + col) = lp1;
    }
}

// ---------------- positional encoding ----------------
__global__ void pe_kernel()
{
    int idx = blockIdx.x*blockDim.x + threadIdx.x;
    if (idx >= SS*DD) return;
    int s = idx / DD, d = idx % DD;
    const float LOG10000 = 9.210340371976184f;
    float val;
    int i = d >> 1;
    if ((d & 1) == 0) {
        float freq = expf(-(2.0f*i/DD)*LOG10000);
        val = sinf(s*freq);
    } else {
        float freq = expf(-(2.0f*(i+1)/DD)*LOG10000);
        val = cosf(s*freq);
    }
    g_pe[idx] = val;
}

// ---------------- embedding + PE (+ split) ----------------
__global__ void embed_kernel(const int* __restrict__ x, const float* __restrict__ emb)
{
    int idx = blockIdx.x*blockDim.x + threadIdx.x;
    if (idx >= MM*DD) return;
    int m = idx / DD, d = idx % DD;
    int s = m % SS;
    int tok = x[m];
    float v = emb[(size_t)tok*DD + d] + g_pe[s*DD + d];
    g_h[idx] = v;
    __nv_bfloat16 h = __float2bfloat16(v);
    g_hhi[idx] = h;
    g_hlo[idx] = __float2bfloat16(v - __bfloat162float(h));
}

// ---------------- fused split-K-reduce + layernorm (warp-per-row) ----------------
__global__ void __launch_bounds__(256)
ln2_kernel(const float* __restrict__ p1, const float* __restrict__ p2,
           const float* __restrict__ res, const float* __restrict__ bias,
           const float* __restrict__ g, const float* __restrict__ be,
           float* __restrict__ out,
           __nv_bfloat16* __restrict__ ohi, __nv_bfloat16* __restrict__ olo)
{
    int row = blockIdx.x*8 + (threadIdx.x >> 5);
    int lane = threadIdx.x & 31;
    size_t base = (size_t)row*DD;

    float v[24];
    float s = 0.f, sq = 0.f;
#pragma unroll
    for (int i = 0; i < 6; i++) {
        int col = lane*4 + i*128;
        float4 a  = *(const float4*)(p1  + base + col);
        float4 b  = *(const float4*)(p2  + base + col);
        float4 r  = *(const float4*)(res + base + col);
        float4 bi = *(const float4*)(bias + col);
        float x0 = a.x + b.x + r.x + bi.x;
        float x1 = a.y + b.y + r.y + bi.y;
        float x2 = a.z + b.z + r.z + bi.z;
        float x3 = a.w + b.w + r.w + bi.w;
        v[i*4+0]=x0; v[i*4+1]=x1; v[i*4+2]=x2; v[i*4+3]=x3;
        s += (x0+x1) + (x2+x3);
        sq += (x0*x0 + x1*x1) + (x2*x2 + x3*x3);
    }
#pragma unroll
    for (int o = 16; o > 0; o >>= 1) {
        s  += __shfl_xor_sync(0xFFFFFFFFu, s,  o);
        sq += __shfl_xor_sync(0xFFFFFFFFu, sq, o);
    }
    float mean = s * (1.0f/768.0f);
    float var  = sq * (1.0f/768.0f) - mean*mean;
    float rstd = rsqrtf(var + 1e-5f);

#pragma unroll
    for (int i = 0; i < 6; i++) {
        int col = lane*4 + i*128;
        float4 gg = *(const float4*)(g  + col);
        float4 bb = *(const float4*)(be + col);
        float y0 = (v[i*4+0]-mean)*rstd*gg.x + bb.x;
        float y1 = (v[i*4+1]-mean)*rstd*gg.y + bb.y;
        float y2 = (v[i*4+2]-mean)*rstd*gg.z + bb.z;
        float y3 = (v[i*4+3]-mean)*rstd*gg.w + bb.w;
        *(float4*)(out + base + col) = make_float4(y0, y1, y2, y3);
        __nv_bfloat162 h01 = __floats2bfloat162_rn(y0, y1);
        __nv_bfloat162 h23 = __floats2bfloat162_rn(y2, y3);
        __nv_bfloat162 l01 = __floats2bfloat162_rn(y0 - __low2float(h01), y1 - __high2float(h01));
        __nv_bfloat162 l23 = __floats2bfloat162_rn(y2 - __low2float(h23), y3 - __high2float(h23));
        uint2 hp, lp;
        hp.x = *(uint32_t*)&h01; hp.y = *(uint32_t*)&h23;
        lp.x = *(uint32_t*)&l01; lp.y = *(uint32_t*)&l23;
        *(uint2*)(ohi + base + col) = hp;
        *(uint2*)(olo + base + col) = lp;
    }
}

// ---------------- host ----------------
extern "C" void kernel_launch(void* const* d_in, const int* in_sizes, int n_in,
                              void* d_out, int out_size)
{
    const int*   x    = (const int*)  d_in[0];
    const int*   pmsk = (const int*)  d_in[1];
    const float* emb  = (const float*)d_in[2];
    const float* Wq   = (const float*)d_in[3];
    const float* bq   = (const float*)d_in[4];
    const float* Wk   = (const float*)d_in[5];
    const float* bk   = (const float*)d_in[6];
    const float* Wv   = (const float*)d_in[7];
    const float* bv   = (const float*)d_in[8];
    const float* Wo   = (const float*)d_in[9];
    const float* bo   = (const float*)d_in[10];
    const float* W1   = (const float*)d_in[11];
    const float* b1   = (const float*)d_in[12];
    const float* W2   = (const float*)d_in[13];
    const float* b2   = (const float*)d_in[14];
    const float* g1   = (const float*)d_in[15];
    const float* be1  = (const float*)d_in[16];
    const float* g2   = (const float*)d_in[17];
    const float* be2  = (const float*)d_in[18];
    float* outp = (float*)d_out;

    float *hb, *tb, *tb2;
    __nv_bfloat16 *hhi, *hlo, *qkvh, *qkvl, *ohi, *olo, *fhi, *flo, *whi, *wlo;
    unsigned char* m8;
    cudaGetSymbolAddress((void**)&hb,    g_h);
    cudaGetSymbolAddress((void**)&tb,    g_t);
    cudaGetSymbolAddress((void**)&tb2,   g_t2);
    cudaGetSymbolAddress((void**)&hhi,   g_hhi);
    cudaGetSymbolAddress((void**)&hlo,   g_hlo);
    cudaGetSymbolAddress((void**)&qkvh,  g_qkvh);
    cudaGetSymbolAddress((void**)&qkvl,  g_qkvl);
    cudaGetSymbolAddress((void**)&ohi,   g_ohi);
    cudaGetSymbolAddress((void**)&olo,   g_olo);
    cudaGetSymbolAddress((void**)&fhi,   g_fhi);
    cudaGetSymbolAddress((void**)&flo,   g_flo);
    cudaGetSymbolAddress((void**)&whi,   g_Whi);
    cudaGetSymbolAddress((void**)&wlo,   g_Wlo);
    cudaGetSymbolAddress((void**)&m8,    g_mask8);

    cudaFuncSetAttribute(gemm_mma<1>, cudaFuncAttributeMaxDynamicSharedMemorySize, GEMM_SMEM);
    cudaFuncSetAttribute(gemm_mma<3>, cudaFuncAttributeMaxDynamicSharedMemorySize, GEMM_SMEM);
    cudaFuncSetAttribute(gemm_mma<4>, cudaFuncAttributeMaxDynamicSharedMemorySize, GEMM_SMEM);
    cudaFuncSetAttribute(attn_mma,    cudaFuncAttributeMaxDynamicSharedMemorySize, AT_SMEM);

    dim3 gQKV(NQKV/128, MM/128);
    dim3 gSplit(DD/128, MM/128, 2);
    dim3 gF1 (FF/128,   MM/128);
    dim3 gAttn(BB*HH, SS/128);

    tsplit_qkv<<<dim3(2, 24, LL*36), 256>>>(Wq, Wk, Wv);
    pe_kernel<<<(SS*DD+255)/256, 256>>>();
    embed_kernel<<<(MM*DD+255)/256, 256>>>(x, emb);

    for (int l = 0; l < LL; l++) {
        const __nv_bfloat16* wh = whi + (size_t)l*LAYER_SZ;
        const __nv_bfloat16* wl = wlo + (size_t)l*LAYER_SZ;

        gemm_mma<3><<<gQKV, 256, GEMM_SMEM>>>(hhi, hlo, wh, wl,
            bq + l*DD, bk + l*DD, bv + l*DD,
            nullptr, nullptr, qkvh, qkvl, DD, NQKV);

        if (l == 0)
            mask_conv<<<(BB*SS*SS/4+255)/256, 256>>>(pmsk);

        attn_mma<<<gAttn, 256, AT_SMEM>>>(qkvh, qkvl, m8, ohi, olo);

        if (l == 0)
            tsplit<<<dim3(24, 24, LL), 256>>>(Wo, whi + OFF_O, wlo + OFF_O,
                DD, DD, (size_t)DD*DD, (size_t)LAYER_SZ);

        gemm_mma<4><<<gSplit, 256, GEMM_SMEM>>>(ohi, olo, wh + OFF_O, wl + OFF_O,
            nullptr, nullptr, nullptr, tb, tb2, nullptr, nullptr, DD, DD);

        ln2_kernel<<<MM/8, 256>>>(tb, tb2, hb, bo + l*DD,
                                  g1 + l*DD, be1 + l*DD, hb, hhi, hlo);

        if (l == 0)
            tsplit<<<dim3(96, 24, LL), 256>>>(W1, whi + OFF_W1, wlo + OFF_W1,
                DD, FF, (size_t)DD*FF, (size_t)LAYER_SZ);

        gemm_mma<1><<<gF1, 256, GEMM_SMEM>>>(hhi, hlo, wh + OFF_W1, wl + OFF_W1,
            b1 + l*FF, nullptr, nullptr, nullptr, nullptr, fhi, flo, DD, FF);

        if (l == 0)
            tsplit<<<dim3(24, 96, LL), 256>>>(W2, whi + OFF_W2, wlo + OFF_W2,
                FF, DD, (size_t)FF*DD, (size_t)LAYER_SZ);

        gemm_mma<4><<<gSplit, 256, GEMM_SMEM>>>(fhi, flo, wh + OFF_W2, wl + OFF_W2,
            nullptr, nullptr, nullptr, tb, tb2, nullptr, nullptr, FF, DD);

        float* lnOut = (l == LL-1) ? outp : hb;
        ln2_kernel<<<MM/8, 256>>>(tb, tb2, hb, b2 + l*DD,
                                  g2 + l*DD, be2 + l*DD, lnOut, hhi, hlo);
    }
}

// round 12
// speedup vs baseline: 4.5043x; 1.4036x over previous
#include <cuda_runtime.h>
#include <cuda_fp16.h>
#include <cstdint>
#include <math.h>

#define BB   16
#define SS   512
#define DD   768
#define HH   12
#define DNN  64
#define FF   3072
#define LL   6
#define MM   (BB*SS)
#define NQKV 2304

#define SZ_QKV (NQKV*DD)
#define SZ_O   (DD*DD)
#define SZ_W1  (FF*DD)
#define SZ_W2  (DD*FF)
#define OFF_O   SZ_QKV
#define OFF_W1  (OFF_O + SZ_O)
#define OFF_W2  (OFF_W1 + SZ_W1)
#define LAYER_SZ (OFF_W2 + SZ_W2)

// ---------------- scratch ----------------
__device__ __align__(16) float g_pe [SS*DD];
__device__ __align__(16) float g_h  [MM*DD];
__device__ __align__(16) float g_t  [MM*DD];
__device__ __align__(16) float g_t2 [MM*DD];
__device__ __align__(16) __half g_hhi[(size_t)MM*DD];
__device__ __align__(16) __half g_hlo[(size_t)MM*DD];
__device__ __align__(16) __half g_qkvh[(size_t)MM*NQKV];
__device__ __align__(16) __half g_qkvl[(size_t)MM*NQKV];
__device__ __align__(16) __half g_ohi[(size_t)MM*DD];
__device__ __align__(16) __half g_olo[(size_t)MM*DD];
__device__ __align__(16) __half g_fhi[(size_t)MM*FF];
__device__ __align__(16) __half g_flo[(size_t)MM*FF];
__device__ __align__(16) __half g_Wh [(size_t)LL*LAYER_SZ];
__device__ __align__(16) unsigned char g_mask8[(size_t)BB*SS*SS];

// ======================= PTX helpers =======================
__device__ __forceinline__ uint32_t smem_u32(const void* p) {
    uint32_t a;
    asm("{ .reg .u64 t; cvta.to.shared.u64 t, %1; cvt.u32.u64 %0, t; }" : "=r"(a) : "l"(p));
    return a;
}
#define CP_ASYNC(dst, src) \
    asm volatile("cp.async.cg.shared.global [%0], [%1], 16;" :: "r"(dst), "l"(src) : "memory")
#define CP_COMMIT() asm volatile("cp.async.commit_group;" ::: "memory")
#define CP_WAIT2()  asm volatile("cp.async.wait_group 2;" ::: "memory")
#define CP_WAIT0()  asm volatile("cp.async.wait_group 0;" ::: "memory")

#define LDSM4(r, addr) \
    asm volatile("ldmatrix.sync.aligned.m8n8.x4.shared.b16 {%0,%1,%2,%3}, [%4];" \
        : "=r"((r)[0]), "=r"((r)[1]), "=r"((r)[2]), "=r"((r)[3]) : "r"(addr))
#define LDSM2(r, addr) \
    asm volatile("ldmatrix.sync.aligned.m8n8.x2.shared.b16 {%0,%1}, [%2];" \
        : "=r"((r)[0]), "=r"((r)[1]) : "r"(addr))
#define LDSM2T(r, addr) \
    asm volatile("ldmatrix.sync.aligned.m8n8.x2.trans.shared.b16 {%0,%1}, [%2];" \
        : "=r"((r)[0]), "=r"((r)[1]) : "r"(addr))
#define MMA16816(c, a, b) \
    asm volatile("mma.sync.aligned.m16n8k16.row.col.f32.f16.f16.f32 " \
        "{%0,%1,%2,%3},{%4,%5,%6,%7},{%8,%9},{%0,%1,%2,%3};" \
        : "+f"((c)[0]), "+f"((c)[1]), "+f"((c)[2]), "+f"((c)[3]) \
        : "r"((a)[0]), "r"((a)[1]), "r"((a)[2]), "r"((a)[3]), "r"((b)[0]), "r"((b)[1]))

// fast exp on fma pipe
__device__ __forceinline__ float fexp(float x) {
    x = fminf(fmaxf(x, -60.f), 60.f);
    float y = x * 1.4426950408889634f;
    float t = y + 12582912.0f;
    int n = __float_as_int(t) - 0x4B400000;
    float f = y - (t - 12582912.0f);
    float p =       1.3333558e-3f;
    p = fmaf(p, f,  9.6181291e-3f);
    p = fmaf(p, f,  5.5504109e-2f);
    p = fmaf(p, f,  2.4022651e-1f);
    p = fmaf(p, f,  6.9314718e-1f);
    p = fmaf(p, f,  1.0f);
    return __int_as_float(__float_as_int(p) + (n << 23));
}

__device__ __forceinline__ void hsplit2(float v0, float v1, uint32_t& hi, uint32_t& lo) {
    __half2 h = __floats2half2_rn(v0, v1);
    __half2 l = __floats2half2_rn(v0 - __low2float(h), v1 - __high2float(h));
    hi = *(uint32_t*)&h;
    lo = *(uint32_t*)&l;
}

// ======================= tiled transpose + fp16 (weights: hi only) =======================
__device__ __forceinline__ void tsplit_body(const float* __restrict__ src,
                                            __half* __restrict__ hi,
                                            int R, int C)
{
    __shared__ float t[32][33];
    int c0 = blockIdx.x*32, r0 = blockIdx.y*32;
    int tx = threadIdx.x & 31, ty = threadIdx.x >> 5;
#pragma unroll
    for (int i = 0; i < 32; i += 8)
        t[ty+i][tx] = src[(size_t)(r0+ty+i)*C + c0+tx];
    __syncthreads();
#pragma unroll
    for (int i = 0; i < 32; i += 8) {
        float v = t[tx][ty+i];
        hi[(size_t)(c0+ty+i)*R + r0+tx] = __float2half(v);
    }
}

__global__ void tsplit(const float* __restrict__ src, __half* __restrict__ hi,
                       int R, int C, size_t sStride, size_t dStride)
{
    int z = blockIdx.z;
    tsplit_body(src + z*sStride, hi + z*dStride, R, C);
}

__global__ void tsplit_qkv(const float* __restrict__ Wq, const float* __restrict__ Wk,
                           const float* __restrict__ Wv)
{
    int z = blockIdx.z;
    int l = z / 36, rem = z % 36, sec = rem / 12, h = rem % 12;
    const float* W = sec==0 ? Wq : (sec==1 ? Wk : Wv);
    const float* src = W + ((size_t)l*HH + h)*DD*DNN;
    size_t dofs = (size_t)l*LAYER_SZ + (size_t)(sec*DD + h*DNN)*DD;
    tsplit_body(src, g_Wh + dofs, DD, DNN);
}

__global__ void mask_conv(const int* __restrict__ m)
{
    int i = blockIdx.x*256 + threadIdx.x;
    int4 v = ((const int4*)m)[i];
    ((uchar4*)g_mask8)[i] = make_uchar4((unsigned char)v.x, (unsigned char)v.y,
                                        (unsigned char)v.z, (unsigned char)v.w);
}

// ======================= fp16 2-MMA GEMM (A split hi/lo, B single) =======================
#define NST 4
#define TILE_B 8192
#define STAGE_B (3*TILE_B)        // 24576
#define GEMM_SMEM (NST*STAGE_B)   // 98304

__device__ __forceinline__ uint32_t swz(int r, int cg) {
    return (uint32_t)(r*64 + ((cg ^ ((r>>1)&3))<<4));
}

// EPI 1: relu(+bias)->fp16 hi/lo | 3: +qkv-bias->fp16 hi/lo | 4: split-K raw fp32 partial
template<int EPI>
__global__ void __launch_bounds__(256, 2)
gemm_mma(const __half* __restrict__ Ahi, const __half* __restrict__ Alo,
         const __half* __restrict__ Bh,
         const float* __restrict__ bias, const float* __restrict__ biasK,
         const float* __restrict__ biasV,
         float* __restrict__ outf, float* __restrict__ outf2,
         __half* __restrict__ outhi, __half* __restrict__ outlo,
         int K, int Ndim)
{
    extern __shared__ char sm[];
    int tid = threadIdx.x, wid = tid >> 5, lid = tid & 31;
    int m0 = blockIdx.y * 128, c0 = blockIdx.x * 128;
    int warp_m = (wid & 3) * 32, warp_n = (wid >> 2) * 64;

    const __half *pAh = Ahi, *pAl = Alo, *pB = Bh;
    float* pout = outf;
    int NCH;
    if (EPI == 4) {
        int half_k = K >> 1;
        int kofs = blockIdx.z * half_k;
        pAh += kofs; pAl += kofs; pB += kofs;
        if (blockIdx.z) pout = outf2;
        NCH = half_k >> 5;
    } else {
        NCH = K >> 5;
    }

    float c[2][8][4];
#pragma unroll
    for (int i=0;i<2;i++)
#pragma unroll
        for (int j=0;j<8;j++)
#pragma unroll
            for (int q=0;q<4;q++) c[i][j][q] = 0.f;

    auto load_chunk = [&](int ci, int st) {
        int k0 = ci << 5;
        char* base = sm + st * STAGE_B;
#pragma unroll
        for (int i = 0; i < 6; i++) {
            int seg = tid + i*256;            // 0..1535
            int tl  = seg >> 9;               // 0..2
            int rem = seg & 511;
            int r   = rem >> 2, cg = rem & 3;
            const __half* src;
            if      (tl == 0) src = pAh + (size_t)(m0 + r)*K + k0 + cg*8;
            else if (tl == 1) src = pAl + (size_t)(m0 + r)*K + k0 + cg*8;
            else              src = pB  + (size_t)(c0 + r)*K + k0 + cg*8;
            CP_ASYNC(smem_u32(base + tl*TILE_B + swz(r, cg)), src);
        }
        CP_COMMIT();
    };

    load_chunk(0, 0);
    load_chunk(1, 1);
    load_chunk(2, 2);

    for (int ci = 0; ci < NCH; ci++) {
        int st = ci & 3;
        CP_WAIT2();
        __syncthreads();
        int nci = ci + 3;
        if (nci < NCH) load_chunk(nci, nci & 3);
        else CP_COMMIT();

        uint32_t base = smem_u32(sm + st * STAGE_B);
#pragma unroll
        for (int ks = 0; ks < 2; ks++) {
            uint32_t ah[2][4], al[2][4], bh[8][2];
            int acg = ks*2 + (lid >> 4);
            int bcg = ks*2 + ((lid >> 3) & 1);
#pragma unroll
            for (int mt = 0; mt < 2; mt++) {
                int r = warp_m + mt*16 + (lid & 15);
                LDSM4(ah[mt], base + 0*TILE_B + swz(r, acg));
                LDSM4(al[mt], base + 1*TILE_B + swz(r, acg));
            }
#pragma unroll
            for (int np = 0; np < 4; np++) {
                int r = warp_n + np*16 + ((lid >> 4) << 3) + (lid & 7);
                uint32_t t4[4];
                LDSM4(t4, base + 2*TILE_B + swz(r, bcg));
                bh[np*2][0]=t4[0]; bh[np*2][1]=t4[1]; bh[np*2+1][0]=t4[2]; bh[np*2+1][1]=t4[3];
            }
#pragma unroll
            for (int mt = 0; mt < 2; mt++)
#pragma unroll
                for (int nt = 0; nt < 8; nt++) {
                    MMA16816(c[mt][nt], ah[mt], bh[nt]);
                    MMA16816(c[mt][nt], al[mt], bh[nt]);
                }
        }
    }

    const float* bptr = bias;
    int cofs = 0;
    if (EPI == 3) {
        int sec = (c0 >= 1536) ? 2 : (c0 >= 768 ? 1 : 0);
        bptr = (sec == 0) ? bias : (sec == 1 ? biasK : biasV);
        cofs = sec * 768;
    }
    int g = lid >> 2, t2 = (lid & 3) * 2;
#pragma unroll
    for (int mt = 0; mt < 2; mt++) {
#pragma unroll
        for (int half_i = 0; half_i < 2; half_i++) {
            long m = m0 + warp_m + mt*16 + g + half_i*8;
#pragma unroll
            for (int nt = 0; nt < 8; nt++) {
                int col = c0 + warp_n + nt*8 + t2;
                if (EPI == 4) {
                    *(float2*)(pout + m*(long)Ndim + col) =
                        make_float2(c[mt][nt][half_i*2+0], c[mt][nt][half_i*2+1]);
                } else {
                    float v0 = c[mt][nt][half_i*2+0] + bptr[col - cofs];
                    float v1 = c[mt][nt][half_i*2+1] + bptr[col - cofs + 1];
                    if (EPI == 1) { v0 = fmaxf(v0, 0.f); v1 = fmaxf(v1, 0.f); }
                    uint32_t hp, lp;
                    hsplit2(v0, v1, hp, lp);
                    *(uint32_t*)(outhi + m*(long)Ndim + col) = hp;
                    *(uint32_t*)(outlo + m*(long)Ndim + col) = lp;
                }
            }
        }
    }
}

// ======================= fp16 tensor-core attention (K,V single; Q,P split) =======================
#define AT_QH 0
#define AT_QL 18432
#define AT_ST0 36864
#define AT_KH 0
#define AT_VH 4608
#define AT_MS 9216
#define AT_STAGE 13312
#define AT_SMEM (AT_ST0 + 2*AT_STAGE)   // 63488

__global__ void __launch_bounds__(256, 2)
attn_mma(const __half* __restrict__ qvh, const __half* __restrict__ qvl,
         const unsigned char* __restrict__ mask8,
         __half* __restrict__ ohi, __half* __restrict__ olo)
{
    extern __shared__ char smn[];
    int tid = threadIdx.x, wid = tid >> 5, lid = tid & 31;
    int bh = blockIdx.x;
    int b = bh / HH, h = bh % HH;
    int sq0 = blockIdx.y * 128;
    const size_t rowbase = (size_t)b * SS;
    int g = lid >> 2, t2 = lid & 3;

    // prologue: Q (hi/lo), 128 rows x 128B, stride 144
#pragma unroll
    for (int i = 0; i < 8; i++) {
        int s = tid + i*256;
        int arr = s >> 10, rem = s & 1023;
        int r = rem >> 3, cg = rem & 7;
        const __half* src = (arr ? qvl : qvh) +
            (rowbase + sq0 + r)*(size_t)NQKV + h*DNN + cg*8;
        CP_ASYNC(smem_u32(smn + arr*18432 + r*144 + cg*16), src);
    }

    auto load_kv = [&](int kci, int st) {
        int kc = kci * 32;
        char* base = smn + AT_ST0 + st*AT_STAGE;
        // K,V hi only: 2 tiles x 32 rows x 8 cg = 512 segs
#pragma unroll
        for (int i = 0; i < 2; i++) {
            int s = tid + i*256;
            int tl = s >> 8, rem = s & 255;
            int r = rem >> 3, cg = rem & 7;
            size_t off = (rowbase + kc + r)*(size_t)NQKV + h*DNN + cg*8;
            const __half* src = qvh + off + (tl ? 2*DD : DD);
            CP_ASYNC(smem_u32(base + tl*4608 + r*144 + cg*16), src);
        }
        // mask: 128 q-rows x 32 u8 = 4KB
        {
            int r = tid >> 1, seg = tid & 1;
            CP_ASYNC(smem_u32(base + AT_MS + r*32 + seg*16),
                     mask8 + (rowbase + sq0 + r)*(size_t)SS + kc + seg*16);
        }
        CP_COMMIT();
    };

    load_kv(0, 0);

    uint32_t qfh[4][4], qfl[4][4];
    float o[8][4];
#pragma unroll
    for (int nt = 0; nt < 8; nt++)
#pragma unroll
        for (int q = 0; q < 4; q++) o[nt][q] = 0.f;
    float rs0 = 0.f, rs1 = 0.f;

    for (int ci = 0; ci < 16; ci++) {
        int st = ci & 1;
        CP_WAIT0();
        __syncthreads();
        if (ci == 0) {
            uint32_t qb = smem_u32(smn);
#pragma unroll
            for (int kg = 0; kg < 4; kg++) {
                uint32_t qa = qb + (wid*16 + (lid & 15))*144 + kg*32 + (lid >> 4)*16;
                LDSM4(qfh[kg], qa);
                LDSM4(qfl[kg], qa + 18432);
            }
        }
        if (ci < 15) load_kv(ci + 1, st ^ 1);

        uint32_t sb = smem_u32(smn + AT_ST0 + st*AT_STAGE);
        float s[4][4];
#pragma unroll
        for (int nt = 0; nt < 4; nt++)
#pragma unroll
            for (int q = 0; q < 4; q++) s[nt][q] = 0.f;

        // S = Q K^T: qh*kh + ql*kh
#pragma unroll
        for (int kg = 0; kg < 4; kg++) {
#pragma unroll
            for (int nt = 0; nt < 4; nt++) {
                uint32_t kh2[2];
                uint32_t ka = sb + (nt*8 + (lid & 7))*144 + kg*32 + ((lid >> 3) & 1)*16;
                LDSM2(kh2, ka + AT_KH);
                MMA16816(s[nt], qfh[kg], kh2);
                MMA16816(s[nt], qfl[kg], kh2);
            }
        }

        // softmax numerator + pack P (fp16 hi/lo) into PV A-frags
        const unsigned char* msm = (const unsigned char*)(smn + AT_ST0 + st*AT_STAGE + AT_MS);
        const unsigned char* mr0 = msm + (wid*16 + g)*32;
        const unsigned char* mr1 = mr0 + 8*32;
        uint32_t aPh[2][4], aPl[2][4];
#pragma unroll
        for (int nt = 0; nt < 4; nt++) {
            uchar2 m0 = *(const uchar2*)(mr0 + nt*8 + t2*2);
            uchar2 m1 = *(const uchar2*)(mr1 + nt*8 + t2*2);
            float p0 = m0.x ? 0.f : fexp(s[nt][0]*0.125f);
            float p1 = m0.y ? 0.f : fexp(s[nt][1]*0.125f);
            float p2 = m1.x ? 0.f : fexp(s[nt][2]*0.125f);
            float p3 = m1.y ? 0.f : fexp(s[nt][3]*0.125f);
            rs0 += p0 + p1;
            rs1 += p2 + p3;
            int kg = nt >> 1, sub = (nt & 1)*2;
            hsplit2(p0, p1, aPh[kg][sub],   aPl[kg][sub]);
            hsplit2(p2, p3, aPh[kg][sub+1], aPl[kg][sub+1]);
        }

        // O += P V: ph*vh + pl*vh
#pragma unroll
        for (int kg = 0; kg < 2; kg++) {
#pragma unroll
            for (int nt = 0; nt < 8; nt++) {
                uint32_t vh2[2];
                uint32_t va = sb + (kg*16 + (lid & 15))*144 + nt*16;
                LDSM2T(vh2, va + AT_VH);
                MMA16816(o[nt], aPh[kg], vh2);
                MMA16816(o[nt], aPl[kg], vh2);
            }
        }
    }

    rs0 += __shfl_xor_sync(0xFFFFFFFFu, rs0, 1);
    rs0 += __shfl_xor_sync(0xFFFFFFFFu, rs0, 2);
    rs1 += __shfl_xor_sync(0xFFFFFFFFu, rs1, 1);
    rs1 += __shfl_xor_sync(0xFFFFFFFFu, rs1, 2);
    float inv0 = 1.f / rs0, inv1 = 1.f / rs1;

    long r0 = rowbase + sq0 + wid*16 + g;
    int colb = h*DNN + t2*2;
#pragma unroll
    for (int nt = 0; nt < 8; nt++) {
        int col = colb + nt*8;
        uint32_t hp0, lp0, hp1, lp1;
        hsplit2(o[nt][0]*inv0, o[nt][1]*inv0, hp0, lp0);
        hsplit2(o[nt][2]*inv1, o[nt][3]*inv1, hp1, lp1);
        *(uint32_t*)(ohi + r0*DD + col)     = hp0;
        *(uint32_t*)(olo + r0*DD + col)     = lp0;
        *(uint32_t*)(ohi + (r0+8)*DD + col) = hp1;
        *(uint32_t*)(olo + (r0+8)*DD + col) = lp1;
    }
}

// ---------------- positional encoding ----------------
__global__ void pe_kernel()
{
    int idx = blockIdx.x*blockDim.x + threadIdx.x;
    if (idx >= SS*DD) return;
    int s = idx / DD, d = idx % DD;
    const float LOG10000 = 9.210340371976184f;
    float val;
    int i = d >> 1;
    if ((d & 1) == 0) {
        float freq = expf(-(2.0f*i/DD)*LOG10000);
        val = sinf(s*freq);
    } else {
        float freq = expf(-(2.0f*(i+1)/DD)*LOG10000);
        val = cosf(s*freq);
    }
    g_pe[idx] = val;
}

// ---------------- embedding + PE (+ split) ----------------
__global__ void embed_kernel(const int* __restrict__ x, const float* __restrict__ emb)
{
    int idx = blockIdx.x*blockDim.x + threadIdx.x;
    if (idx >= MM*DD) return;
    int m = idx / DD, d = idx % DD;
    int s = m % SS;
    int tok = x[m];
    float v = emb[(size_t)tok*DD + d] + g_pe[s*DD + d];
    g_h[idx] = v;
    __half h = __float2half(v);
    g_hhi[idx] = h;
    g_hlo[idx] = __float2half(v - __half2float(h));
}

// ---------------- fused split-K-reduce + layernorm (warp-per-row) ----------------
__global__ void __launch_bounds__(256)
ln2_kernel(const float* __restrict__ p1, const float* __restrict__ p2,
           const float* __restrict__ res, const float* __restrict__ bias,
           const float* __restrict__ g, const float* __restrict__ be,
           float* __restrict__ out,
           __half* __restrict__ ohi, __half* __restrict__ olo)
{
    int row = blockIdx.x*8 + (threadIdx.x >> 5);
    int lane = threadIdx.x & 31;
    size_t base = (size_t)row*DD;

    float v[24];
    float s = 0.f, sq = 0.f;
#pragma unroll
    for (int i = 0; i < 6; i++) {
        int col = lane*4 + i*128;
        float4 a  = *(const float4*)(p1  + base + col);
        float4 b  = *(const float4*)(p2  + base + col);
        float4 r  = *(const float4*)(res + base + col);
        float4 bi = *(const float4*)(bias + col);
        float x0 = a.x + b.x + r.x + bi.x;
        float x1 = a.y + b.y + r.y + bi.y;
        float x2 = a.z + b.z + r.z + bi.z;
        float x3 = a.w + b.w + r.w + bi.w;
        v[i*4+0]=x0; v[i*4+1]=x1; v[i*4+2]=x2; v[i*4+3]=x3;
        s += (x0+x1) + (x2+x3);
        sq += (x0*x0 + x1*x1) + (x2*x2 + x3*x3);
    }
#pragma unroll
    for (int o = 16; o > 0; o >>= 1) {
        s  += __shfl_xor_sync(0xFFFFFFFFu, s,  o);
        sq += __shfl_xor_sync(0xFFFFFFFFu, sq, o);
    }
    float mean = s * (1.0f/768.0f);
    float var  = sq * (1.0f/768.0f) - mean*mean;
    float rstd = rsqrtf(var + 1e-5f);

#pragma unroll
    for (int i = 0; i < 6; i++) {
        int col = lane*4 + i*128;
        float4 gg = *(const float4*)(g  + col);
        float4 bb = *(const float4*)(be + col);
        float y0 = (v[i*4+0]-mean)*rstd*gg.x + bb.x;
        float y1 = (v[i*4+1]-mean)*rstd*gg.y + bb.y;
        float y2 = (v[i*4+2]-mean)*rstd*gg.z + bb.z;
        float y3 = (v[i*4+3]-mean)*rstd*gg.w + bb.w;
        *(float4*)(out + base + col) = make_float4(y0, y1, y2, y3);
        uint2 hp, lp;
        hsplit2(y0, y1, hp.x, lp.x);
        hsplit2(y2, y3, hp.y, lp.y);
        *(uint2*)(ohi + base + col) = hp;
        *(uint2*)(olo + base + col) = lp;
    }
}

// ---------------- host ----------------
extern "C" void kernel_launch(void* const* d_in, const int* in_sizes, int n_in,
                              void* d_out, int out_size)
{
    const int*   x    = (const int*)  d_in[0];
    const int*   pmsk = (const int*)  d_in[1];
    const float* emb  = (const float*)d_in[2];
    const float* Wq   = (const float*)d_in[3];
    const float* bq   = (const float*)d_in[4];
    const float* Wk   = (const float*)d_in[5];
    const float* bk   = (const float*)d_in[6];
    const float* Wv   = (const float*)d_in[7];
    const float* bv   = (const float*)d_in[8];
    const float* Wo   = (const float*)d_in[9];
    const float* bo   = (const float*)d_in[10];
    const float* W1   = (const float*)d_in[11];
    const float* b1   = (const float*)d_in[12];
    const float* W2   = (const float*)d_in[13];
    const float* b2   = (const float*)d_in[14];
    const float* g1   = (const float*)d_in[15];
    const float* be1  = (const float*)d_in[16];
    const float* g2   = (const float*)d_in[17];
    const float* be2  = (const float*)d_in[18];
    float* outp = (float*)d_out;

    float *hb, *tb, *tb2;
    __half *hhi, *hlo, *qkvh, *qkvl, *ohi, *olo, *fhi, *flo, *wh;
    unsigned char* m8;
    cudaGetSymbolAddress((void**)&hb,    g_h);
    cudaGetSymbolAddress((void**)&tb,    g_t);
    cudaGetSymbolAddress((void**)&tb2,   g_t2);
    cudaGetSymbolAddress((void**)&hhi,   g_hhi);
    cudaGetSymbolAddress((void**)&hlo,   g_hlo);
    cudaGetSymbolAddress((void**)&qkvh,  g_qkvh);
    cudaGetSymbolAddress((void**)&qkvl,  g_qkvl);
    cudaGetSymbolAddress((void**)&ohi,   g_ohi);
    cudaGetSymbolAddress((void**)&olo,   g_olo);
    cudaGetSymbolAddress((void**)&fhi,   g_fhi);
    cudaGetSymbolAddress((void**)&flo,   g_flo);
    cudaGetSymbolAddress((void**)&wh,    g_Wh);
    cudaGetSymbolAddress((void**)&m8,    g_mask8);

    cudaFuncSetAttribute(gemm_mma<1>, cudaFuncAttributeMaxDynamicSharedMemorySize, GEMM_SMEM);
    cudaFuncSetAttribute(gemm_mma<3>, cudaFuncAttributeMaxDynamicSharedMemorySize, GEMM_SMEM);
    cudaFuncSetAttribute(gemm_mma<4>, cudaFuncAttributeMaxDynamicSharedMemorySize, GEMM_SMEM);
    cudaFuncSetAttribute(attn_mma,    cudaFuncAttributeMaxDynamicSharedMemorySize, AT_SMEM);

    dim3 gQKV(NQKV/128, MM/128);
    dim3 gSplit(DD/128, MM/128, 2);
    dim3 gF1 (FF/128,   MM/128);
    dim3 gAttn(BB*HH, SS/128);

    tsplit_qkv<<<dim3(2, 24, LL*36), 256>>>(Wq, Wk, Wv);
    pe_kernel<<<(SS*DD+255)/256, 256>>>();
    embed_kernel<<<(MM*DD+255)/256, 256>>>(x, emb);

    for (int l = 0; l < LL; l++) {
        const __half* wl = wh + (size_t)l*LAYER_SZ;

        gemm_mma<3><<<gQKV, 256, GEMM_SMEM>>>(hhi, hlo, wl,
            bq + l*DD, bk + l*DD, bv + l*DD,
            nullptr, nullptr, qkvh, qkvl, DD, NQKV);

        if (l == 0)
            mask_conv<<<(BB*SS*SS/4+255)/256, 256>>>(pmsk);

        attn_mma<<<gAttn, 256, AT_SMEM>>>(qkvh, qkvl, m8, ohi, olo);

        if (l == 0)
            tsplit<<<dim3(24, 24, LL), 256>>>(Wo, wh + OFF_O,
                DD, DD, (size_t)DD*DD, (size_t)LAYER_SZ);

        gemm_mma<4><<<gSplit, 256, GEMM_SMEM>>>(ohi, olo, wl + OFF_O,
            nullptr, nullptr, nullptr, tb, tb2, nullptr, nullptr, DD, DD);

        ln2_kernel<<<MM/8, 256>>>(tb, tb2, hb, bo + l*DD,
                                  g1 + l*DD, be1 + l*DD, hb, hhi, hlo);

        if (l == 0)
            tsplit<<<dim3(96, 24, LL), 256>>>(W1, wh + OFF_W1,
                DD, FF, (size_t)DD*FF, (size_t)LAYER_SZ);

        gemm_mma<1><<<gF1, 256, GEMM_SMEM>>>(hhi, hlo, wl + OFF_W1,
            b1 + l*FF, nullptr, nullptr, nullptr, nullptr, fhi, flo, DD, FF);

        if (l == 0)
            tsplit<<<dim3(24, 96, LL), 256>>>(W2, wh + OFF_W2,
                FF, DD, (size_t)FF*DD, (size_t)LAYER_SZ);

        gemm_mma<4><<<gSplit, 256, GEMM_SMEM>>>(fhi, flo, wl + OFF_W2,
            nullptr, nullptr, nullptr, tb, tb2, nullptr, nullptr, FF, DD);

        float* lnOut = (l == LL-1) ? outp : hb;
        ln2_kernel<<<MM/8, 256>>>(tb, tb2, hb, b2 + l*DD,
                                  g2 + l*DD, be2 + l*DD, lnOut, hhi, hlo);
    }
}

// round 13
// speedup vs baseline: 4.5375x; 1.0074x over previous
#include <cuda_runtime.h>
#include <cuda_fp16.h>
#include <cstdint>
#include <math.h>

#define BB   16
#define SS   512
#define DD   768
#define HH   12
#define DNN  64
#define FF   3072
#define LL   6
#define MM   (BB*SS)
#define NQKV 2304

#define SZ_QKV (NQKV*DD)
#define SZ_O   (DD*DD)
#define SZ_W1  (FF*DD)
#define SZ_W2  (DD*FF)
#define OFF_O   SZ_QKV
#define OFF_W1  (OFF_O + SZ_O)
#define OFF_W2  (OFF_W1 + SZ_W1)
#define LAYER_SZ (OFF_W2 + SZ_W2)

// ---------------- scratch ----------------
__device__ __align__(16) float g_h  [MM*DD];
__device__ __align__(16) float g_t  [MM*DD];
__device__ __align__(16) float g_t2 [MM*DD];
__device__ __align__(16) __half g_hhi[(size_t)MM*DD];
__device__ __align__(16) __half g_hlo[(size_t)MM*DD];
__device__ __align__(16) __half g_qkvh[(size_t)MM*NQKV];
__device__ __align__(16) __half g_qkvl[(size_t)MM*NQKV];
__device__ __align__(16) __half g_ohi[(size_t)MM*DD];
__device__ __align__(16) __half g_olo[(size_t)MM*DD];
__device__ __align__(16) __half g_fhi[(size_t)MM*FF];
__device__ __align__(16) __half g_flo[(size_t)MM*FF];
__device__ __align__(16) __half g_Wh [(size_t)LL*LAYER_SZ];
__device__ __align__(16) unsigned char g_mask8[(size_t)BB*SS*SS];

// ======================= PTX helpers =======================
__device__ __forceinline__ uint32_t smem_u32(const void* p) {
    uint32_t a;
    asm("{ .reg .u64 t; cvta.to.shared.u64 t, %1; cvt.u32.u64 %0, t; }" : "=r"(a) : "l"(p));
    return a;
}
#define CP_ASYNC(dst, src) \
    asm volatile("cp.async.cg.shared.global [%0], [%1], 16;" :: "r"(dst), "l"(src) : "memory")
#define CP_COMMIT() asm volatile("cp.async.commit_group;" ::: "memory")
#define CP_WAIT2()  asm volatile("cp.async.wait_group 2;" ::: "memory")

#define LDSM4(r, addr) \
    asm volatile("ldmatrix.sync.aligned.m8n8.x4.shared.b16 {%0,%1,%2,%3}, [%4];" \
        : "=r"((r)[0]), "=r"((r)[1]), "=r"((r)[2]), "=r"((r)[3]) : "r"(addr))
#define LDSM2(r, addr) \
    asm volatile("ldmatrix.sync.aligned.m8n8.x2.shared.b16 {%0,%1}, [%2];" \
        : "=r"((r)[0]), "=r"((r)[1]) : "r"(addr))
#define LDSM2T(r, addr) \
    asm volatile("ldmatrix.sync.aligned.m8n8.x2.trans.shared.b16 {%0,%1}, [%2];" \
        : "=r"((r)[0]), "=r"((r)[1]) : "r"(addr))
#define MMA16816(c, a, b) \
    asm volatile("mma.sync.aligned.m16n8k16.row.col.f32.f16.f16.f32 " \
        "{%0,%1,%2,%3},{%4,%5,%6,%7},{%8,%9},{%0,%1,%2,%3};" \
        : "+f"((c)[0]), "+f"((c)[1]), "+f"((c)[2]), "+f"((c)[3]) \
        : "r"((a)[0]), "r"((a)[1]), "r"((a)[2]), "r"((a)[3]), "r"((b)[0]), "r"((b)[1]))

// fast exp on fma pipe
__device__ __forceinline__ float fexp(float x) {
    x = fminf(fmaxf(x, -60.f), 60.f);
    float y = x * 1.4426950408889634f;
    float t = y + 12582912.0f;
    int n = __float_as_int(t) - 0x4B400000;
    float f = y - (t - 12582912.0f);
    float p =       1.3333558e-3f;
    p = fmaf(p, f,  9.6181291e-3f);
    p = fmaf(p, f,  5.5504109e-2f);
    p = fmaf(p, f,  2.4022651e-1f);
    p = fmaf(p, f,  6.9314718e-1f);
    p = fmaf(p, f,  1.0f);
    return __int_as_float(__float_as_int(p) + (n << 23));
}

__device__ __forceinline__ void hsplit2(float v0, float v1, uint32_t& hi, uint32_t& lo) {
    __half2 h = __floats2half2_rn(v0, v1);
    __half2 l = __floats2half2_rn(v0 - __low2float(h), v1 - __high2float(h));
    hi = *(uint32_t*)&h;
    lo = *(uint32_t*)&l;
}

// ======================= tiled transpose -> fp16 =======================
__device__ __forceinline__ void tsplit_body(const float* __restrict__ src,
                                            __half* __restrict__ hi,
                                            int R, int C)
{
    __shared__ float t[32][33];
    int c0 = blockIdx.x*32, r0 = blockIdx.y*32;
    int tx = threadIdx.x & 31, ty = threadIdx.x >> 5;
#pragma unroll
    for (int i = 0; i < 32; i += 8)
        t[ty+i][tx] = src[(size_t)(r0+ty+i)*C + c0+tx];
    __syncthreads();
#pragma unroll
    for (int i = 0; i < 32; i += 8) {
        float v = t[tx][ty+i];
        hi[(size_t)(c0+ty+i)*R + r0+tx] = __float2half(v);
    }
}

__global__ void tsplit(const float* __restrict__ src, __half* __restrict__ hi,
                       int R, int C, size_t sStride, size_t dStride)
{
    int z = blockIdx.z;
    tsplit_body(src + z*sStride, hi + z*dStride, R, C);
}

__global__ void tsplit_qkv(const float* __restrict__ Wq, const float* __restrict__ Wk,
                           const float* __restrict__ Wv)
{
    int z = blockIdx.z;
    int l = z / 36, rem = z % 36, sec = rem / 12, h = rem % 12;
    const float* W = sec==0 ? Wq : (sec==1 ? Wk : Wv);
    const float* src = W + ((size_t)l*HH + h)*DD*DNN;
    size_t dofs = (size_t)l*LAYER_SZ + (size_t)(sec*DD + h*DNN)*DD;
    tsplit_body(src, g_Wh + dofs, DD, DNN);
}

__global__ void mask_conv(const int* __restrict__ m)
{
    int i = blockIdx.x*256 + threadIdx.x;
    int4 v = ((const int4*)m)[i];
    ((uchar4*)g_mask8)[i] = make_uchar4((unsigned char)v.x, (unsigned char)v.y,
                                        (unsigned char)v.z, (unsigned char)v.w);
}

// ======================= fp16 2-MMA GEMM (A split hi/lo, B single) =======================
#define NST 4
#define TILE_B 8192
#define STAGE_B (3*TILE_B)        // 24576
#define GEMM_SMEM (NST*STAGE_B)   // 98304

__device__ __forceinline__ uint32_t swz(int r, int cg) {
    return (uint32_t)(r*64 + ((cg ^ ((r>>1)&3))<<4));
}

// EPI 1: relu(+bias)->fp16 hi/lo | 3: +qkv-bias->fp16 (lo only for Q cols) | 4: split-K fp32 partial
template<int EPI>
__global__ void __launch_bounds__(256, 2)
gemm_mma(const __half* __restrict__ Ahi, const __half* __restrict__ Alo,
         const __half* __restrict__ Bh,
         const float* __restrict__ bias, const float* __restrict__ biasK,
         const float* __restrict__ biasV,
         float* __restrict__ outf, float* __restrict__ outf2,
         __half* __restrict__ outhi, __half* __restrict__ outlo,
         int K, int Ndim)
{
    extern __shared__ char sm[];
    int tid = threadIdx.x, wid = tid >> 5, lid = tid & 31;
    int m0 = blockIdx.y * 128, c0 = blockIdx.x * 128;
    int warp_m = (wid & 3) * 32, warp_n = (wid >> 2) * 64;

    const __half *pAh = Ahi, *pAl = Alo, *pB = Bh;
    float* pout = outf;
    int NCH;
    if (EPI == 4) {
        int half_k = K >> 1;
        int kofs = blockIdx.z * half_k;
        pAh += kofs; pAl += kofs; pB += kofs;
        if (blockIdx.z) pout = outf2;
        NCH = half_k >> 5;
    } else {
        NCH = K >> 5;
    }

    float c[2][8][4];
#pragma unroll
    for (int i=0;i<2;i++)
#pragma unroll
        for (int j=0;j<8;j++)
#pragma unroll
            for (int q=0;q<4;q++) c[i][j][q] = 0.f;

    auto load_chunk = [&](int ci, int st) {
        int k0 = ci << 5;
        char* base = sm + st * STAGE_B;
#pragma unroll
        for (int i = 0; i < 6; i++) {
            int seg = tid + i*256;
            int tl  = seg >> 9;
            int rem = seg & 511;
            int r   = rem >> 2, cg = rem & 3;
            const __half* src;
            if      (tl == 0) src = pAh + (size_t)(m0 + r)*K + k0 + cg*8;
            else if (tl == 1) src = pAl + (size_t)(m0 + r)*K + k0 + cg*8;
            else              src = pB  + (size_t)(c0 + r)*K + k0 + cg*8;
            CP_ASYNC(smem_u32(base + tl*TILE_B + swz(r, cg)), src);
        }
        CP_COMMIT();
    };

    load_chunk(0, 0);
    load_chunk(1, 1);
    load_chunk(2, 2);

    for (int ci = 0; ci < NCH; ci++) {
        int st = ci & 3;
        CP_WAIT2();
        __syncthreads();
        int nci = ci + 3;
        if (nci < NCH) load_chunk(nci, nci & 3);
        else CP_COMMIT();

        uint32_t base = smem_u32(sm + st * STAGE_B);
#pragma unroll
        for (int ks = 0; ks < 2; ks++) {
            uint32_t ah[2][4], al[2][4], bh[8][2];
            int acg = ks*2 + (lid >> 4);
            int bcg = ks*2 + ((lid >> 3) & 1);
#pragma unroll
            for (int mt = 0; mt < 2; mt++) {
                int r = warp_m + mt*16 + (lid & 15);
                LDSM4(ah[mt], base + 0*TILE_B + swz(r, acg));
                LDSM4(al[mt], base + 1*TILE_B + swz(r, acg));
            }
#pragma unroll
            for (int np = 0; np < 4; np++) {
                int r = warp_n + np*16 + ((lid >> 4) << 3) + (lid & 7);
                uint32_t t4[4];
                LDSM4(t4, base + 2*TILE_B + swz(r, bcg));
                bh[np*2][0]=t4[0]; bh[np*2][1]=t4[1]; bh[np*2+1][0]=t4[2]; bh[np*2+1][1]=t4[3];
            }
#pragma unroll
            for (int mt = 0; mt < 2; mt++)
#pragma unroll
                for (int nt = 0; nt < 8; nt++) {
                    MMA16816(c[mt][nt], ah[mt], bh[nt]);
                    MMA16816(c[mt][nt], al[mt], bh[nt]);
                }
        }
    }

    const float* bptr = bias;
    int cofs = 0;
    bool wantLo = true;
    if (EPI == 3) {
        int sec = (c0 >= 1536) ? 2 : (c0 >= 768 ? 1 : 0);
        bptr = (sec == 0) ? bias : (sec == 1 ? biasK : biasV);
        cofs = sec * 768;
        wantLo = (sec == 0);   // attention consumes lo only for Q
    }
    int g = lid >> 2, t2 = (lid & 3) * 2;
#pragma unroll
    for (int mt = 0; mt < 2; mt++) {
#pragma unroll
        for (int half_i = 0; half_i < 2; half_i++) {
            long m = m0 + warp_m + mt*16 + g + half_i*8;
#pragma unroll
            for (int nt = 0; nt < 8; nt++) {
                int col = c0 + warp_n + nt*8 + t2;
                if (EPI == 4) {
                    *(float2*)(pout + m*(long)Ndim + col) =
                        make_float2(c[mt][nt][half_i*2+0], c[mt][nt][half_i*2+1]);
                } else {
                    float v0 = c[mt][nt][half_i*2+0] + bptr[col - cofs];
                    float v1 = c[mt][nt][half_i*2+1] + bptr[col - cofs + 1];
                    if (EPI == 1) { v0 = fmaxf(v0, 0.f); v1 = fmaxf(v1, 0.f); }
                    uint32_t hp, lp;
                    hsplit2(v0, v1, hp, lp);
                    *(uint32_t*)(outhi + m*(long)Ndim + col) = hp;
                    if (EPI != 3 || wantLo)
                        *(uint32_t*)(outlo + m*(long)Ndim + col) = lp;
                }
            }
        }
    }
}

// ======================= fp16 attention, 4-stage pipeline, 2 CTA/SM =======================
#define AT_QH 0
#define AT_QL 18432
#define AT_ST0 36864
#define AT_KH 0
#define AT_VH 4608
#define AT_MS 9216
#define AT_STAGE 13312
#define AT_NST 4
#define AT_SMEM (AT_ST0 + AT_NST*AT_STAGE)   // 90112

__global__ void __launch_bounds__(256, 2)
attn_mma(const __half* __restrict__ qvh, const __half* __restrict__ qvl,
         const unsigned char* __restrict__ mask8,
         __half* __restrict__ ohi, __half* __restrict__ olo)
{
    extern __shared__ char smn[];
    int tid = threadIdx.x, wid = tid >> 5, lid = tid & 31;
    int bh = blockIdx.x;
    int b = bh / HH, h = bh % HH;
    int sq0 = blockIdx.y * 128;
    const size_t rowbase = (size_t)b * SS;
    int g = lid >> 2, t2 = lid & 3;

    // prologue: Q (hi/lo), 128 rows x 128B, stride 144 (goes into commit group 0)
#pragma unroll
    for (int i = 0; i < 8; i++) {
        int s = tid + i*256;
        int arr = s >> 10, rem = s & 1023;
        int r = rem >> 3, cg = rem & 7;
        const __half* src = (arr ? qvl : qvh) +
            (rowbase + sq0 + r)*(size_t)NQKV + h*DNN + cg*8;
        CP_ASYNC(smem_u32(smn + arr*18432 + r*144 + cg*16), src);
    }

    auto load_kv = [&](int kci, int st) {
        int kc = kci * 32;
        char* base = smn + AT_ST0 + st*AT_STAGE;
#pragma unroll
        for (int i = 0; i < 2; i++) {
            int s = tid + i*256;
            int tl = s >> 8, rem = s & 255;
            int r = rem >> 3, cg = rem & 7;
            size_t off = (rowbase + kc + r)*(size_t)NQKV + h*DNN + cg*8;
            const __half* src = qvh + off + (tl ? 2*DD : DD);
            CP_ASYNC(smem_u32(base + tl*4608 + r*144 + cg*16), src);
        }
        {
            int r = tid >> 1, seg = tid & 1;
            CP_ASYNC(smem_u32(base + AT_MS + r*32 + seg*16),
                     mask8 + (rowbase + sq0 + r)*(size_t)SS + kc + seg*16);
        }
        CP_COMMIT();
    };

    load_kv(0, 0);
    load_kv(1, 1);
    load_kv(2, 2);

    uint32_t qfh[4][4], qfl[4][4];
    float o[8][4];
#pragma unroll
    for (int nt = 0; nt < 8; nt++)
#pragma unroll
        for (int q = 0; q < 4; q++) o[nt][q] = 0.f;
    float rs0 = 0.f, rs1 = 0.f;

    for (int ci = 0; ci < 16; ci++) {
        int st = ci & 3;
        CP_WAIT2();
        __syncthreads();
        if (ci == 0) {
            uint32_t qb = smem_u32(smn);
#pragma unroll
            for (int kg = 0; kg < 4; kg++) {
                uint32_t qa = qb + (wid*16 + (lid & 15))*144 + kg*32 + (lid >> 4)*16;
                LDSM4(qfh[kg], qa);
                LDSM4(qfl[kg], qa + 18432);
            }
        }
        int nci = ci + 3;
        if (nci < 16) load_kv(nci, nci & 3);
        else CP_COMMIT();

        uint32_t sb = smem_u32(smn + AT_ST0 + st*AT_STAGE);
        float s[4][4];
#pragma unroll
        for (int nt = 0; nt < 4; nt++)
#pragma unroll
            for (int q = 0; q < 4; q++) s[nt][q] = 0.f;

        // S = Q K^T: qh*kh + ql*kh
#pragma unroll
        for (int kg = 0; kg < 4; kg++) {
#pragma unroll
            for (int nt = 0; nt < 4; nt++) {
                uint32_t kh2[2];
                uint32_t ka = sb + (nt*8 + (lid & 7))*144 + kg*32 + ((lid >> 3) & 1)*16;
                LDSM2(kh2, ka + AT_KH);
                MMA16816(s[nt], qfh[kg], kh2);
                MMA16816(s[nt], qfl[kg], kh2);
            }
        }

        // softmax numerator + pack P into PV A-frags
        const unsigned char* msm = (const unsigned char*)(smn + AT_ST0 + st*AT_STAGE + AT_MS);
        const unsigned char* mr0 = msm + (wid*16 + g)*32;
        const unsigned char* mr1 = mr0 + 8*32;
        uint32_t aPh[2][4], aPl[2][4];
#pragma unroll
        for (int nt = 0; nt < 4; nt++) {
            uchar2 m0 = *(const uchar2*)(mr0 + nt*8 + t2*2);
            uchar2 m1 = *(const uchar2*)(mr1 + nt*8 + t2*2);
            float p0 = m0.x ? 0.f : fexp(s[nt][0]*0.125f);
            float p1 = m0.y ? 0.f : fexp(s[nt][1]*0.125f);
            float p2 = m1.x ? 0.f : fexp(s[nt][2]*0.125f);
            float p3 = m1.y ? 0.f : fexp(s[nt][3]*0.125f);
            rs0 += p0 + p1;
            rs1 += p2 + p3;
            int kg = nt >> 1, sub = (nt & 1)*2;
            hsplit2(p0, p1, aPh[kg][sub],   aPl[kg][sub]);
            hsplit2(p2, p3, aPh[kg][sub+1], aPl[kg][sub+1]);
        }

        // O += P V
#pragma unroll
        for (int kg = 0; kg < 2; kg++) {
#pragma unroll
            for (int nt = 0; nt < 8; nt++) {
                uint32_t vh2[2];
                uint32_t va = sb + (kg*16 + (lid & 15))*144 + nt*16;
                LDSM2T(vh2, va + AT_VH);
                MMA16816(o[nt], aPh[kg], vh2);
                MMA16816(o[nt], aPl[kg], vh2);
            }
        }
    }

    rs0 += __shfl_xor_sync(0xFFFFFFFFu, rs0, 1);
    rs0 += __shfl_xor_sync(0xFFFFFFFFu, rs0, 2);
    rs1 += __shfl_xor_sync(0xFFFFFFFFu, rs1, 1);
    rs1 += __shfl_xor_sync(0xFFFFFFFFu, rs1, 2);
    float inv0 = 1.f / rs0, inv1 = 1.f / rs1;

    long r0 = rowbase + sq0 + wid*16 + g;
    int colb = h*DNN + t2*2;
#pragma unroll
    for (int nt = 0; nt < 8; nt++) {
        int col = colb + nt*8;
        uint32_t hp0, lp0, hp1, lp1;
        hsplit2(o[nt][0]*inv0, o[nt][1]*inv0, hp0, lp0);
        hsplit2(o[nt][2]*inv1, o[nt][3]*inv1, hp1, lp1);
        *(uint32_t*)(ohi + r0*DD + col)     = hp0;
        *(uint32_t*)(olo + r0*DD + col)     = lp0;
        *(uint32_t*)(ohi + (r0+8)*DD + col) = hp1;
        *(uint32_t*)(olo + (r0+8)*DD + col) = lp1;
    }
}

// ---------------- embedding + inline PE (+ split) ----------------
__global__ void embed_kernel(const int* __restrict__ x, const float* __restrict__ emb)
{
    int idx = blockIdx.x*blockDim.x + threadIdx.x;
    if (idx >= MM*DD) return;
    int m = idx / DD, d = idx % DD;
    int s = m % SS;
    int tok = x[m];
    const float LOG10000 = 9.210340371976184f;
    int i = d >> 1;
    float pe;
    if ((d & 1) == 0) {
        float freq = expf(-(2.0f*i/DD)*LOG10000);
        pe = sinf(s*freq);
    } else {
        float freq = expf(-(2.0f*(i+1)/DD)*LOG10000);
        pe = cosf(s*freq);
    }
    float v = emb[(size_t)tok*DD + d] + pe;
    g_h[idx] = v;
    __half h = __float2half(v);
    g_hhi[idx] = h;
    g_hlo[idx] = __float2half(v - __half2float(h));
}

// ---------------- fused split-K-reduce + layernorm (warp-per-row) ----------------
__global__ void __launch_bounds__(256)
ln2_kernel(const float* __restrict__ p1, const float* __restrict__ p2,
           const float* __restrict__ res, const float* __restrict__ bias,
           const float* __restrict__ g, const float* __restrict__ be,
           float* __restrict__ out,
           __half* __restrict__ ohi, __half* __restrict__ olo)
{
    int row = blockIdx.x*8 + (threadIdx.x >> 5);
    int lane = threadIdx.x & 31;
    size_t base = (size_t)row*DD;

    float v[24];
    float s = 0.f, sq = 0.f;
#pragma unroll
    for (int i = 0; i < 6; i++) {
        int col = lane*4 + i*128;
        float4 a  = *(const float4*)(p1  + base + col);
        float4 b  = *(const float4*)(p2  + base + col);
        float4 r  = *(const float4*)(res + base + col);
        float4 bi = *(const float4*)(bias + col);
        float x0 = a.x + b.x + r.x + bi.x;
        float x1 = a.y + b.y + r.y + bi.y;
        float x2 = a.z + b.z + r.z + bi.z;
        float x3 = a.w + b.w + r.w + bi.w;
        v[i*4+0]=x0; v[i*4+1]=x1; v[i*4+2]=x2; v[i*4+3]=x3;
        s += (x0+x1) + (x2+x3);
        sq += (x0*x0 + x1*x1) + (x2*x2 + x3*x3);
    }
#pragma unroll
    for (int o = 16; o > 0; o >>= 1) {
        s  += __shfl_xor_sync(0xFFFFFFFFu, s,  o);
        sq += __shfl_xor_sync(0xFFFFFFFFu, sq, o);
    }
    float mean = s * (1.0f/768.0f);
    float var  = sq * (1.0f/768.0f) - mean*mean;
    float rstd = rsqrtf(var + 1e-5f);

#pragma unroll
    for (int i = 0; i < 6; i++) {
        int col = lane*4 + i*128;
        float4 gg = *(const float4*)(g  + col);
        float4 bb = *(const float4*)(be + col);
        float y0 = (v[i*4+0]-mean)*rstd*gg.x + bb.x;
        float y1 = (v[i*4+1]-mean)*rstd*gg.y + bb.y;
        float y2 = (v[i*4+2]-mean)*rstd*gg.z + bb.z;
        float y3 = (v[i*4+3]-mean)*rstd*gg.w + bb.w;
        *(float4*)(out + base + col) = make_float4(y0, y1, y2, y3);
        uint2 hp, lp;
        hsplit2(y0, y1, hp.x, lp.x);
        hsplit2(y2, y3, hp.y, lp.y);
        *(uint2*)(ohi + base + col) = hp;
        *(uint2*)(olo + base + col) = lp;
    }
}

// ---------------- host ----------------
extern "C" void kernel_launch(void* const* d_in, const int* in_sizes, int n_in,
                              void* d_out, int out_size)
{
    const int*   x    = (const int*)  d_in[0];
    const int*   pmsk = (const int*)  d_in[1];
    const float* emb  = (const float*)d_in[2];
    const float* Wq   = (const float*)d_in[3];
    const float* bq   = (const float*)d_in[4];
    const float* Wk   = (const float*)d_in[5];
    const float* bk   = (const float*)d_in[6];
    const float* Wv   = (const float*)d_in[7];
    const float* bv   = (const float*)d_in[8];
    const float* Wo   = (const float*)d_in[9];
    const float* bo   = (const float*)d_in[10];
    const float* W1   = (const float*)d_in[11];
    const float* b1   = (const float*)d_in[12];
    const float* W2   = (const float*)d_in[13];
    const float* b2   = (const float*)d_in[14];
    const float* g1   = (const float*)d_in[15];
    const float* be1  = (const float*)d_in[16];
    const float* g2   = (const float*)d_in[17];
    const float* be2  = (const float*)d_in[18];
    float* outp = (float*)d_out;

    float *hb, *tb, *tb2;
    __half *hhi, *hlo, *qkvh, *qkvl, *ohi, *olo, *fhi, *flo, *wh;
    unsigned char* m8;
    cudaGetSymbolAddress((void**)&hb,    g_h);
    cudaGetSymbolAddress((void**)&tb,    g_t);
    cudaGetSymbolAddress((void**)&tb2,   g_t2);
    cudaGetSymbolAddress((void**)&hhi,   g_hhi);
    cudaGetSymbolAddress((void**)&hlo,   g_hlo);
    cudaGetSymbolAddress((void**)&qkvh,  g_qkvh);
    cudaGetSymbolAddress((void**)&qkvl,  g_qkvl);
    cudaGetSymbolAddress((void**)&ohi,   g_ohi);
    cudaGetSymbolAddress((void**)&olo,   g_olo);
    cudaGetSymbolAddress((void**)&fhi,   g_fhi);
    cudaGetSymbolAddress((void**)&flo,   g_flo);
    cudaGetSymbolAddress((void**)&wh,    g_Wh);
    cudaGetSymbolAddress((void**)&m8,    g_mask8);

    cudaFuncSetAttribute(gemm_mma<1>, cudaFuncAttributeMaxDynamicSharedMemorySize, GEMM_SMEM);
    cudaFuncSetAttribute(gemm_mma<3>, cudaFuncAttributeMaxDynamicSharedMemorySize, GEMM_SMEM);
    cudaFuncSetAttribute(gemm_mma<4>, cudaFuncAttributeMaxDynamicSharedMemorySize, GEMM_SMEM);
    cudaFuncSetAttribute(attn_mma,    cudaFuncAttributeMaxDynamicSharedMemorySize, AT_SMEM);

    dim3 gQKV(NQKV/128, MM/128);
    dim3 gSplit(DD/128, MM/128, 2);
    dim3 gF1 (FF/128,   MM/128);
    dim3 gAttn(BB*HH, SS/128);

    tsplit_qkv<<<dim3(2, 24, LL*36), 256>>>(Wq, Wk, Wv);
    embed_kernel<<<(MM*DD+255)/256, 256>>>(x, emb);

    for (int l = 0; l < LL; l++) {
        const __half* wl = wh + (size_t)l*LAYER_SZ;

        gemm_mma<3><<<gQKV, 256, GEMM_SMEM>>>(hhi, hlo, wl,
            bq + l*DD, bk + l*DD, bv + l*DD,
            nullptr, nullptr, qkvh, qkvl, DD, NQKV);

        if (l == 0)
            mask_conv<<<(BB*SS*SS/4+255)/256, 256>>>(pmsk);

        attn_mma<<<gAttn, 256, AT_SMEM>>>(qkvh, qkvl, m8, ohi, olo);

        if (l == 0)
            tsplit<<<dim3(24, 24, LL), 256>>>(Wo, wh + OFF_O,
                DD, DD, (size_t)DD*DD, (size_t)LAYER_SZ);

        gemm_mma<4><<<gSplit, 256, GEMM_SMEM>>>(ohi, olo, wl + OFF_O,
            nullptr, nullptr, nullptr, tb, tb2, nullptr, nullptr, DD, DD);

        ln2_kernel<<<MM/8, 256>>>(tb, tb2, hb, bo + l*DD,
                                  g1 + l*DD, be1 + l*DD, hb, hhi, hlo);

        if (l == 0)
            tsplit<<<dim3(96, 24, LL), 256>>>(W1, wh + OFF_W1,
                DD, FF, (size_t)DD*FF, (size_t)LAYER_SZ);

        gemm_mma<1><<<gF1, 256, GEMM_SMEM>>>(hhi, hlo, wl + OFF_W1,
            b1 + l*FF, nullptr, nullptr, nullptr, nullptr, fhi, flo, DD, FF);

        if (l == 0)
            tsplit<<<dim3(24, 96, LL), 256>>>(W2, wh + OFF_W2,
                FF, DD, (size_t)FF*DD, (size_t)LAYER_SZ);

        gemm_mma<4><<<gSplit, 256, GEMM_SMEM>>>(fhi, flo, wl + OFF_W2,
            nullptr, nullptr, nullptr, tb, tb2, nullptr, nullptr, FF, DD);

        float* lnOut = (l == LL-1) ? outp : hb;
        ln2_kernel<<<MM/8, 256>>>(tb, tb2, hb, b2 + l*DD,
                                  g2 + l*DD, be2 + l*DD, lnOut, hhi, hlo);
    }
}

// round 14
// speedup vs baseline: 4.6337x; 1.0212x over previous
#include <cuda_runtime.h>
#include <cuda_fp16.h>
#include <cstdint>
#include <math.h>

#define BB   16
#define SS   512
#define DD   768
#define HH   12
#define DNN  64
#define FF   3072
#define LL   6
#define MM   (BB*SS)
#define NQKV 2304

#define SZ_QKV (NQKV*DD)
#define SZ_O   (DD*DD)
#define SZ_W1  (FF*DD)
#define SZ_W2  (DD*FF)
#define OFF_O   SZ_QKV
#define OFF_W1  (OFF_O + SZ_O)
#define OFF_W2  (OFF_W1 + SZ_W1)
#define LAYER_SZ (OFF_W2 + SZ_W2)

// ---------------- scratch ----------------
__device__ __align__(16) float g_h  [MM*DD];
__device__ __align__(16) float g_t  [MM*DD];
__device__ __align__(16) float g_t2 [MM*DD];
__device__ __align__(16) __half g_hhi[(size_t)MM*DD];
__device__ __align__(16) __half g_hlo[(size_t)MM*DD];
__device__ __align__(16) __half g_qkvh[(size_t)MM*NQKV];
__device__ __align__(16) __half g_qkvl[(size_t)MM*NQKV];
__device__ __align__(16) __half g_ohi[(size_t)MM*DD];
__device__ __align__(16) __half g_olo[(size_t)MM*DD];
__device__ __align__(16) __half g_fhi[(size_t)MM*FF];
__device__ __align__(16) __half g_flo[(size_t)MM*FF];
__device__ __align__(16) __half g_Wh [(size_t)LL*LAYER_SZ];
__device__ __align__(16) unsigned char g_mask8[(size_t)BB*SS*SS];

// ======================= PTX helpers =======================
__device__ __forceinline__ uint32_t smem_u32(const void* p) {
    uint32_t a;
    asm("{ .reg .u64 t; cvta.to.shared.u64 t, %1; cvt.u32.u64 %0, t; }" : "=r"(a) : "l"(p));
    return a;
}
#define CP_ASYNC(dst, src) \
    asm volatile("cp.async.cg.shared.global [%0], [%1], 16;" :: "r"(dst), "l"(src) : "memory")
#define CP_COMMIT() asm volatile("cp.async.commit_group;" ::: "memory")
#define CP_WAIT0()  asm volatile("cp.async.wait_group 0;" ::: "memory")

#define LDSM4(r, addr) \
    asm volatile("ldmatrix.sync.aligned.m8n8.x4.shared.b16 {%0,%1,%2,%3}, [%4];" \
        : "=r"((r)[0]), "=r"((r)[1]), "=r"((r)[2]), "=r"((r)[3]) : "r"(addr))
#define LDSM2(r, addr) \
    asm volatile("ldmatrix.sync.aligned.m8n8.x2.shared.b16 {%0,%1}, [%2];" \
        : "=r"((r)[0]), "=r"((r)[1]) : "r"(addr))
#define LDSM2T(r, addr) \
    asm volatile("ldmatrix.sync.aligned.m8n8.x2.trans.shared.b16 {%0,%1}, [%2];" \
        : "=r"((r)[0]), "=r"((r)[1]) : "r"(addr))
#define MMA16816(c, a, b) \
    asm volatile("mma.sync.aligned.m16n8k16.row.col.f32.f16.f16.f32 " \
        "{%0,%1,%2,%3},{%4,%5,%6,%7},{%8,%9},{%0,%1,%2,%3};" \
        : "+f"((c)[0]), "+f"((c)[1]), "+f"((c)[2]), "+f"((c)[3]) \
        : "r"((a)[0]), "r"((a)[1]), "r"((a)[2]), "r"((a)[3]), "r"((b)[0]), "r"((b)[1]))

// fast exp on fma pipe
__device__ __forceinline__ float fexp(float x) {
    x = fminf(fmaxf(x, -60.f), 60.f);
    float y = x * 1.4426950408889634f;
    float t = y + 12582912.0f;
    int n = __float_as_int(t) - 0x4B400000;
    float f = y - (t - 12582912.0f);
    float p =       1.3333558e-3f;
    p = fmaf(p, f,  9.6181291e-3f);
    p = fmaf(p, f,  5.5504109e-2f);
    p = fmaf(p, f,  2.4022651e-1f);
    p = fmaf(p, f,  6.9314718e-1f);
    p = fmaf(p, f,  1.0f);
    return __int_as_float(__float_as_int(p) + (n << 23));
}

__device__ __forceinline__ void hsplit2(float v0, float v1, uint32_t& hi, uint32_t& lo) {
    __half2 h = __floats2half2_rn(v0, v1);
    __half2 l = __floats2half2_rn(v0 - __low2float(h), v1 - __high2float(h));
    hi = *(uint32_t*)&h;
    lo = *(uint32_t*)&l;
}

// ======================= tiled transpose -> fp16 =======================
__device__ __forceinline__ void tsplit_body(const float* __restrict__ src,
                                            __half* __restrict__ hi,
                                            int R, int C)
{
    __shared__ float t[32][33];
    int c0 = blockIdx.x*32, r0 = blockIdx.y*32;
    int tx = threadIdx.x & 31, ty = threadIdx.x >> 5;
#pragma unroll
    for (int i = 0; i < 32; i += 8)
        t[ty+i][tx] = src[(size_t)(r0+ty+i)*C + c0+tx];
    __syncthreads();
#pragma unroll
    for (int i = 0; i < 32; i += 8) {
        float v = t[tx][ty+i];
        hi[(size_t)(c0+ty+i)*R + r0+tx] = __float2half(v);
    }
}

__global__ void tsplit(const float* __restrict__ src, __half* __restrict__ hi,
                       int R, int C, size_t sStride, size_t dStride)
{
    int z = blockIdx.z;
    tsplit_body(src + z*sStride, hi + z*dStride, R, C);
}

__global__ void tsplit_qkv(const float* __restrict__ Wq, const float* __restrict__ Wk,
                           const float* __restrict__ Wv)
{
    int z = blockIdx.z;
    int l = z / 36, rem = z % 36, sec = rem / 12, h = rem % 12;
    const float* W = sec==0 ? Wq : (sec==1 ? Wk : Wv);
    const float* src = W + ((size_t)l*HH + h)*DD*DNN;
    size_t dofs = (size_t)l*LAYER_SZ + (size_t)(sec*DD + h*DNN)*DD;
    tsplit_body(src, g_Wh + dofs, DD, DNN);
}

// ---------------- embedding + inline PE + mask conversion (fused) ----------------
#define EMBED_BLKS ((MM*DD+255)/256)
#define MASK_BLKS  ((BB*SS*SS/4+255)/256)

__global__ void embed_mask_kernel(const int* __restrict__ x, const float* __restrict__ emb,
                                  const int* __restrict__ msk)
{
    if (blockIdx.x >= EMBED_BLKS) {
        int i = (blockIdx.x - EMBED_BLKS)*256 + threadIdx.x;
        int4 v = ((const int4*)msk)[i];
        ((uchar4*)g_mask8)[i] = make_uchar4((unsigned char)v.x, (unsigned char)v.y,
                                            (unsigned char)v.z, (unsigned char)v.w);
        return;
    }
    int idx = blockIdx.x*256 + threadIdx.x;
    if (idx >= MM*DD) return;
    int m = idx / DD, d = idx % DD;
    int s = m % SS;
    int tok = x[m];
    const float LOG10000 = 9.210340371976184f;
    int i = d >> 1;
    float pe;
    if ((d & 1) == 0) {
        float freq = expf(-(2.0f*i/DD)*LOG10000);
        pe = sinf(s*freq);
    } else {
        float freq = expf(-(2.0f*(i+1)/DD)*LOG10000);
        pe = cosf(s*freq);
    }
    float v = emb[(size_t)tok*DD + d] + pe;
    g_h[idx] = v;
    __half h = __float2half(v);
    g_hhi[idx] = h;
    g_hlo[idx] = __float2half(v - __half2float(h));
}

// ======================= fp16 2-MMA GEMM, 64-wide k-chunks, 2-stage =======================
#define GTILE 16384               // 128 rows x 128B
#define GSTAGE (3*GTILE)          // 49152
#define GEMM_SMEM (2*GSTAGE)      // 98304

__device__ __forceinline__ uint32_t swz128(int r, int cg) {
    return (uint32_t)(r*128 + ((cg ^ (r & 7)) << 4));
}

// EPI 1: relu(+bias)->fp16 hi/lo | 3: +qkv-bias->fp16 (lo only for Q cols) | 4: split-K fp32 partial
template<int EPI>
__global__ void __launch_bounds__(256, 2)
gemm_mma(const __half* __restrict__ Ahi, const __half* __restrict__ Alo,
         const __half* __restrict__ Bh,
         const float* __restrict__ bias, const float* __restrict__ biasK,
         const float* __restrict__ biasV,
         float* __restrict__ outf, float* __restrict__ outf2,
         __half* __restrict__ outhi, __half* __restrict__ outlo,
         int K, int Ndim)
{
    extern __shared__ char sm[];
    int tid = threadIdx.x, wid = tid >> 5, lid = tid & 31;
    int m0 = blockIdx.y * 128, c0 = blockIdx.x * 128;
    int warp_m = (wid & 3) * 32, warp_n = (wid >> 2) * 64;

    const __half *pAh = Ahi, *pAl = Alo, *pB = Bh;
    float* pout = outf;
    int NCH;
    if (EPI == 4) {
        int half_k = K >> 1;
        int kofs = blockIdx.z * half_k;
        pAh += kofs; pAl += kofs; pB += kofs;
        if (blockIdx.z) pout = outf2;
        NCH = half_k >> 6;
    } else {
        NCH = K >> 6;
    }

    float c[2][8][4];
#pragma unroll
    for (int i=0;i<2;i++)
#pragma unroll
        for (int j=0;j<8;j++)
#pragma unroll
            for (int q=0;q<4;q++) c[i][j][q] = 0.f;

    auto load_chunk = [&](int ci, int st) {
        int k0 = ci << 6;
        char* base = sm + st * GSTAGE;
#pragma unroll
        for (int i = 0; i < 12; i++) {
            int seg = tid + i*256;            // 0..3071
            int tl  = seg >> 10;              // 0..2
            int rem = seg & 1023;
            int r   = rem >> 3, cg = rem & 7;
            const __half* src;
            if      (tl == 0) src = pAh + (size_t)(m0 + r)*K + k0 + cg*8;
            else if (tl == 1) src = pAl + (size_t)(m0 + r)*K + k0 + cg*8;
            else              src = pB  + (size_t)(c0 + r)*K + k0 + cg*8;
            CP_ASYNC(smem_u32(base + tl*GTILE + swz128(r, cg)), src);
        }
        CP_COMMIT();
    };

    load_chunk(0, 0);

    for (int ci = 0; ci < NCH; ci++) {
        int st = ci & 1;
        CP_WAIT0();
        __syncthreads();
        if (ci + 1 < NCH) load_chunk(ci + 1, st ^ 1);

        uint32_t base = smem_u32(sm + st * GSTAGE);
#pragma unroll
        for (int ks = 0; ks < 4; ks++) {
            uint32_t ah[2][4], al[2][4], bh[8][2];
            int acg = ks*2 + (lid >> 4);
            int bcg = ks*2 + ((lid >> 3) & 1);
#pragma unroll
            for (int mt = 0; mt < 2; mt++) {
                int r = warp_m + mt*16 + (lid & 15);
                LDSM4(ah[mt], base + 0*GTILE + swz128(r, acg));
                LDSM4(al[mt], base + 1*GTILE + swz128(r, acg));
            }
#pragma unroll
            for (int np = 0; np < 4; np++) {
                int r = warp_n + np*16 + ((lid >> 4) << 3) + (lid & 7);
                uint32_t t4[4];
                LDSM4(t4, base + 2*GTILE + swz128(r, bcg));
                bh[np*2][0]=t4[0]; bh[np*2][1]=t4[1]; bh[np*2+1][0]=t4[2]; bh[np*2+1][1]=t4[3];
            }
#pragma unroll
            for (int mt = 0; mt < 2; mt++)
#pragma unroll
                for (int nt = 0; nt < 8; nt++) {
                    MMA16816(c[mt][nt], ah[mt], bh[nt]);
                    MMA16816(c[mt][nt], al[mt], bh[nt]);
                }
        }
    }

    const float* bptr = bias;
    int cofs = 0;
    bool wantLo = true;
    if (EPI == 3) {
        int sec = (c0 >= 1536) ? 2 : (c0 >= 768 ? 1 : 0);
        bptr = (sec == 0) ? bias : (sec == 1 ? biasK : biasV);
        cofs = sec * 768;
        wantLo = (sec == 0);
    }
    int g = lid >> 2, t2 = (lid & 3) * 2;
#pragma unroll
    for (int mt = 0; mt < 2; mt++) {
#pragma unroll
        for (int half_i = 0; half_i < 2; half_i++) {
            long m = m0 + warp_m + mt*16 + g + half_i*8;
#pragma unroll
            for (int nt = 0; nt < 8; nt++) {
                int col = c0 + warp_n + nt*8 + t2;
                if (EPI == 4) {
                    *(float2*)(pout + m*(long)Ndim + col) =
                        make_float2(c[mt][nt][half_i*2+0], c[mt][nt][half_i*2+1]);
                } else {
                    float v0 = c[mt][nt][half_i*2+0] + bptr[col - cofs];
                    float v1 = c[mt][nt][half_i*2+1] + bptr[col - cofs + 1];
                    if (EPI == 1) { v0 = fmaxf(v0, 0.f); v1 = fmaxf(v1, 0.f); }
                    uint32_t hp, lp;
                    hsplit2(v0, v1, hp, lp);
                    *(uint32_t*)(outhi + m*(long)Ndim + col) = hp;
                    if (EPI != 3 || wantLo)
                        *(uint32_t*)(outlo + m*(long)Ndim + col) = lp;
                }
            }
        }
    }
}

// ======================= fp16 attention, 64-row stages (2x32 inner), 2-stage, 2 CTA/SM =======================
#define AT_ST0 36864
#define AT_KH 0
#define AT_VH 9216
#define AT_MS 18432
#define AT_STAGE 26624
#define AT_SMEM (AT_ST0 + 2*AT_STAGE)   // 90112

__global__ void __launch_bounds__(256, 2)
attn_mma(const __half* __restrict__ qvh, const __half* __restrict__ qvl,
         const unsigned char* __restrict__ mask8,
         __half* __restrict__ ohi, __half* __restrict__ olo)
{
    extern __shared__ char smn[];
    int tid = threadIdx.x, wid = tid >> 5, lid = tid & 31;
    int bh = blockIdx.x;
    int b = bh / HH, h = bh % HH;
    int sq0 = blockIdx.y * 128;
    const size_t rowbase = (size_t)b * SS;
    int g = lid >> 2, t2 = lid & 3;

    // prologue: Q (hi/lo), 128 rows x 128B, stride 144 (joins commit group 0)
#pragma unroll
    for (int i = 0; i < 8; i++) {
        int s = tid + i*256;
        int arr = s >> 10, rem = s & 1023;
        int r = rem >> 3, cg = rem & 7;
        const __half* src = (arr ? qvl : qvh) +
            (rowbase + sq0 + r)*(size_t)NQKV + h*DNN + cg*8;
        CP_ASYNC(smem_u32(smn + arr*18432 + r*144 + cg*16), src);
    }

    auto load_kv = [&](int kci, int st) {
        int kc = kci * 64;
        char* base = smn + AT_ST0 + st*AT_STAGE;
        // K,V: 2 tiles x 64 rows x 8 cg = 1024 segs
#pragma unroll
        for (int i = 0; i < 4; i++) {
            int s = tid + i*256;
            int tl = s >> 9, rem = s & 511;
            int r = rem >> 3, cg = rem & 7;
            size_t off = (rowbase + kc + r)*(size_t)NQKV + h*DNN + cg*8;
            const __half* src = qvh + off + (tl ? 2*DD : DD);
            CP_ASYNC(smem_u32(base + tl*9216 + r*144 + cg*16), src);
        }
        // mask: 128 q-rows x 64 u8 = 8KB = 512 x 16B
#pragma unroll
        for (int i = 0; i < 2; i++) {
            int s = tid + i*256;
            int r = s >> 2, seg = s & 3;
            CP_ASYNC(smem_u32(base + AT_MS + r*64 + seg*16),
                     mask8 + (rowbase + sq0 + r)*(size_t)SS + kc + seg*16);
        }
        CP_COMMIT();
    };

    load_kv(0, 0);

    uint32_t qfh[4][4], qfl[4][4];
    float o[8][4];
#pragma unroll
    for (int nt = 0; nt < 8; nt++)
#pragma unroll
        for (int q = 0; q < 4; q++) o[nt][q] = 0.f;
    float rs0 = 0.f, rs1 = 0.f;

    for (int ci = 0; ci < 8; ci++) {
        int st = ci & 1;
        CP_WAIT0();
        __syncthreads();
        if (ci == 0) {
            uint32_t qb = smem_u32(smn);
#pragma unroll
            for (int kg = 0; kg < 4; kg++) {
                uint32_t qa = qb + (wid*16 + (lid & 15))*144 + kg*32 + (lid >> 4)*16;
                LDSM4(qfh[kg], qa);
                LDSM4(qfl[kg], qa + 18432);
            }
        }
        if (ci + 1 < 8) load_kv(ci + 1, st ^ 1);

        uint32_t sb = smem_u32(smn + AT_ST0 + st*AT_STAGE);
        const unsigned char* msm = (const unsigned char*)(smn + AT_ST0 + st*AT_STAGE + AT_MS);

        // inner: two 32-row halves (register pressure identical to 32-row chunks)
#pragma unroll
        for (int h2 = 0; h2 < 2; h2++) {
            int rof = h2 * 32;
            float s[4][4];
#pragma unroll
            for (int nt = 0; nt < 4; nt++)
#pragma unroll
                for (int q = 0; q < 4; q++) s[nt][q] = 0.f;

            // S = Q K^T
#pragma unroll
            for (int kg = 0; kg < 4; kg++) {
#pragma unroll
                for (int nt = 0; nt < 4; nt++) {
                    uint32_t kh2[2];
                    uint32_t ka = sb + (rof + nt*8 + (lid & 7))*144 + kg*32 + ((lid >> 3) & 1)*16;
                    LDSM2(kh2, ka + AT_KH);
                    MMA16816(s[nt], qfh[kg], kh2);
                    MMA16816(s[nt], qfl[kg], kh2);
                }
            }

            // softmax numerator + pack P
            const unsigned char* mr0 = msm + (wid*16 + g)*64 + rof;
            const unsigned char* mr1 = mr0 + 8*64;
            uint32_t aPh[2][4], aPl[2][4];
#pragma unroll
            for (int nt = 0; nt < 4; nt++) {
                uchar2 m0 = *(const uchar2*)(mr0 + nt*8 + t2*2);
                uchar2 m1 = *(const uchar2*)(mr1 + nt*8 + t2*2);
                float p0 = m0.x ? 0.f : fexp(s[nt][0]*0.125f);
                float p1 = m0.y ? 0.f : fexp(s[nt][1]*0.125f);
                float p2 = m1.x ? 0.f : fexp(s[nt][2]*0.125f);
                float p3 = m1.y ? 0.f : fexp(s[nt][3]*0.125f);
                rs0 += p0 + p1;
                rs1 += p2 + p3;
                int kg = nt >> 1, sub = (nt & 1)*2;
                hsplit2(p0, p1, aPh[kg][sub],   aPl[kg][sub]);
                hsplit2(p2, p3, aPh[kg][sub+1], aPl[kg][sub+1]);
            }

            // O += P V
#pragma unroll
            for (int kg = 0; kg < 2; kg++) {
#pragma unroll
                for (int nt = 0; nt < 8; nt++) {
                    uint32_t vh2[2];
                    uint32_t va = sb + AT_VH + (rof + kg*16 + (lid & 15))*144 + nt*16;
                    LDSM2T(vh2, va);
                    MMA16816(o[nt], aPh[kg], vh2);
                    MMA16816(o[nt], aPl[kg], vh2);
                }
            }
        }
    }

    rs0 += __shfl_xor_sync(0xFFFFFFFFu, rs0, 1);
    rs0 += __shfl_xor_sync(0xFFFFFFFFu, rs0, 2);
    rs1 += __shfl_xor_sync(0xFFFFFFFFu, rs1, 1);
    rs1 += __shfl_xor_sync(0xFFFFFFFFu, rs1, 2);
    float inv0 = 1.f / rs0, inv1 = 1.f / rs1;

    long r0 = rowbase + sq0 + wid*16 + g;
    int colb = h*DNN + t2*2;
#pragma unroll
    for (int nt = 0; nt < 8; nt++) {
        int col = colb + nt*8;
        uint32_t hp0, lp0, hp1, lp1;
        hsplit2(o[nt][0]*inv0, o[nt][1]*inv0, hp0, lp0);
        hsplit2(o[nt][2]*inv1, o[nt][3]*inv1, hp1, lp1);
        *(uint32_t*)(ohi + r0*DD + col)     = hp0;
        *(uint32_t*)(olo + r0*DD + col)     = lp0;
        *(uint32_t*)(ohi + (r0+8)*DD + col) = hp1;
        *(uint32_t*)(olo + (r0+8)*DD + col) = lp1;
    }
}

// ---------------- fused split-K-reduce + layernorm (warp-per-row) ----------------
__global__ void __launch_bounds__(256)
ln2_kernel(const float* __restrict__ p1, const float* __restrict__ p2,
           const float* __restrict__ res, const float* __restrict__ bias,
           const float* __restrict__ g, const float* __restrict__ be,
           float* __restrict__ out,
           __half* __restrict__ ohi, __half* __restrict__ olo)
{
    int row = blockIdx.x*8 + (threadIdx.x >> 5);
    int lane = threadIdx.x & 31;
    size_t base = (size_t)row*DD;

    float v[24];
    float s = 0.f, sq = 0.f;
#pragma unroll
    for (int i = 0; i < 6; i++) {
        int col = lane*4 + i*128;
        float4 a  = *(const float4*)(p1  + base + col);
        float4 b  = *(const float4*)(p2  + base + col);
        float4 r  = *(const float4*)(res + base + col);
        float4 bi = *(const float4*)(bias + col);
        float x0 = a.x + b.x + r.x + bi.x;
        float x1 = a.y + b.y + r.y + bi.y;
        float x2 = a.z + b.z + r.z + bi.z;
        float x3 = a.w + b.w + r.w + bi.w;
        v[i*4+0]=x0; v[i*4+1]=x1; v[i*4+2]=x2; v[i*4+3]=x3;
        s += (x0+x1) + (x2+x3);
        sq += (x0*x0 + x1*x1) + (x2*x2 + x3*x3);
    }
#pragma unroll
    for (int o = 16; o > 0; o >>= 1) {
        s  += __shfl_xor_sync(0xFFFFFFFFu, s,  o);
        sq += __shfl_xor_sync(0xFFFFFFFFu, sq, o);
    }
    float mean = s * (1.0f/768.0f);
    float var  = sq * (1.0f/768.0f) - mean*mean;
    float rstd = rsqrtf(var + 1e-5f);

#pragma unroll
    for (int i = 0; i < 6; i++) {
        int col = lane*4 + i*128;
        float4 gg = *(const float4*)(g  + col);
        float4 bb = *(const float4*)(be + col);
        float y0 = (v[i*4+0]-mean)*rstd*gg.x + bb.x;
        float y1 = (v[i*4+1]-mean)*rstd*gg.y + bb.y;
        float y2 = (v[i*4+2]-mean)*rstd*gg.z + bb.z;
        float y3 = (v[i*4+3]-mean)*rstd*gg.w + bb.w;
        *(float4*)(out + base + col) = make_float4(y0, y1, y2, y3);
        uint2 hp, lp;
        hsplit2(y0, y1, hp.x, lp.x);
        hsplit2(y2, y3, hp.y, lp.y);
        *(uint2*)(ohi + base + col) = hp;
        *(uint2*)(olo + base + col) = lp;
    }
}

// ---------------- host ----------------
extern "C" void kernel_launch(void* const* d_in, const int* in_sizes, int n_in,
                              void* d_out, int out_size)
{
    const int*   x    = (const int*)  d_in[0];
    const int*   pmsk = (const int*)  d_in[1];
    const float* emb  = (const float*)d_in[2];
    const float* Wq   = (const float*)d_in[3];
    const float* bq   = (const float*)d_in[4];
    const float* Wk   = (const float*)d_in[5];
    const float* bk   = (const float*)d_in[6];
    const float* Wv   = (const float*)d_in[7];
    const float* bv   = (const float*)d_in[8];
    const float* Wo   = (const float*)d_in[9];
    const float* bo   = (const float*)d_in[10];
    const float* W1   = (const float*)d_in[11];
    const float* b1   = (const float*)d_in[12];
    const float* W2   = (const float*)d_in[13];
    const float* b2   = (const float*)d_in[14];
    const float* g1   = (const float*)d_in[15];
    const float* be1  = (const float*)d_in[16];
    const float* g2   = (const float*)d_in[17];
    const float* be2  = (const float*)d_in[18];
    float* outp = (float*)d_out;

    float *hb, *tb, *tb2;
    __half *hhi, *hlo, *qkvh, *qkvl, *ohi, *olo, *fhi, *flo, *wh;
    unsigned char* m8;
    cudaGetSymbolAddress((void**)&hb,    g_h);
    cudaGetSymbolAddress((void**)&tb,    g_t);
    cudaGetSymbolAddress((void**)&tb2,   g_t2);
    cudaGetSymbolAddress((void**)&hhi,   g_hhi);
    cudaGetSymbolAddress((void**)&hlo,   g_hlo);
    cudaGetSymbolAddress((void**)&qkvh,  g_qkvh);
    cudaGetSymbolAddress((void**)&qkvl,  g_qkvl);
    cudaGetSymbolAddress((void**)&ohi,   g_ohi);
    cudaGetSymbolAddress((void**)&olo,   g_olo);
    cudaGetSymbolAddress((void**)&fhi,   g_fhi);
    cudaGetSymbolAddress((void**)&flo,   g_flo);
    cudaGetSymbolAddress((void**)&wh,    g_Wh);
    cudaGetSymbolAddress((void**)&m8,    g_mask8);

    cudaFuncSetAttribute(gemm_mma<1>, cudaFuncAttributeMaxDynamicSharedMemorySize, GEMM_SMEM);
    cudaFuncSetAttribute(gemm_mma<3>, cudaFuncAttributeMaxDynamicSharedMemorySize, GEMM_SMEM);
    cudaFuncSetAttribute(gemm_mma<4>, cudaFuncAttributeMaxDynamicSharedMemorySize, GEMM_SMEM);
    cudaFuncSetAttribute(attn_mma,    cudaFuncAttributeMaxDynamicSharedMemorySize, AT_SMEM);

    dim3 gQKV(NQKV/128, MM/128);
    dim3 gSplit(DD/128, MM/128, 2);
    dim3 gF1 (FF/128,   MM/128);
    dim3 gAttn(BB*HH, SS/128);

    tsplit_qkv<<<dim3(2, 24, LL*36), 256>>>(Wq, Wk, Wv);                      // 1
    embed_mask_kernel<<<EMBED_BLKS + MASK_BLKS, 256>>>(x, emb, pmsk);         // 2

    for (int l = 0; l < LL; l++) {
        const __half* wl = wh + (size_t)l*LAYER_SZ;

        gemm_mma<3><<<gQKV, 256, GEMM_SMEM>>>(hhi, hlo, wl,                   // 3
            bq + l*DD, bk + l*DD, bv + l*DD,
            nullptr, nullptr, qkvh, qkvl, DD, NQKV);

        attn_mma<<<gAttn, 256, AT_SMEM>>>(qkvh, qkvl, m8, ohi, olo);          // 4 (ncu capture)

        if (l == 0)
            tsplit<<<dim3(24, 24, LL), 256>>>(Wo, wh + OFF_O,
                DD, DD, (size_t)DD*DD, (size_t)LAYER_SZ);

        gemm_mma<4><<<gSplit, 256, GEMM_SMEM>>>(ohi, olo, wl + OFF_O,
            nullptr, nullptr, nullptr, tb, tb2, nullptr, nullptr, DD, DD);

        ln2_kernel<<<MM/8, 256>>>(tb, tb2, hb, bo + l*DD,
                                  g1 + l*DD, be1 + l*DD, hb, hhi, hlo);

        if (l == 0)
            tsplit<<<dim3(96, 24, LL), 256>>>(W1, wh + OFF_W1,
                DD, FF, (size_t)DD*FF, (size_t)LAYER_SZ);

        gemm_mma<1><<<gF1, 256, GEMM_SMEM>>>(hhi, hlo, wl + OFF_W1,
            b1 + l*FF, nullptr, nullptr, nullptr, nullptr, fhi, flo, DD, FF);

        if (l == 0)
            tsplit<<<dim3(24, 96, LL), 256>>>(W2, wh + OFF_W2,
                FF, DD, (size_t)FF*DD, (size_t)LAYER_SZ);

        gemm_mma<4><<<gSplit, 256, GEMM_SMEM>>>(fhi, flo, wl + OFF_W2,
            nullptr, nullptr, nullptr, tb, tb2, nullptr, nullptr, FF, DD);

        float* lnOut = (l == LL-1) ? outp : hb;
        ln2_kernel<<<MM/8, 256>>>(tb, tb2, hb, b2 + l*DD,
                                  g2 + l*DD, be2 + l*DD, lnOut, hhi, hlo);
    }
}